// round 5
// baseline (speedup 1.0000x reference)
#include <cuda_runtime.h>

// ---------------------------------------------------------------------------
// GraphormerMultiHeadAttention  (B=16, N=512, HIDDEN=768, 12 heads x 64)
//
// Pipeline:
//   1) gemm_nt: Q = x @ Wq^T, K = x @ Wk^T, V = x @ Wv^T + bv   (scratch)
//   2) attn:    flash-style attention with graph bias + exact pad-mask
//   3) gemm_nt: out = O @ Wo^T + bo
// ---------------------------------------------------------------------------

#define HID    768
#define MTOT   8192          // B * N
#define NSEQ   512
#define NHEAD  12
#define DHEAD  64
#define SCALE_F 0.03608439182435161f   // 768^-0.5  (module scales by hidden^-0.5)
#define LOG2E_F 1.4426950408889634f

// Scratch (device globals: allocation-free per harness rules)
__device__ float g_q[MTOT * HID];
__device__ float g_k[MTOT * HID];
__device__ float g_v[MTOT * HID];
__device__ float g_o[MTOT * HID];

// ---------------------------------------------------------------------------
// GEMM (NT): C[m][n] = sum_k A[m][k] * W[n][k] + bias[n]
// M=8192, N=768, K=768. Tiles 128x64x16, 256 threads, 8x4 per-thread tile.
// Register prefetch + double-buffered smem.
// ---------------------------------------------------------------------------
#define BM 128
#define BN 64
#define BK 16
#define ASTR 132   // padded strides: conflict-light stores, aligned vector reads
#define BSTR 68
#define KTILES (HID / BK)

__global__ __launch_bounds__(256)
void gemm_nt_kernel(const float* __restrict__ Aext,
                    const float* __restrict__ W,
                    const float* __restrict__ bias,
                    float* __restrict__ Cext,
                    int mode)   // 0:C=g_q 1:C=g_k 2:C=g_v 3:A=g_o,C=Cext
{
    __shared__ float As[2][BK][ASTR];
    __shared__ float Bs[2][BK][BSTR];

    const float* A = (mode == 3) ? g_o : Aext;
    float* C = (mode == 0) ? g_q : (mode == 1) ? g_k : (mode == 2) ? g_v : Cext;

    const int tid = threadIdx.x;
    const int tx  = tid & 15;
    const int ty  = tid >> 4;
    const int m0  = blockIdx.x * BM;
    const int n0  = blockIdx.y * BN;

    const int lrow = tid >> 2;          // 0..63
    const int lkq  = (tid & 3) * 4;     // 0,4,8,12

    const float* Aptr0 = A + (size_t)(m0 + lrow) * HID + lkq;
    const float* Aptr1 = A + (size_t)(m0 + lrow + 64) * HID + lkq;
    const float* Wptr  = W + (size_t)(n0 + lrow) * HID + lkq;

    float acc[8][4];
#pragma unroll
    for (int i = 0; i < 8; i++)
#pragma unroll
        for (int j = 0; j < 4; j++) acc[i][j] = 0.f;

    // tile 0 load + store
    float4 fa0 = *(const float4*)(Aptr0);
    float4 fa1 = *(const float4*)(Aptr1);
    float4 fb  = *(const float4*)(Wptr);
    {
        As[0][lkq + 0][lrow] = fa0.x; As[0][lkq + 1][lrow] = fa0.y;
        As[0][lkq + 2][lrow] = fa0.z; As[0][lkq + 3][lrow] = fa0.w;
        As[0][lkq + 0][lrow + 64] = fa1.x; As[0][lkq + 1][lrow + 64] = fa1.y;
        As[0][lkq + 2][lrow + 64] = fa1.z; As[0][lkq + 3][lrow + 64] = fa1.w;
        Bs[0][lkq + 0][lrow] = fb.x; Bs[0][lkq + 1][lrow] = fb.y;
        Bs[0][lkq + 2][lrow] = fb.z; Bs[0][lkq + 3][lrow] = fb.w;
    }
    __syncthreads();

    int buf = 0;
    for (int t = 0; t < KTILES; t++) {
        if (t + 1 < KTILES) {                 // prefetch next tile into regs
            const int off = (t + 1) * BK;
            fa0 = *(const float4*)(Aptr0 + off);
            fa1 = *(const float4*)(Aptr1 + off);
            fb  = *(const float4*)(Wptr + off);
        }
#pragma unroll
        for (int kk = 0; kk < BK; kk++) {
            float4 a0 = *(const float4*)&As[buf][kk][ty * 8];
            float4 a1 = *(const float4*)&As[buf][kk][ty * 8 + 4];
            float4 b  = *(const float4*)&Bs[buf][kk][tx * 4];
            float av[8] = {a0.x, a0.y, a0.z, a0.w, a1.x, a1.y, a1.z, a1.w};
            float bv[4] = {b.x, b.y, b.z, b.w};
#pragma unroll
            for (int i = 0; i < 8; i++)
#pragma unroll
                for (int j = 0; j < 4; j++)
                    acc[i][j] = fmaf(av[i], bv[j], acc[i][j]);
        }
        if (t + 1 < KTILES) {                 // store prefetched tile
            const int nb = buf ^ 1;
            As[nb][lkq + 0][lrow] = fa0.x; As[nb][lkq + 1][lrow] = fa0.y;
            As[nb][lkq + 2][lrow] = fa0.z; As[nb][lkq + 3][lrow] = fa0.w;
            As[nb][lkq + 0][lrow + 64] = fa1.x; As[nb][lkq + 1][lrow + 64] = fa1.y;
            As[nb][lkq + 2][lrow + 64] = fa1.z; As[nb][lkq + 3][lrow + 64] = fa1.w;
            Bs[nb][lkq + 0][lrow] = fb.x; Bs[nb][lkq + 1][lrow] = fb.y;
            Bs[nb][lkq + 2][lrow] = fb.z; Bs[nb][lkq + 3][lrow] = fb.w;
        }
        __syncthreads();
        buf ^= 1;
    }

    float badd[4] = {0.f, 0.f, 0.f, 0.f};
    if (bias) {
        float4 bb = *(const float4*)(bias + n0 + tx * 4);
        badd[0] = bb.x; badd[1] = bb.y; badd[2] = bb.z; badd[3] = bb.w;
    }
#pragma unroll
    for (int i = 0; i < 8; i++) {
        float4 o = make_float4(acc[i][0] + badd[0], acc[i][1] + badd[1],
                               acc[i][2] + badd[2], acc[i][3] + badd[3]);
        *(float4*)(C + (size_t)(m0 + ty * 8 + i) * HID + n0 + tx * 4) = o;
    }
}

// ---------------------------------------------------------------------------
// exp2 on the FMA pipe (avoids MUFU bottleneck: 50M exps in this problem).
// Valid for x <= 0 (softmax args); clamped at -80 (result ~ 8e-25 -> irrelevant).
// ---------------------------------------------------------------------------
__device__ __forceinline__ float fast_exp2(float x)
{
    x = fmaxf(x, -80.0f);
    float n = rintf(x);
    float f = x - n;
    float p = 1.5403530e-4f;               // Taylor of 2^f = e^{f ln2}
    p = fmaf(p, f, 1.3333558e-3f);
    p = fmaf(p, f, 9.6181291e-3f);
    p = fmaf(p, f, 5.5504109e-2f);
    p = fmaf(p, f, 2.4022651e-1f);
    p = fmaf(p, f, 6.9314718e-1f);
    p = fmaf(p, f, 1.0f);
    return p * __int_as_float(((int)n + 127) << 23);
}

// ---------------------------------------------------------------------------
// Flash-style attention. One CTA per (b, h, 64-query tile).
// Streams 64-key chunks, online softmax, exact pad-mask (all-zero rows -> 0).
// smem: Qs[64][64] + KV[64][65] + Ps[64][64]  = 49408 bytes (dynamic).
// ---------------------------------------------------------------------------
#define ATTN_SMEM ((64 * 64 + 64 * 65 + 64 * 64) * 4)

__global__ __launch_bounds__(256)
void attn_kernel(const float* __restrict__ ebias)
{
    extern __shared__ float sm[];
    float* Qs = sm;                // [64][64]
    float* KV = sm + 64 * 64;      // [64][65]  (K then V, per chunk)
    float* Ps = KV + 64 * 65;      // [64][64]

    const int tid = threadIdx.x;
    const int tx  = tid & 15;
    const int ty  = tid >> 4;
    const int qt  = blockIdx.x;    // 0..7
    const int h   = blockIdx.y;    // 0..11
    const int b   = blockIdx.z;    // 0..15
    const int q0  = qt * 64;

    const float* qg = g_q + ((size_t)(b * NSEQ + q0)) * HID + h * DHEAD;
    const float* kg = g_k + ((size_t)b * NSEQ) * HID + h * DHEAD;
    const float* vg = g_v + ((size_t)b * NSEQ) * HID + h * DHEAD;
    const float* bg = ebias + ((size_t)(b * NSEQ + q0)) * NSEQ;

    // load Q tile [64 rows][64 d]
#pragma unroll
    for (int l = 0; l < 4; l++) {
        int idx = tid + l * 256;
        int row = idx >> 4;
        int d4  = (idx & 15) * 4;
        *(float4*)(Qs + row * 64 + d4) =
            *(const float4*)(qg + (size_t)row * HID + d4);
    }

    float acc[4][4];
    float mrow[4], rsum[4];
    int   nz[4];
#pragma unroll
    for (int i = 0; i < 4; i++) {
        mrow[i] = -1e30f; rsum[i] = 0.f; nz[i] = 0;
#pragma unroll
        for (int j = 0; j < 4; j++) acc[i][j] = 0.f;
    }

    for (int kc = 0; kc < 8; kc++) {
        __syncthreads();   // KV / Ps free from previous iteration
        // load K chunk [key][65]
#pragma unroll
        for (int l = 0; l < 4; l++) {
            int idx = tid + l * 256;
            int key = idx >> 4;
            int d4  = (idx & 15) * 4;
            float4 v = *(const float4*)(kg + (size_t)(kc * 64 + key) * HID + d4);
            float* p = KV + key * 65 + d4;
            p[0] = v.x; p[1] = v.y; p[2] = v.z; p[3] = v.w;
        }
        __syncthreads();

        // S = Q @ K^T   (thread tile: rows ty*4+i, keys tx*4+j)
        float s[4][4];
#pragma unroll
        for (int i = 0; i < 4; i++)
#pragma unroll
            for (int j = 0; j < 4; j++) s[i][j] = 0.f;

#pragma unroll 8
        for (int k4 = 0; k4 < 16; k4++) {
            float4 a[4];
#pragma unroll
            for (int i = 0; i < 4; i++)
                a[i] = *(const float4*)(Qs + (ty * 4 + i) * 64 + k4 * 4);
#pragma unroll
            for (int j = 0; j < 4; j++) {
                const float* kp = KV + (size_t)(tx * 4 + j) * 65 + k4 * 4;
                float b0 = kp[0], b1 = kp[1], b2 = kp[2], b3 = kp[3];
#pragma unroll
                for (int i = 0; i < 4; i++) {
                    s[i][j] = fmaf(a[i].x, b0, s[i][j]);
                    s[i][j] = fmaf(a[i].y, b1, s[i][j]);
                    s[i][j] = fmaf(a[i].z, b2, s[i][j]);
                    s[i][j] = fmaf(a[i].w, b3, s[i][j]);
                }
            }
        }

        // a = s*SCALE + bias; online softmax update
#pragma unroll
        for (int i = 0; i < 4; i++) {
            float4 bb = *(const float4*)(bg + (size_t)(ty * 4 + i) * NSEQ + kc * 64 + tx * 4);
            s[i][0] = fmaf(s[i][0], SCALE_F, bb.x);
            s[i][1] = fmaf(s[i][1], SCALE_F, bb.y);
            s[i][2] = fmaf(s[i][2], SCALE_F, bb.z);
            s[i][3] = fmaf(s[i][3], SCALE_F, bb.w);

            float mc = fmaxf(fmaxf(s[i][0], s[i][1]), fmaxf(s[i][2], s[i][3]));
            int nzc = (s[i][0] != 0.f) | (s[i][1] != 0.f) |
                      (s[i][2] != 0.f) | (s[i][3] != 0.f);
#pragma unroll
            for (int o = 1; o < 16; o <<= 1) {
                mc   = fmaxf(mc, __shfl_xor_sync(0xffffffffu, mc, o));
                nzc |= __shfl_xor_sync(0xffffffffu, nzc, o);
            }
            nz[i] |= nzc;
            float mnew = fmaxf(mrow[i], mc);
            float corr = fast_exp2((mrow[i] - mnew) * LOG2E_F);
            mrow[i] = mnew;

            float p0 = fast_exp2((s[i][0] - mnew) * LOG2E_F);
            float p1 = fast_exp2((s[i][1] - mnew) * LOG2E_F);
            float p2 = fast_exp2((s[i][2] - mnew) * LOG2E_F);
            float p3 = fast_exp2((s[i][3] - mnew) * LOG2E_F);

            float ps = (p0 + p1) + (p2 + p3);
#pragma unroll
            for (int o = 1; o < 16; o <<= 1)
                ps += __shfl_xor_sync(0xffffffffu, ps, o);
            rsum[i] = rsum[i] * corr + ps;
#pragma unroll
            for (int j = 0; j < 4; j++) acc[i][j] *= corr;

            *(float4*)(Ps + (ty * 4 + i) * 64 + tx * 4) = make_float4(p0, p1, p2, p3);
        }
        __syncthreads();   // done reading K, done writing Ps

        // load V chunk [key][65] (reuse KV)
#pragma unroll
        for (int l = 0; l < 4; l++) {
            int idx = tid + l * 256;
            int key = idx >> 4;
            int d4  = (idx & 15) * 4;
            float4 v = *(const float4*)(vg + (size_t)(kc * 64 + key) * HID + d4);
            float* p = KV + key * 65 + d4;
            p[0] = v.x; p[1] = v.y; p[2] = v.z; p[3] = v.w;
        }
        __syncthreads();

        // acc += P @ V   (rows ty*4+i, d-cols tx*4+j, contraction over keys)
#pragma unroll 8
        for (int k4 = 0; k4 < 16; k4++) {
            float av[4][4];
#pragma unroll
            for (int i = 0; i < 4; i++) {
                float4 a = *(const float4*)(Ps + (ty * 4 + i) * 64 + k4 * 4);
                av[i][0] = a.x; av[i][1] = a.y; av[i][2] = a.z; av[i][3] = a.w;
            }
#pragma unroll
            for (int kk = 0; kk < 4; kk++) {
                const float* vp = KV + (size_t)(k4 * 4 + kk) * 65 + tx * 4;
                float b0 = vp[0], b1 = vp[1], b2 = vp[2], b3 = vp[3];
#pragma unroll
                for (int i = 0; i < 4; i++) {
                    acc[i][0] = fmaf(av[i][kk], b0, acc[i][0]);
                    acc[i][1] = fmaf(av[i][kk], b1, acc[i][1]);
                    acc[i][2] = fmaf(av[i][kk], b2, acc[i][2]);
                    acc[i][3] = fmaf(av[i][kk], b3, acc[i][3]);
                }
            }
        }
    }

    // epilogue: normalize (or zero masked rows) and store
    float* og = g_o + ((size_t)(b * NSEQ + q0)) * HID + h * DHEAD;
#pragma unroll
    for (int i = 0; i < 4; i++) {
        float inv = nz[i] ? (1.f / rsum[i]) : 0.f;
        float4 o = make_float4(acc[i][0] * inv, acc[i][1] * inv,
                               acc[i][2] * inv, acc[i][3] * inv);
        *(float4*)(og + (size_t)(ty * 4 + i) * HID + tx * 4) = o;
    }
}

// ---------------------------------------------------------------------------
// inputs (metadata order): x, encoding_bias, Wq, Wk, Wv, bv, Wo, bo
// ---------------------------------------------------------------------------
extern "C" void kernel_launch(void* const* d_in, const int* in_sizes, int n_in,
                              void* d_out, int out_size)
{
    const float* x  = (const float*)d_in[0];
    const float* eb = (const float*)d_in[1];
    const float* Wq = (const float*)d_in[2];
    const float* Wk = (const float*)d_in[3];
    const float* Wv = (const float*)d_in[4];
    const float* bv = (const float*)d_in[5];
    const float* Wo = (const float*)d_in[6];
    const float* bo = (const float*)d_in[7];
    float* out = (float*)d_out;

    static_assert(ATTN_SMEM == 49408, "smem layout");
    cudaFuncSetAttribute(attn_kernel,
                         cudaFuncAttributeMaxDynamicSharedMemorySize, ATTN_SMEM);

    dim3 gb(MTOT / BM, HID / BN);   // (64, 12)

    gemm_nt_kernel<<<gb, 256>>>(x, Wq, nullptr, nullptr, 0);           // Q
    gemm_nt_kernel<<<gb, 256>>>(x, Wk, nullptr, nullptr, 1);           // K
    gemm_nt_kernel<<<gb, 256>>>(x, Wv, bv,      nullptr, 2);           // V + bv

    attn_kernel<<<dim3(8, NHEAD, 16), 256, ATTN_SMEM>>>(eb);           // attention

    gemm_nt_kernel<<<gb, 256>>>(nullptr, Wo, bo, out, 3);              // O proj
}

// round 9
// speedup vs baseline: 1.6100x; 1.6100x over previous
#include <cuda_runtime.h>
#include <cuda_bf16.h>
#include <cstdint>

// ---------------------------------------------------------------------------
// GraphormerMultiHeadAttention  (B=16, N=512, HIDDEN=768, 12 heads x 64)
//
//   1) split x, W* into bf16 hi/lo planes
//   2) mma.sync bf16 GEMM (3-term split = fp32-grade): QKV fused; later O
//   3) SIMT flash attention (unchanged from R5)
//
// NOTE: tcgen05 is ptxas-rejected on this build (.target sm_103 family, no 'a'
// feature). mma.sync / ldmatrix are non-gated and hit the tensor pipe (HMMA).
// ---------------------------------------------------------------------------

#define HID    768
#define MTOT   8192
#define NSEQ   512
#define NHEAD  12
#define DHEAD  64
#define SCALE_F 0.03608439182435161f   // 768^-0.5
#define LOG2E_F 1.4426950408889634f
#define WSZ (HID * HID)

// ---------------- scratch (device globals; allocation-free) ----------------
__device__ float g_q[MTOT * HID];
__device__ float g_k[MTOT * HID];
__device__ float g_v[MTOT * HID];
__device__ float g_o[MTOT * HID];
__device__ __align__(16) __nv_bfloat16 g_ah[MTOT * HID];
__device__ __align__(16) __nv_bfloat16 g_al[MTOT * HID];
__device__ __align__(16) __nv_bfloat16 g_oh[MTOT * HID];
__device__ __align__(16) __nv_bfloat16 g_ol[MTOT * HID];
__device__ __align__(16) __nv_bfloat16 g_wh[4 * WSZ];
__device__ __align__(16) __nv_bfloat16 g_wl[4 * WSZ];

// ---------------------------------------------------------------------------
// fp32 -> (hi, lo) bf16 split. mode selects destination device globals so no
// cudaGetSymbolAddress is needed during graph capture.
//   0: x -> g_ah/g_al   1..4: W(mode-1) -> g_wh/g_wl   5: g_o -> g_oh/g_ol
// ---------------------------------------------------------------------------
__global__ void conv_split_kernel(const float* __restrict__ src, int mode, int n4)
{
    int i = blockIdx.x * blockDim.x + threadIdx.x;
    if (i >= n4) return;

    __nv_bfloat16 *hi, *lo;
    const float* s = src;
    if (mode == 0)       { hi = g_ah; lo = g_al; }
    else if (mode <= 4)  { hi = g_wh + (size_t)(mode - 1) * WSZ;
                           lo = g_wl + (size_t)(mode - 1) * WSZ; }
    else                 { hi = g_oh; lo = g_ol; s = g_o; }

    float4 v = ((const float4*)s)[i];
    __nv_bfloat16 h0 = __float2bfloat16_rn(v.x);
    __nv_bfloat16 h1 = __float2bfloat16_rn(v.y);
    __nv_bfloat16 h2 = __float2bfloat16_rn(v.z);
    __nv_bfloat16 h3 = __float2bfloat16_rn(v.w);
    __nv_bfloat162 H0, H1, L0, L1;
    H0.x = h0; H0.y = h1; H1.x = h2; H1.y = h3;
    L0.x = __float2bfloat16_rn(v.x - __bfloat162float(h0));
    L0.y = __float2bfloat16_rn(v.y - __bfloat162float(h1));
    L1.x = __float2bfloat16_rn(v.z - __bfloat162float(h2));
    L1.y = __float2bfloat16_rn(v.w - __bfloat162float(h3));
    ((__nv_bfloat162*)hi)[2 * i]     = H0;
    ((__nv_bfloat162*)hi)[2 * i + 1] = H1;
    ((__nv_bfloat162*)lo)[2 * i]     = L0;
    ((__nv_bfloat162*)lo)[2 * i + 1] = L1;
}

// ---------------------------------------------------------------------------
// warp-mma helpers
// ---------------------------------------------------------------------------
__device__ __forceinline__ uint32_t smem_u32(const void* p)
{
    uint32_t a;
    asm("{ .reg .u64 t; cvta.to.shared.u64 t, %1; cvt.u32.u64 %0, t; }"
        : "=r"(a) : "l"(p));
    return a;
}
__device__ __forceinline__ void ldm4(uint32_t* r, uint32_t addr)
{
    asm volatile("ldmatrix.sync.aligned.m8n8.x4.shared.b16 {%0,%1,%2,%3}, [%4];"
                 : "=r"(r[0]), "=r"(r[1]), "=r"(r[2]), "=r"(r[3]) : "r"(addr));
}
__device__ __forceinline__ void mma16816(float* c, const uint32_t* a,
                                         uint32_t b0, uint32_t b1)
{
    asm volatile(
        "mma.sync.aligned.m16n8k16.row.col.f32.bf16.bf16.f32 "
        "{%0,%1,%2,%3}, {%4,%5,%6,%7}, {%8,%9}, {%0,%1,%2,%3};"
        : "+f"(c[0]), "+f"(c[1]), "+f"(c[2]), "+f"(c[3])
        : "r"(a[0]), "r"(a[1]), "r"(a[2]), "r"(a[3]), "r"(b0), "r"(b1));
}

// ---------------------------------------------------------------------------
// GEMM-NT: C[m][n] = sum_k A[m][k] * W[n][k] (+ bias[n]) via mma.sync bf16,
// 3-term split. CTA 128x128x(k32), 8 warps (4m x 2n), warp tile 32x64.
// ---------------------------------------------------------------------------
#define GBM 128
#define GBN 128
#define GBK 32
#define BKP 40                         // padded row stride (elements): bank-clean
#define PLANE (128 * BKP * 2)          // 10240 B per tile plane
#define BUFB  (4 * PLANE)              // Ah,Al,Bh,Bl = 40960 B per buffer
#define GSMEM (2 * BUFB)               // 81920 B
#define NKC (HID / GBK)                // 24 k-chunks

__global__ __launch_bounds__(256)
void gemm_mma_kernel(float* __restrict__ outp,
                     const float* __restrict__ bias_v,
                     const float* __restrict__ bias_o,
                     int which)        // 0: QKV via blockIdx.z, 1: O proj
{
    extern __shared__ char smem[];
    const uint32_t sbase = smem_u32(smem);
    const int tid = threadIdx.x, wid = tid >> 5, lid = tid & 31;

    const int z  = which ? 3 : blockIdx.z;
    const int n0 = blockIdx.x * GBN;
    const int m0 = blockIdx.y * GBM;

    const __nv_bfloat16* gAh = ((z == 3) ? g_oh : g_ah) + (size_t)m0 * HID;
    const __nv_bfloat16* gAl = ((z == 3) ? g_ol : g_al) + (size_t)m0 * HID;
    const __nv_bfloat16* gBh = g_wh + (size_t)z * WSZ + (size_t)n0 * HID;
    const __nv_bfloat16* gBl = g_wl + (size_t)z * WSZ + (size_t)n0 * HID;
    float* C = (z == 0) ? g_q : (z == 1) ? g_k : (z == 2) ? g_v : outp;
    const float* bias = (z == 2) ? bias_v : (z == 3) ? bias_o : nullptr;

    // ---- loader coordinates: 512 (row,16B-seg) items over 256 threads x2 ----
    const int lr = tid >> 2;               // row 0..63 (and +64)
    const int ls = (tid & 3) * 8;          // k-seg (elements)
    const size_t gofs0 = (size_t)lr * HID + ls;
    const size_t gofs1 = (size_t)(lr + 64) * HID + ls;
    const uint32_t eofs0 = (lr * BKP + ls) * 2;         // smem byte offsets
    const uint32_t eofs1 = ((lr + 64) * BKP + ls) * 2;

    // ---- mma coordinates ----
    const int wm = wid & 3, wn = wid >> 2;
    const int gr = lid >> 2, tq = (lid & 3) * 2;
    // ldmatrix lane->row/k mapping (see fragment layouts, PTX ISA m16n8k16)
    const int rA = (lid & 7) + ((lid >> 3) & 1) * 8;
    const int kA = (lid >> 4) * 8;
    const int rB = (lid & 7) + (lid >> 4) * 8;
    const int kB = ((lid >> 3) & 1) * 8;
    const uint32_t aoff = sbase + ((wm * 32 + rA) * BKP + kA) * 2;          // Ah plane
    const uint32_t boff = sbase + 2 * PLANE + ((wn * 64 + rB) * BKP + kB) * 2; // Bh plane

    float c[2][8][4];
#pragma unroll
    for (int mi = 0; mi < 2; mi++)
#pragma unroll
        for (int ni = 0; ni < 8; ni++)
#pragma unroll
            for (int r = 0; r < 4; r++) c[mi][ni][r] = 0.f;

    uint4 pAh0, pAh1, pAl0, pAl1, pBh0, pBh1, pBl0, pBl1;

    // chunk 0 -> buffer 0
    pAh0 = *(const uint4*)(gAh + gofs0); pAh1 = *(const uint4*)(gAh + gofs1);
    pAl0 = *(const uint4*)(gAl + gofs0); pAl1 = *(const uint4*)(gAl + gofs1);
    pBh0 = *(const uint4*)(gBh + gofs0); pBh1 = *(const uint4*)(gBh + gofs1);
    pBl0 = *(const uint4*)(gBl + gofs0); pBl1 = *(const uint4*)(gBl + gofs1);
    {
        char* s = smem;
        *(uint4*)(s + 0 * PLANE + eofs0) = pAh0; *(uint4*)(s + 0 * PLANE + eofs1) = pAh1;
        *(uint4*)(s + 1 * PLANE + eofs0) = pAl0; *(uint4*)(s + 1 * PLANE + eofs1) = pAl1;
        *(uint4*)(s + 2 * PLANE + eofs0) = pBh0; *(uint4*)(s + 2 * PLANE + eofs1) = pBh1;
        *(uint4*)(s + 3 * PLANE + eofs0) = pBl0; *(uint4*)(s + 3 * PLANE + eofs1) = pBl1;
    }
    __syncthreads();

    int buf = 0;
#pragma unroll 1
    for (int t = 0; t < NKC; t++) {
        if (t + 1 < NKC) {                         // prefetch next chunk
            const int ko = (t + 1) * GBK;
            pAh0 = *(const uint4*)(gAh + gofs0 + ko); pAh1 = *(const uint4*)(gAh + gofs1 + ko);
            pAl0 = *(const uint4*)(gAl + gofs0 + ko); pAl1 = *(const uint4*)(gAl + gofs1 + ko);
            pBh0 = *(const uint4*)(gBh + gofs0 + ko); pBh1 = *(const uint4*)(gBh + gofs1 + ko);
            pBl0 = *(const uint4*)(gBl + gofs0 + ko); pBl1 = *(const uint4*)(gBl + gofs1 + ko);
        }

        const uint32_t bb = buf * BUFB;
#pragma unroll
        for (int ks = 0; ks < 2; ks++) {
            uint32_t Ah[2][4], Al[2][4];
            ldm4(Ah[0], aoff + bb + ks * 32);
            ldm4(Ah[1], aoff + bb + ks * 32 + 16 * BKP * 2);
            ldm4(Al[0], aoff + bb + PLANE + ks * 32);
            ldm4(Al[1], aoff + bb + PLANE + ks * 32 + 16 * BKP * 2);
#pragma unroll
            for (int np = 0; np < 4; np++) {
                uint32_t Bh[4], Bl[4];
                ldm4(Bh, boff + bb + ks * 32 + np * 16 * BKP * 2);
                ldm4(Bl, boff + bb + PLANE + ks * 32 + np * 16 * BKP * 2);
#pragma unroll
                for (int mi = 0; mi < 2; mi++) {
                    mma16816(c[mi][np * 2],     Ah[mi], Bh[0], Bh[1]);
                    mma16816(c[mi][np * 2 + 1], Ah[mi], Bh[2], Bh[3]);
                    mma16816(c[mi][np * 2],     Al[mi], Bh[0], Bh[1]);
                    mma16816(c[mi][np * 2 + 1], Al[mi], Bh[2], Bh[3]);
                    mma16816(c[mi][np * 2],     Ah[mi], Bl[0], Bl[1]);
                    mma16816(c[mi][np * 2 + 1], Ah[mi], Bl[2], Bl[3]);
                }
            }
        }

        if (t + 1 < NKC) {                         // store prefetched -> other buf
            char* s = smem + (buf ^ 1) * BUFB;
            *(uint4*)(s + 0 * PLANE + eofs0) = pAh0; *(uint4*)(s + 0 * PLANE + eofs1) = pAh1;
            *(uint4*)(s + 1 * PLANE + eofs0) = pAl0; *(uint4*)(s + 1 * PLANE + eofs1) = pAl1;
            *(uint4*)(s + 2 * PLANE + eofs0) = pBh0; *(uint4*)(s + 2 * PLANE + eofs1) = pBh1;
            *(uint4*)(s + 3 * PLANE + eofs0) = pBl0; *(uint4*)(s + 3 * PLANE + eofs1) = pBl1;
        }
        __syncthreads();
        buf ^= 1;
    }

    // ---- epilogue ----
#pragma unroll
    for (int mi = 0; mi < 2; mi++) {
        const int row = m0 + wm * 32 + mi * 16 + gr;
#pragma unroll
        for (int ni = 0; ni < 8; ni++) {
            const int col = n0 + wn * 64 + ni * 8 + tq;
            float b0 = 0.f, b1 = 0.f;
            if (bias) { b0 = bias[col]; b1 = bias[col + 1]; }
            float2 v0 = make_float2(c[mi][ni][0] + b0, c[mi][ni][1] + b1);
            float2 v1 = make_float2(c[mi][ni][2] + b0, c[mi][ni][3] + b1);
            *(float2*)(C + (size_t)row * HID + col)       = v0;
            *(float2*)(C + (size_t)(row + 8) * HID + col) = v1;
        }
    }
}

// ---------------------------------------------------------------------------
// exp2 on the FMA pipe (softmax args are <= 0; clamp at -80)
// ---------------------------------------------------------------------------
__device__ __forceinline__ float fast_exp2(float x)
{
    x = fmaxf(x, -80.0f);
    float n = rintf(x);
    float f = x - n;
    float p = 1.5403530e-4f;
    p = fmaf(p, f, 1.3333558e-3f);
    p = fmaf(p, f, 9.6181291e-3f);
    p = fmaf(p, f, 5.5504109e-2f);
    p = fmaf(p, f, 2.4022651e-1f);
    p = fmaf(p, f, 6.9314718e-1f);
    p = fmaf(p, f, 1.0f);
    return p * __int_as_float(((int)n + 127) << 23);
}

// ---------------------------------------------------------------------------
// Flash-style attention (unchanged from R5). One CTA per (b, h, 64-q tile).
// ---------------------------------------------------------------------------
#define ATTN_SMEM ((64 * 64 + 64 * 65 + 64 * 64) * 4)

__global__ __launch_bounds__(256)
void attn_kernel(const float* __restrict__ ebias)
{
    extern __shared__ float sm[];
    float* Qs = sm;
    float* KV = sm + 64 * 64;
    float* Ps = KV + 64 * 65;

    const int tid = threadIdx.x;
    const int tx  = tid & 15;
    const int ty  = tid >> 4;
    const int qt  = blockIdx.x;
    const int h   = blockIdx.y;
    const int b   = blockIdx.z;
    const int q0  = qt * 64;

    const float* qg = g_q + ((size_t)(b * NSEQ + q0)) * HID + h * DHEAD;
    const float* kg = g_k + ((size_t)b * NSEQ) * HID + h * DHEAD;
    const float* vg = g_v + ((size_t)b * NSEQ) * HID + h * DHEAD;
    const float* bg = ebias + ((size_t)(b * NSEQ + q0)) * NSEQ;

#pragma unroll
    for (int l = 0; l < 4; l++) {
        int idx = tid + l * 256;
        int row = idx >> 4;
        int d4  = (idx & 15) * 4;
        *(float4*)(Qs + row * 64 + d4) =
            *(const float4*)(qg + (size_t)row * HID + d4);
    }

    float acc[4][4];
    float mrow[4], rsum[4];
    int   nz[4];
#pragma unroll
    for (int i = 0; i < 4; i++) {
        mrow[i] = -1e30f; rsum[i] = 0.f; nz[i] = 0;
#pragma unroll
        for (int j = 0; j < 4; j++) acc[i][j] = 0.f;
    }

    for (int kc = 0; kc < 8; kc++) {
        __syncthreads();
#pragma unroll
        for (int l = 0; l < 4; l++) {
            int idx = tid + l * 256;
            int key = idx >> 4;
            int d4  = (idx & 15) * 4;
            float4 v = *(const float4*)(kg + (size_t)(kc * 64 + key) * HID + d4);
            float* p = KV + key * 65 + d4;
            p[0] = v.x; p[1] = v.y; p[2] = v.z; p[3] = v.w;
        }
        __syncthreads();

        float s[4][4];
#pragma unroll
        for (int i = 0; i < 4; i++)
#pragma unroll
            for (int j = 0; j < 4; j++) s[i][j] = 0.f;

#pragma unroll 8
        for (int k4 = 0; k4 < 16; k4++) {
            float4 a[4];
#pragma unroll
            for (int i = 0; i < 4; i++)
                a[i] = *(const float4*)(Qs + (ty * 4 + i) * 64 + k4 * 4);
#pragma unroll
            for (int j = 0; j < 4; j++) {
                const float* kp = KV + (size_t)(tx * 4 + j) * 65 + k4 * 4;
                float b0 = kp[0], b1 = kp[1], b2 = kp[2], b3 = kp[3];
#pragma unroll
                for (int i = 0; i < 4; i++) {
                    s[i][j] = fmaf(a[i].x, b0, s[i][j]);
                    s[i][j] = fmaf(a[i].y, b1, s[i][j]);
                    s[i][j] = fmaf(a[i].z, b2, s[i][j]);
                    s[i][j] = fmaf(a[i].w, b3, s[i][j]);
                }
            }
        }

#pragma unroll
        for (int i = 0; i < 4; i++) {
            float4 bb = *(const float4*)(bg + (size_t)(ty * 4 + i) * NSEQ + kc * 64 + tx * 4);
            s[i][0] = fmaf(s[i][0], SCALE_F, bb.x);
            s[i][1] = fmaf(s[i][1], SCALE_F, bb.y);
            s[i][2] = fmaf(s[i][2], SCALE_F, bb.z);
            s[i][3] = fmaf(s[i][3], SCALE_F, bb.w);

            float mc = fmaxf(fmaxf(s[i][0], s[i][1]), fmaxf(s[i][2], s[i][3]));
            int nzc = (s[i][0] != 0.f) | (s[i][1] != 0.f) |
                      (s[i][2] != 0.f) | (s[i][3] != 0.f);
#pragma unroll
            for (int o = 1; o < 16; o <<= 1) {
                mc   = fmaxf(mc, __shfl_xor_sync(0xffffffffu, mc, o));
                nzc |= __shfl_xor_sync(0xffffffffu, nzc, o);
            }
            nz[i] |= nzc;
            float mnew = fmaxf(mrow[i], mc);
            float corr = fast_exp2((mrow[i] - mnew) * LOG2E_F);
            mrow[i] = mnew;

            float p0 = fast_exp2((s[i][0] - mnew) * LOG2E_F);
            float p1 = fast_exp2((s[i][1] - mnew) * LOG2E_F);
            float p2 = fast_exp2((s[i][2] - mnew) * LOG2E_F);
            float p3 = fast_exp2((s[i][3] - mnew) * LOG2E_F);

            float ps = (p0 + p1) + (p2 + p3);
#pragma unroll
            for (int o = 1; o < 16; o <<= 1)
                ps += __shfl_xor_sync(0xffffffffu, ps, o);
            rsum[i] = rsum[i] * corr + ps;
#pragma unroll
            for (int j = 0; j < 4; j++) acc[i][j] *= corr;

            *(float4*)(Ps + (ty * 4 + i) * 64 + tx * 4) = make_float4(p0, p1, p2, p3);
        }
        __syncthreads();

#pragma unroll
        for (int l = 0; l < 4; l++) {
            int idx = tid + l * 256;
            int key = idx >> 4;
            int d4  = (idx & 15) * 4;
            float4 v = *(const float4*)(vg + (size_t)(kc * 64 + key) * HID + d4);
            float* p = KV + key * 65 + d4;
            p[0] = v.x; p[1] = v.y; p[2] = v.z; p[3] = v.w;
        }
        __syncthreads();

#pragma unroll 8
        for (int k4 = 0; k4 < 16; k4++) {
            float av[4][4];
#pragma unroll
            for (int i = 0; i < 4; i++) {
                float4 a = *(const float4*)(Ps + (ty * 4 + i) * 64 + k4 * 4);
                av[i][0] = a.x; av[i][1] = a.y; av[i][2] = a.z; av[i][3] = a.w;
            }
#pragma unroll
            for (int kk = 0; kk < 4; kk++) {
                const float* vp = KV + (size_t)(k4 * 4 + kk) * 65 + tx * 4;
                float b0 = vp[0], b1 = vp[1], b2 = vp[2], b3 = vp[3];
#pragma unroll
                for (int i = 0; i < 4; i++) {
                    acc[i][0] = fmaf(av[i][kk], b0, acc[i][0]);
                    acc[i][1] = fmaf(av[i][kk], b1, acc[i][1]);
                    acc[i][2] = fmaf(av[i][kk], b2, acc[i][2]);
                    acc[i][3] = fmaf(av[i][kk], b3, acc[i][3]);
                }
            }
        }
    }

    float* og = g_o + ((size_t)(b * NSEQ + q0)) * HID + h * DHEAD;
#pragma unroll
    for (int i = 0; i < 4; i++) {
        float inv = nz[i] ? (1.f / rsum[i]) : 0.f;
        float4 o = make_float4(acc[i][0] * inv, acc[i][1] * inv,
                               acc[i][2] * inv, acc[i][3] * inv);
        *(float4*)(og + (size_t)(ty * 4 + i) * HID + tx * 4) = o;
    }
}

// ---------------------------------------------------------------------------
// inputs: x, encoding_bias, Wq, Wk, Wv, bv, Wo, bo
// ---------------------------------------------------------------------------
extern "C" void kernel_launch(void* const* d_in, const int* in_sizes, int n_in,
                              void* d_out, int out_size)
{
    const float* x  = (const float*)d_in[0];
    const float* eb = (const float*)d_in[1];
    const float* Wq = (const float*)d_in[2];
    const float* Wk = (const float*)d_in[3];
    const float* Wv = (const float*)d_in[4];
    const float* bv = (const float*)d_in[5];
    const float* Wo = (const float*)d_in[6];
    const float* bo = (const float*)d_in[7];
    float* out = (float*)d_out;

    cudaFuncSetAttribute(attn_kernel,
                         cudaFuncAttributeMaxDynamicSharedMemorySize, ATTN_SMEM);
    cudaFuncSetAttribute(gemm_mma_kernel,
                         cudaFuncAttributeMaxDynamicSharedMemorySize, GSMEM);

    const int nx4 = MTOT * HID / 4;
    const int nw4 = WSZ / 4;

    conv_split_kernel<<<(nx4 + 255) / 256, 256>>>(x,  0, nx4);
    conv_split_kernel<<<(nw4 + 255) / 256, 256>>>(Wq, 1, nw4);
    conv_split_kernel<<<(nw4 + 255) / 256, 256>>>(Wk, 2, nw4);
    conv_split_kernel<<<(nw4 + 255) / 256, 256>>>(Wv, 3, nw4);
    conv_split_kernel<<<(nw4 + 255) / 256, 256>>>(Wo, 4, nw4);

    gemm_mma_kernel<<<dim3(HID / GBN, MTOT / GBM, 3), 256, GSMEM>>>(
        nullptr, bv, nullptr, 0);                                   // Q, K, V

    attn_kernel<<<dim3(8, NHEAD, 16), 256, ATTN_SMEM>>>(eb);

    conv_split_kernel<<<(nx4 + 255) / 256, 256>>>(nullptr, 5, nx4); // split g_o

    gemm_mma_kernel<<<dim3(HID / GBN, MTOT / GBM, 1), 256, GSMEM>>>(
        out, nullptr, bo, 1);                                       // O proj
}

// round 10
// speedup vs baseline: 1.6126x; 1.0016x over previous
#include <cuda_runtime.h>
#include <cuda_bf16.h>
#include <cstdint>

// ---------------------------------------------------------------------------
// GraphormerMultiHeadAttention  (B=16, N=512, HIDDEN=768, 12 heads x 64)
//
//   1) split x, W* into bf16 hi/lo planes
//   2) mma.sync bf16 GEMM (3-term split = fp32-grade): QKV fused; later O
//   3) SIMT flash attention (unchanged from R5)
//
// NOTE: tcgen05 is ptxas-rejected on this build (.target sm_103 family, no 'a'
// feature). mma.sync / ldmatrix are non-gated and hit the tensor pipe (HMMA).
// ---------------------------------------------------------------------------

#define HID    768
#define MTOT   8192
#define NSEQ   512
#define NHEAD  12
#define DHEAD  64
#define SCALE_F 0.03608439182435161f   // 768^-0.5
#define LOG2E_F 1.4426950408889634f
#define WSZ (HID * HID)

// ---------------- scratch (device globals; allocation-free) ----------------
__device__ float g_q[MTOT * HID];
__device__ float g_k[MTOT * HID];
__device__ float g_v[MTOT * HID];
__device__ float g_o[MTOT * HID];
__device__ __align__(16) __nv_bfloat16 g_ah[MTOT * HID];
__device__ __align__(16) __nv_bfloat16 g_al[MTOT * HID];
__device__ __align__(16) __nv_bfloat16 g_oh[MTOT * HID];
__device__ __align__(16) __nv_bfloat16 g_ol[MTOT * HID];
__device__ __align__(16) __nv_bfloat16 g_wh[4 * WSZ];
__device__ __align__(16) __nv_bfloat16 g_wl[4 * WSZ];

// ---------------------------------------------------------------------------
// fp32 -> (hi, lo) bf16 split. mode selects destination device globals so no
// cudaGetSymbolAddress is needed during graph capture.
//   0: x -> g_ah/g_al   1..4: W(mode-1) -> g_wh/g_wl   5: g_o -> g_oh/g_ol
// ---------------------------------------------------------------------------
__global__ void conv_split_kernel(const float* __restrict__ src, int mode, int n4)
{
    int i = blockIdx.x * blockDim.x + threadIdx.x;
    if (i >= n4) return;

    __nv_bfloat16 *hi, *lo;
    const float* s = src;
    if (mode == 0)       { hi = g_ah; lo = g_al; }
    else if (mode <= 4)  { hi = g_wh + (size_t)(mode - 1) * WSZ;
                           lo = g_wl + (size_t)(mode - 1) * WSZ; }
    else                 { hi = g_oh; lo = g_ol; s = g_o; }

    float4 v = ((const float4*)s)[i];
    __nv_bfloat16 h0 = __float2bfloat16_rn(v.x);
    __nv_bfloat16 h1 = __float2bfloat16_rn(v.y);
    __nv_bfloat16 h2 = __float2bfloat16_rn(v.z);
    __nv_bfloat16 h3 = __float2bfloat16_rn(v.w);
    __nv_bfloat162 H0, H1, L0, L1;
    H0.x = h0; H0.y = h1; H1.x = h2; H1.y = h3;
    L0.x = __float2bfloat16_rn(v.x - __bfloat162float(h0));
    L0.y = __float2bfloat16_rn(v.y - __bfloat162float(h1));
    L1.x = __float2bfloat16_rn(v.z - __bfloat162float(h2));
    L1.y = __float2bfloat16_rn(v.w - __bfloat162float(h3));
    ((__nv_bfloat162*)hi)[2 * i]     = H0;
    ((__nv_bfloat162*)hi)[2 * i + 1] = H1;
    ((__nv_bfloat162*)lo)[2 * i]     = L0;
    ((__nv_bfloat162*)lo)[2 * i + 1] = L1;
}

// ---------------------------------------------------------------------------
// warp-mma helpers
// ---------------------------------------------------------------------------
__device__ __forceinline__ uint32_t smem_u32(const void* p)
{
    uint32_t a;
    asm("{ .reg .u64 t; cvta.to.shared.u64 t, %1; cvt.u32.u64 %0, t; }"
        : "=r"(a) : "l"(p));
    return a;
}
__device__ __forceinline__ void ldm4(uint32_t* r, uint32_t addr)
{
    asm volatile("ldmatrix.sync.aligned.m8n8.x4.shared.b16 {%0,%1,%2,%3}, [%4];"
                 : "=r"(r[0]), "=r"(r[1]), "=r"(r[2]), "=r"(r[3]) : "r"(addr));
}
__device__ __forceinline__ void mma16816(float* c, const uint32_t* a,
                                         uint32_t b0, uint32_t b1)
{
    asm volatile(
        "mma.sync.aligned.m16n8k16.row.col.f32.bf16.bf16.f32 "
        "{%0,%1,%2,%3}, {%4,%5,%6,%7}, {%8,%9}, {%0,%1,%2,%3};"
        : "+f"(c[0]), "+f"(c[1]), "+f"(c[2]), "+f"(c[3])
        : "r"(a[0]), "r"(a[1]), "r"(a[2]), "r"(a[3]), "r"(b0), "r"(b1));
}

// ---------------------------------------------------------------------------
// GEMM-NT: C[m][n] = sum_k A[m][k] * W[n][k] (+ bias[n]) via mma.sync bf16,
// 3-term split. CTA 128x128x(k32), 8 warps (4m x 2n), warp tile 32x64.
// ---------------------------------------------------------------------------
#define GBM 128
#define GBN 128
#define GBK 32
#define BKP 40                         // padded row stride (elements): bank-clean
#define PLANE (128 * BKP * 2)          // 10240 B per tile plane
#define BUFB  (4 * PLANE)              // Ah,Al,Bh,Bl = 40960 B per buffer
#define GSMEM (2 * BUFB)               // 81920 B
#define NKC (HID / GBK)                // 24 k-chunks

__global__ __launch_bounds__(256)
void gemm_mma_kernel(float* __restrict__ outp,
                     const float* __restrict__ bias_v,
                     const float* __restrict__ bias_o,
                     int which)        // 0: QKV via blockIdx.z, 1: O proj
{
    extern __shared__ char smem[];
    const uint32_t sbase = smem_u32(smem);
    const int tid = threadIdx.x, wid = tid >> 5, lid = tid & 31;

    const int z  = which ? 3 : blockIdx.z;
    const int n0 = blockIdx.x * GBN;
    const int m0 = blockIdx.y * GBM;

    const __nv_bfloat16* gAh = ((z == 3) ? g_oh : g_ah) + (size_t)m0 * HID;
    const __nv_bfloat16* gAl = ((z == 3) ? g_ol : g_al) + (size_t)m0 * HID;
    const __nv_bfloat16* gBh = g_wh + (size_t)z * WSZ + (size_t)n0 * HID;
    const __nv_bfloat16* gBl = g_wl + (size_t)z * WSZ + (size_t)n0 * HID;
    float* C = (z == 0) ? g_q : (z == 1) ? g_k : (z == 2) ? g_v : outp;
    const float* bias = (z == 2) ? bias_v : (z == 3) ? bias_o : nullptr;

    // ---- loader coordinates: 512 (row,16B-seg) items over 256 threads x2 ----
    const int lr = tid >> 2;               // row 0..63 (and +64)
    const int ls = (tid & 3) * 8;          // k-seg (elements)
    const size_t gofs0 = (size_t)lr * HID + ls;
    const size_t gofs1 = (size_t)(lr + 64) * HID + ls;
    const uint32_t eofs0 = (lr * BKP + ls) * 2;         // smem byte offsets
    const uint32_t eofs1 = ((lr + 64) * BKP + ls) * 2;

    // ---- mma coordinates ----
    const int wm = wid & 3, wn = wid >> 2;
    const int gr = lid >> 2, tq = (lid & 3) * 2;
    // ldmatrix lane->row/k mapping (see fragment layouts, PTX ISA m16n8k16)
    const int rA = (lid & 7) + ((lid >> 3) & 1) * 8;
    const int kA = (lid >> 4) * 8;
    const int rB = (lid & 7) + (lid >> 4) * 8;
    const int kB = ((lid >> 3) & 1) * 8;
    const uint32_t aoff = sbase + ((wm * 32 + rA) * BKP + kA) * 2;          // Ah plane
    const uint32_t boff = sbase + 2 * PLANE + ((wn * 64 + rB) * BKP + kB) * 2; // Bh plane

    float c[2][8][4];
#pragma unroll
    for (int mi = 0; mi < 2; mi++)
#pragma unroll
        for (int ni = 0; ni < 8; ni++)
#pragma unroll
            for (int r = 0; r < 4; r++) c[mi][ni][r] = 0.f;

    uint4 pAh0, pAh1, pAl0, pAl1, pBh0, pBh1, pBl0, pBl1;

    // chunk 0 -> buffer 0
    pAh0 = *(const uint4*)(gAh + gofs0); pAh1 = *(const uint4*)(gAh + gofs1);
    pAl0 = *(const uint4*)(gAl + gofs0); pAl1 = *(const uint4*)(gAl + gofs1);
    pBh0 = *(const uint4*)(gBh + gofs0); pBh1 = *(const uint4*)(gBh + gofs1);
    pBl0 = *(const uint4*)(gBl + gofs0); pBl1 = *(const uint4*)(gBl + gofs1);
    {
        char* s = smem;
        *(uint4*)(s + 0 * PLANE + eofs0) = pAh0; *(uint4*)(s + 0 * PLANE + eofs1) = pAh1;
        *(uint4*)(s + 1 * PLANE + eofs0) = pAl0; *(uint4*)(s + 1 * PLANE + eofs1) = pAl1;
        *(uint4*)(s + 2 * PLANE + eofs0) = pBh0; *(uint4*)(s + 2 * PLANE + eofs1) = pBh1;
        *(uint4*)(s + 3 * PLANE + eofs0) = pBl0; *(uint4*)(s + 3 * PLANE + eofs1) = pBl1;
    }
    __syncthreads();

    int buf = 0;
#pragma unroll 1
    for (int t = 0; t < NKC; t++) {
        if (t + 1 < NKC) {                         // prefetch next chunk
            const int ko = (t + 1) * GBK;
            pAh0 = *(const uint4*)(gAh + gofs0 + ko); pAh1 = *(const uint4*)(gAh + gofs1 + ko);
            pAl0 = *(const uint4*)(gAl + gofs0 + ko); pAl1 = *(const uint4*)(gAl + gofs1 + ko);
            pBh0 = *(const uint4*)(gBh + gofs0 + ko); pBh1 = *(const uint4*)(gBh + gofs1 + ko);
            pBl0 = *(const uint4*)(gBl + gofs0 + ko); pBl1 = *(const uint4*)(gBl + gofs1 + ko);
        }

        const uint32_t bb = buf * BUFB;
#pragma unroll
        for (int ks = 0; ks < 2; ks++) {
            uint32_t Ah[2][4], Al[2][4];
            ldm4(Ah[0], aoff + bb + ks * 32);
            ldm4(Ah[1], aoff + bb + ks * 32 + 16 * BKP * 2);
            ldm4(Al[0], aoff + bb + PLANE + ks * 32);
            ldm4(Al[1], aoff + bb + PLANE + ks * 32 + 16 * BKP * 2);
#pragma unroll
            for (int np = 0; np < 4; np++) {
                uint32_t Bh[4], Bl[4];
                ldm4(Bh, boff + bb + ks * 32 + np * 16 * BKP * 2);
                ldm4(Bl, boff + bb + PLANE + ks * 32 + np * 16 * BKP * 2);
#pragma unroll
                for (int mi = 0; mi < 2; mi++) {
                    mma16816(c[mi][np * 2],     Ah[mi], Bh[0], Bh[1]);
                    mma16816(c[mi][np * 2 + 1], Ah[mi], Bh[2], Bh[3]);
                    mma16816(c[mi][np * 2],     Al[mi], Bh[0], Bh[1]);
                    mma16816(c[mi][np * 2 + 1], Al[mi], Bh[2], Bh[3]);
                    mma16816(c[mi][np * 2],     Ah[mi], Bl[0], Bl[1]);
                    mma16816(c[mi][np * 2 + 1], Ah[mi], Bl[2], Bl[3]);
                }
            }
        }

        if (t + 1 < NKC) {                         // store prefetched -> other buf
            char* s = smem + (buf ^ 1) * BUFB;
            *(uint4*)(s + 0 * PLANE + eofs0) = pAh0; *(uint4*)(s + 0 * PLANE + eofs1) = pAh1;
            *(uint4*)(s + 1 * PLANE + eofs0) = pAl0; *(uint4*)(s + 1 * PLANE + eofs1) = pAl1;
            *(uint4*)(s + 2 * PLANE + eofs0) = pBh0; *(uint4*)(s + 2 * PLANE + eofs1) = pBh1;
            *(uint4*)(s + 3 * PLANE + eofs0) = pBl0; *(uint4*)(s + 3 * PLANE + eofs1) = pBl1;
        }
        __syncthreads();
        buf ^= 1;
    }

    // ---- epilogue ----
#pragma unroll
    for (int mi = 0; mi < 2; mi++) {
        const int row = m0 + wm * 32 + mi * 16 + gr;
#pragma unroll
        for (int ni = 0; ni < 8; ni++) {
            const int col = n0 + wn * 64 + ni * 8 + tq;
            float b0 = 0.f, b1 = 0.f;
            if (bias) { b0 = bias[col]; b1 = bias[col + 1]; }
            float2 v0 = make_float2(c[mi][ni][0] + b0, c[mi][ni][1] + b1);
            float2 v1 = make_float2(c[mi][ni][2] + b0, c[mi][ni][3] + b1);
            *(float2*)(C + (size_t)row * HID + col)       = v0;
            *(float2*)(C + (size_t)(row + 8) * HID + col) = v1;
        }
    }
}

// ---------------------------------------------------------------------------
// exp2 on the FMA pipe (softmax args are <= 0; clamp at -80)
// ---------------------------------------------------------------------------
__device__ __forceinline__ float fast_exp2(float x)
{
    x = fmaxf(x, -80.0f);
    float n = rintf(x);
    float f = x - n;
    float p = 1.5403530e-4f;
    p = fmaf(p, f, 1.3333558e-3f);
    p = fmaf(p, f, 9.6181291e-3f);
    p = fmaf(p, f, 5.5504109e-2f);
    p = fmaf(p, f, 2.4022651e-1f);
    p = fmaf(p, f, 6.9314718e-1f);
    p = fmaf(p, f, 1.0f);
    return p * __int_as_float(((int)n + 127) << 23);
}

// ---------------------------------------------------------------------------
// Flash-style attention (unchanged from R5). One CTA per (b, h, 64-q tile).
// ---------------------------------------------------------------------------
#define ATTN_SMEM ((64 * 64 + 64 * 65 + 64 * 64) * 4)

__global__ __launch_bounds__(256)
void attn_kernel(const float* __restrict__ ebias)
{
    extern __shared__ float sm[];
    float* Qs = sm;
    float* KV = sm + 64 * 64;
    float* Ps = KV + 64 * 65;

    const int tid = threadIdx.x;
    const int tx  = tid & 15;
    const int ty  = tid >> 4;
    const int qt  = blockIdx.x;
    const int h   = blockIdx.y;
    const int b   = blockIdx.z;
    const int q0  = qt * 64;

    const float* qg = g_q + ((size_t)(b * NSEQ + q0)) * HID + h * DHEAD;
    const float* kg = g_k + ((size_t)b * NSEQ) * HID + h * DHEAD;
    const float* vg = g_v + ((size_t)b * NSEQ) * HID + h * DHEAD;
    const float* bg = ebias + ((size_t)(b * NSEQ + q0)) * NSEQ;

#pragma unroll
    for (int l = 0; l < 4; l++) {
        int idx = tid + l * 256;
        int row = idx >> 4;
        int d4  = (idx & 15) * 4;
        *(float4*)(Qs + row * 64 + d4) =
            *(const float4*)(qg + (size_t)row * HID + d4);
    }

    float acc[4][4];
    float mrow[4], rsum[4];
    int   nz[4];
#pragma unroll
    for (int i = 0; i < 4; i++) {
        mrow[i] = -1e30f; rsum[i] = 0.f; nz[i] = 0;
#pragma unroll
        for (int j = 0; j < 4; j++) acc[i][j] = 0.f;
    }

    for (int kc = 0; kc < 8; kc++) {
        __syncthreads();
#pragma unroll
        for (int l = 0; l < 4; l++) {
            int idx = tid + l * 256;
            int key = idx >> 4;
            int d4  = (idx & 15) * 4;
            float4 v = *(const float4*)(kg + (size_t)(kc * 64 + key) * HID + d4);
            float* p = KV + key * 65 + d4;
            p[0] = v.x; p[1] = v.y; p[2] = v.z; p[3] = v.w;
        }
        __syncthreads();

        float s[4][4];
#pragma unroll
        for (int i = 0; i < 4; i++)
#pragma unroll
            for (int j = 0; j < 4; j++) s[i][j] = 0.f;

#pragma unroll 8
        for (int k4 = 0; k4 < 16; k4++) {
            float4 a[4];
#pragma unroll
            for (int i = 0; i < 4; i++)
                a[i] = *(const float4*)(Qs + (ty * 4 + i) * 64 + k4 * 4);
#pragma unroll
            for (int j = 0; j < 4; j++) {
                const float* kp = KV + (size_t)(tx * 4 + j) * 65 + k4 * 4;
                float b0 = kp[0], b1 = kp[1], b2 = kp[2], b3 = kp[3];
#pragma unroll
                for (int i = 0; i < 4; i++) {
                    s[i][j] = fmaf(a[i].x, b0, s[i][j]);
                    s[i][j] = fmaf(a[i].y, b1, s[i][j]);
                    s[i][j] = fmaf(a[i].z, b2, s[i][j]);
                    s[i][j] = fmaf(a[i].w, b3, s[i][j]);
                }
            }
        }

#pragma unroll
        for (int i = 0; i < 4; i++) {
            float4 bb = *(const float4*)(bg + (size_t)(ty * 4 + i) * NSEQ + kc * 64 + tx * 4);
            s[i][0] = fmaf(s[i][0], SCALE_F, bb.x);
            s[i][1] = fmaf(s[i][1], SCALE_F, bb.y);
            s[i][2] = fmaf(s[i][2], SCALE_F, bb.z);
            s[i][3] = fmaf(s[i][3], SCALE_F, bb.w);

            float mc = fmaxf(fmaxf(s[i][0], s[i][1]), fmaxf(s[i][2], s[i][3]));
            int nzc = (s[i][0] != 0.f) | (s[i][1] != 0.f) |
                      (s[i][2] != 0.f) | (s[i][3] != 0.f);
#pragma unroll
            for (int o = 1; o < 16; o <<= 1) {
                mc   = fmaxf(mc, __shfl_xor_sync(0xffffffffu, mc, o));
                nzc |= __shfl_xor_sync(0xffffffffu, nzc, o);
            }
            nz[i] |= nzc;
            float mnew = fmaxf(mrow[i], mc);
            float corr = fast_exp2((mrow[i] - mnew) * LOG2E_F);
            mrow[i] = mnew;

            float p0 = fast_exp2((s[i][0] - mnew) * LOG2E_F);
            float p1 = fast_exp2((s[i][1] - mnew) * LOG2E_F);
            float p2 = fast_exp2((s[i][2] - mnew) * LOG2E_F);
            float p3 = fast_exp2((s[i][3] - mnew) * LOG2E_F);

            float ps = (p0 + p1) + (p2 + p3);
#pragma unroll
            for (int o = 1; o < 16; o <<= 1)
                ps += __shfl_xor_sync(0xffffffffu, ps, o);
            rsum[i] = rsum[i] * corr + ps;
#pragma unroll
            for (int j = 0; j < 4; j++) acc[i][j] *= corr;

            *(float4*)(Ps + (ty * 4 + i) * 64 + tx * 4) = make_float4(p0, p1, p2, p3);
        }
        __syncthreads();

#pragma unroll
        for (int l = 0; l < 4; l++) {
            int idx = tid + l * 256;
            int key = idx >> 4;
            int d4  = (idx & 15) * 4;
            float4 v = *(const float4*)(vg + (size_t)(kc * 64 + key) * HID + d4);
            float* p = KV + key * 65 + d4;
            p[0] = v.x; p[1] = v.y; p[2] = v.z; p[3] = v.w;
        }
        __syncthreads();

#pragma unroll 8
        for (int k4 = 0; k4 < 16; k4++) {
            float av[4][4];
#pragma unroll
            for (int i = 0; i < 4; i++) {
                float4 a = *(const float4*)(Ps + (ty * 4 + i) * 64 + k4 * 4);
                av[i][0] = a.x; av[i][1] = a.y; av[i][2] = a.z; av[i][3] = a.w;
            }
#pragma unroll
            for (int kk = 0; kk < 4; kk++) {
                const float* vp = KV + (size_t)(k4 * 4 + kk) * 65 + tx * 4;
                float b0 = vp[0], b1 = vp[1], b2 = vp[2], b3 = vp[3];
#pragma unroll
                for (int i = 0; i < 4; i++) {
                    acc[i][0] = fmaf(av[i][kk], b0, acc[i][0]);
                    acc[i][1] = fmaf(av[i][kk], b1, acc[i][1]);
                    acc[i][2] = fmaf(av[i][kk], b2, acc[i][2]);
                    acc[i][3] = fmaf(av[i][kk], b3, acc[i][3]);
                }
            }
        }
    }

    float* og = g_o + ((size_t)(b * NSEQ + q0)) * HID + h * DHEAD;
#pragma unroll
    for (int i = 0; i < 4; i++) {
        float inv = nz[i] ? (1.f / rsum[i]) : 0.f;
        float4 o = make_float4(acc[i][0] * inv, acc[i][1] * inv,
                               acc[i][2] * inv, acc[i][3] * inv);
        *(float4*)(og + (size_t)(ty * 4 + i) * HID + tx * 4) = o;
    }
}

// ---------------------------------------------------------------------------
// inputs: x, encoding_bias, Wq, Wk, Wv, bv, Wo, bo
// ---------------------------------------------------------------------------
extern "C" void kernel_launch(void* const* d_in, const int* in_sizes, int n_in,
                              void* d_out, int out_size)
{
    const float* x  = (const float*)d_in[0];
    const float* eb = (const float*)d_in[1];
    const float* Wq = (const float*)d_in[2];
    const float* Wk = (const float*)d_in[3];
    const float* Wv = (const float*)d_in[4];
    const float* bv = (const float*)d_in[5];
    const float* Wo = (const float*)d_in[6];
    const float* bo = (const float*)d_in[7];
    float* out = (float*)d_out;

    cudaFuncSetAttribute(attn_kernel,
                         cudaFuncAttributeMaxDynamicSharedMemorySize, ATTN_SMEM);
    cudaFuncSetAttribute(gemm_mma_kernel,
                         cudaFuncAttributeMaxDynamicSharedMemorySize, GSMEM);

    const int nx4 = MTOT * HID / 4;
    const int nw4 = WSZ / 4;

    conv_split_kernel<<<(nx4 + 255) / 256, 256>>>(x,  0, nx4);
    conv_split_kernel<<<(nw4 + 255) / 256, 256>>>(Wq, 1, nw4);
    conv_split_kernel<<<(nw4 + 255) / 256, 256>>>(Wk, 2, nw4);
    conv_split_kernel<<<(nw4 + 255) / 256, 256>>>(Wv, 3, nw4);
    conv_split_kernel<<<(nw4 + 255) / 256, 256>>>(Wo, 4, nw4);

    gemm_mma_kernel<<<dim3(HID / GBN, MTOT / GBM, 3), 256, GSMEM>>>(
        nullptr, bv, nullptr, 0);                                   // Q, K, V

    attn_kernel<<<dim3(8, NHEAD, 16), 256, ATTN_SMEM>>>(eb);

    conv_split_kernel<<<(nx4 + 255) / 256, 256>>>(nullptr, 5, nx4); // split g_o

    gemm_mma_kernel<<<dim3(HID / GBN, MTOT / GBM, 1), 256, GSMEM>>>(
        out, nullptr, bo, 1);                                       // O proj
}

// round 11
// speedup vs baseline: 2.3451x; 1.4542x over previous
#include <cuda_runtime.h>
#include <cuda_bf16.h>
#include <cstdint>

// ---------------------------------------------------------------------------
// GraphormerMultiHeadAttention  (B=16, N=512, HIDDEN=768, 12 heads x 64)
//
//   1) split x, W* into bf16 hi/lo planes
//   2) mma.sync bf16 GEMM (3-term split): QKV fused -> bf16 hi/lo outputs
//      (scale folded into Q)
//   3) mma.sync bf16 flash attention (3-term QK^T and PV), exact pad-mask
//   4) mma.sync GEMM O projection -> fp32 out
// ---------------------------------------------------------------------------

#define HID    768
#define MTOT   8192
#define NSEQ   512
#define NHEAD  12
#define DHEAD  64
#define SCALE_F 0.03608439182435161f   // 768^-0.5
#define LOG2E_F 1.4426950408889634f
#define WSZ (HID * HID)

// ---------------- scratch (device globals; allocation-free) ----------------
__device__ __align__(16) __nv_bfloat16 g_ah[MTOT * HID];
__device__ __align__(16) __nv_bfloat16 g_al[MTOT * HID];
__device__ __align__(16) __nv_bfloat16 g_qh[MTOT * HID];
__device__ __align__(16) __nv_bfloat16 g_ql[MTOT * HID];
__device__ __align__(16) __nv_bfloat16 g_kh[MTOT * HID];
__device__ __align__(16) __nv_bfloat16 g_kl[MTOT * HID];
__device__ __align__(16) __nv_bfloat16 g_vh[MTOT * HID];
__device__ __align__(16) __nv_bfloat16 g_vl[MTOT * HID];
__device__ __align__(16) __nv_bfloat16 g_oh[MTOT * HID];
__device__ __align__(16) __nv_bfloat16 g_ol[MTOT * HID];
__device__ __align__(16) __nv_bfloat16 g_wh[4 * WSZ];
__device__ __align__(16) __nv_bfloat16 g_wl[4 * WSZ];

// ---------------------------------------------------------------------------
// fp32 -> (hi, lo) bf16 split. mode 0: x -> g_ah/g_al, 1..4: W(mode-1)
// ---------------------------------------------------------------------------
__global__ void conv_split_kernel(const float* __restrict__ src, int mode, int n4)
{
    int i = blockIdx.x * blockDim.x + threadIdx.x;
    if (i >= n4) return;

    __nv_bfloat16 *hi, *lo;
    if (mode == 0) { hi = g_ah; lo = g_al; }
    else           { hi = g_wh + (size_t)(mode - 1) * WSZ;
                     lo = g_wl + (size_t)(mode - 1) * WSZ; }

    float4 v = ((const float4*)src)[i];
    __nv_bfloat16 h0 = __float2bfloat16_rn(v.x);
    __nv_bfloat16 h1 = __float2bfloat16_rn(v.y);
    __nv_bfloat16 h2 = __float2bfloat16_rn(v.z);
    __nv_bfloat16 h3 = __float2bfloat16_rn(v.w);
    __nv_bfloat162 H0, H1, L0, L1;
    H0.x = h0; H0.y = h1; H1.x = h2; H1.y = h3;
    L0.x = __float2bfloat16_rn(v.x - __bfloat162float(h0));
    L0.y = __float2bfloat16_rn(v.y - __bfloat162float(h1));
    L1.x = __float2bfloat16_rn(v.z - __bfloat162float(h2));
    L1.y = __float2bfloat16_rn(v.w - __bfloat162float(h3));
    ((__nv_bfloat162*)hi)[2 * i]     = H0;
    ((__nv_bfloat162*)hi)[2 * i + 1] = H1;
    ((__nv_bfloat162*)lo)[2 * i]     = L0;
    ((__nv_bfloat162*)lo)[2 * i + 1] = L1;
}

// ---------------------------------------------------------------------------
// warp-mma helpers
// ---------------------------------------------------------------------------
__device__ __forceinline__ uint32_t smem_u32(const void* p)
{
    uint32_t a;
    asm("{ .reg .u64 t; cvta.to.shared.u64 t, %1; cvt.u32.u64 %0, t; }"
        : "=r"(a) : "l"(p));
    return a;
}
__device__ __forceinline__ void ldm4(uint32_t* r, uint32_t addr)
{
    asm volatile("ldmatrix.sync.aligned.m8n8.x4.shared.b16 {%0,%1,%2,%3}, [%4];"
                 : "=r"(r[0]), "=r"(r[1]), "=r"(r[2]), "=r"(r[3]) : "r"(addr));
}
__device__ __forceinline__ void ldm4t(uint32_t* r, uint32_t addr)
{
    asm volatile("ldmatrix.sync.aligned.m8n8.x4.trans.shared.b16 {%0,%1,%2,%3}, [%4];"
                 : "=r"(r[0]), "=r"(r[1]), "=r"(r[2]), "=r"(r[3]) : "r"(addr));
}
__device__ __forceinline__ void mma16816(float* c, const uint32_t* a,
                                         uint32_t b0, uint32_t b1)
{
    asm volatile(
        "mma.sync.aligned.m16n8k16.row.col.f32.bf16.bf16.f32 "
        "{%0,%1,%2,%3}, {%4,%5,%6,%7}, {%8,%9}, {%0,%1,%2,%3};"
        : "+f"(c[0]), "+f"(c[1]), "+f"(c[2]), "+f"(c[3])
        : "r"(a[0]), "r"(a[1]), "r"(a[2]), "r"(a[3]), "r"(b0), "r"(b1));
}
// pack two fp32 into bf16x2 hi + bf16x2 lo
__device__ __forceinline__ void split2(float x, float y, uint32_t& h, uint32_t& l)
{
    __nv_bfloat162 H, L;
    H.x = __float2bfloat16_rn(x); H.y = __float2bfloat16_rn(y);
    L.x = __float2bfloat16_rn(x - __bfloat162float(H.x));
    L.y = __float2bfloat16_rn(y - __bfloat162float(H.y));
    h = *(uint32_t*)&H; l = *(uint32_t*)&L;
}

// ---------------------------------------------------------------------------
// GEMM-NT: C[m][n] = sum_k A[m][k] * W[n][k] (+ bias[n]) via mma.sync bf16,
// 3-term split. CTA 128x128x(k32), 8 warps (4m x 2n), warp tile 32x64.
// z=0,1,2 -> bf16 hi/lo outputs (q scaled); z=3 -> fp32 out (+bo).
// ---------------------------------------------------------------------------
#define GBM 128
#define GBN 128
#define GBK 32
#define BKP 40
#define PLANE (128 * BKP * 2)
#define BUFB  (4 * PLANE)
#define GSMEM (2 * BUFB)
#define NKC (HID / GBK)

__global__ __launch_bounds__(256)
void gemm_mma_kernel(float* __restrict__ outp,
                     const float* __restrict__ bias_v,
                     const float* __restrict__ bias_o,
                     int which)
{
    extern __shared__ char smem[];
    const uint32_t sbase = smem_u32(smem);
    const int tid = threadIdx.x, wid = tid >> 5, lid = tid & 31;

    const int z  = which ? 3 : blockIdx.z;
    const int n0 = blockIdx.x * GBN;
    const int m0 = blockIdx.y * GBM;

    const __nv_bfloat16* gAh = ((z == 3) ? g_oh : g_ah) + (size_t)m0 * HID;
    const __nv_bfloat16* gAl = ((z == 3) ? g_ol : g_al) + (size_t)m0 * HID;
    const __nv_bfloat16* gBh = g_wh + (size_t)z * WSZ + (size_t)n0 * HID;
    const __nv_bfloat16* gBl = g_wl + (size_t)z * WSZ + (size_t)n0 * HID;

    const int lr = tid >> 2;
    const int ls = (tid & 3) * 8;
    const size_t gofs0 = (size_t)lr * HID + ls;
    const size_t gofs1 = (size_t)(lr + 64) * HID + ls;
    const uint32_t eofs0 = (lr * BKP + ls) * 2;
    const uint32_t eofs1 = ((lr + 64) * BKP + ls) * 2;

    const int wm = wid & 3, wn = wid >> 2;
    const int gr = lid >> 2, tq = (lid & 3) * 2;
    const int rA = (lid & 7) + ((lid >> 3) & 1) * 8;
    const int kA = (lid >> 4) * 8;
    const int rB = (lid & 7) + (lid >> 4) * 8;
    const int kB = ((lid >> 3) & 1) * 8;
    const uint32_t aoff = sbase + ((wm * 32 + rA) * BKP + kA) * 2;
    const uint32_t boff = sbase + 2 * PLANE + ((wn * 64 + rB) * BKP + kB) * 2;

    float c[2][8][4];
#pragma unroll
    for (int mi = 0; mi < 2; mi++)
#pragma unroll
        for (int ni = 0; ni < 8; ni++)
#pragma unroll
            for (int r = 0; r < 4; r++) c[mi][ni][r] = 0.f;

    uint4 pAh0, pAh1, pAl0, pAl1, pBh0, pBh1, pBl0, pBl1;

    pAh0 = *(const uint4*)(gAh + gofs0); pAh1 = *(const uint4*)(gAh + gofs1);
    pAl0 = *(const uint4*)(gAl + gofs0); pAl1 = *(const uint4*)(gAl + gofs1);
    pBh0 = *(const uint4*)(gBh + gofs0); pBh1 = *(const uint4*)(gBh + gofs1);
    pBl0 = *(const uint4*)(gBl + gofs0); pBl1 = *(const uint4*)(gBl + gofs1);
    {
        char* s = smem;
        *(uint4*)(s + 0 * PLANE + eofs0) = pAh0; *(uint4*)(s + 0 * PLANE + eofs1) = pAh1;
        *(uint4*)(s + 1 * PLANE + eofs0) = pAl0; *(uint4*)(s + 1 * PLANE + eofs1) = pAl1;
        *(uint4*)(s + 2 * PLANE + eofs0) = pBh0; *(uint4*)(s + 2 * PLANE + eofs1) = pBh1;
        *(uint4*)(s + 3 * PLANE + eofs0) = pBl0; *(uint4*)(s + 3 * PLANE + eofs1) = pBl1;
    }
    __syncthreads();

    int buf = 0;
#pragma unroll 1
    for (int t = 0; t < NKC; t++) {
        if (t + 1 < NKC) {
            const int ko = (t + 1) * GBK;
            pAh0 = *(const uint4*)(gAh + gofs0 + ko); pAh1 = *(const uint4*)(gAh + gofs1 + ko);
            pAl0 = *(const uint4*)(gAl + gofs0 + ko); pAl1 = *(const uint4*)(gAl + gofs1 + ko);
            pBh0 = *(const uint4*)(gBh + gofs0 + ko); pBh1 = *(const uint4*)(gBh + gofs1 + ko);
            pBl0 = *(const uint4*)(gBl + gofs0 + ko); pBl1 = *(const uint4*)(gBl + gofs1 + ko);
        }

        const uint32_t bb = buf * BUFB;
#pragma unroll
        for (int ks = 0; ks < 2; ks++) {
            uint32_t Ah[2][4], Al[2][4];
            ldm4(Ah[0], aoff + bb + ks * 32);
            ldm4(Ah[1], aoff + bb + ks * 32 + 16 * BKP * 2);
            ldm4(Al[0], aoff + bb + PLANE + ks * 32);
            ldm4(Al[1], aoff + bb + PLANE + ks * 32 + 16 * BKP * 2);
#pragma unroll
            for (int np = 0; np < 4; np++) {
                uint32_t Bh[4], Bl[4];
                ldm4(Bh, boff + bb + ks * 32 + np * 16 * BKP * 2);
                ldm4(Bl, boff + bb + PLANE + ks * 32 + np * 16 * BKP * 2);
#pragma unroll
                for (int mi = 0; mi < 2; mi++) {
                    mma16816(c[mi][np * 2],     Ah[mi], Bh[0], Bh[1]);
                    mma16816(c[mi][np * 2 + 1], Ah[mi], Bh[2], Bh[3]);
                    mma16816(c[mi][np * 2],     Al[mi], Bh[0], Bh[1]);
                    mma16816(c[mi][np * 2 + 1], Al[mi], Bh[2], Bh[3]);
                    mma16816(c[mi][np * 2],     Ah[mi], Bl[0], Bl[1]);
                    mma16816(c[mi][np * 2 + 1], Ah[mi], Bl[2], Bl[3]);
                }
            }
        }

        if (t + 1 < NKC) {
            char* s = smem + (buf ^ 1) * BUFB;
            *(uint4*)(s + 0 * PLANE + eofs0) = pAh0; *(uint4*)(s + 0 * PLANE + eofs1) = pAh1;
            *(uint4*)(s + 1 * PLANE + eofs0) = pAl0; *(uint4*)(s + 1 * PLANE + eofs1) = pAl1;
            *(uint4*)(s + 2 * PLANE + eofs0) = pBh0; *(uint4*)(s + 2 * PLANE + eofs1) = pBh1;
            *(uint4*)(s + 3 * PLANE + eofs0) = pBl0; *(uint4*)(s + 3 * PLANE + eofs1) = pBl1;
        }
        __syncthreads();
        buf ^= 1;
    }

    // ---- epilogue ----
    if (z < 3) {
        __nv_bfloat16* dh = (z == 0) ? g_qh : (z == 1) ? g_kh : g_vh;
        __nv_bfloat16* dl = (z == 0) ? g_ql : (z == 1) ? g_kl : g_vl;
        const float sc = (z == 0) ? SCALE_F : 1.0f;
#pragma unroll
        for (int mi = 0; mi < 2; mi++) {
            const int row = m0 + wm * 32 + mi * 16 + gr;
#pragma unroll
            for (int ni = 0; ni < 8; ni++) {
                const int col = n0 + wn * 64 + ni * 8 + tq;
                float b0 = 0.f, b1 = 0.f;
                if (z == 2) { b0 = bias_v[col]; b1 = bias_v[col + 1]; }
                uint32_t h0, l0, h1, l1;
                split2((c[mi][ni][0] + b0) * sc, (c[mi][ni][1] + b1) * sc, h0, l0);
                split2((c[mi][ni][2] + b0) * sc, (c[mi][ni][3] + b1) * sc, h1, l1);
                *(uint32_t*)(dh + (size_t)row * HID + col)       = h0;
                *(uint32_t*)(dl + (size_t)row * HID + col)       = l0;
                *(uint32_t*)(dh + (size_t)(row + 8) * HID + col) = h1;
                *(uint32_t*)(dl + (size_t)(row + 8) * HID + col) = l1;
            }
        }
    } else {
#pragma unroll
        for (int mi = 0; mi < 2; mi++) {
            const int row = m0 + wm * 32 + mi * 16 + gr;
#pragma unroll
            for (int ni = 0; ni < 8; ni++) {
                const int col = n0 + wn * 64 + ni * 8 + tq;
                float b0 = bias_o[col], b1 = bias_o[col + 1];
                *(float2*)(outp + (size_t)row * HID + col) =
                    make_float2(c[mi][ni][0] + b0, c[mi][ni][1] + b1);
                *(float2*)(outp + (size_t)(row + 8) * HID + col) =
                    make_float2(c[mi][ni][2] + b0, c[mi][ni][3] + b1);
            }
        }
    }
}

// ---------------------------------------------------------------------------
// exp2 on the FMA pipe (softmax args are <= 0; clamp at -80)
// ---------------------------------------------------------------------------
__device__ __forceinline__ float fast_exp2(float x)
{
    x = fmaxf(x, -80.0f);
    float n = rintf(x);
    float f = x - n;
    float p = 1.5403530e-4f;
    p = fmaf(p, f, 1.3333558e-3f);
    p = fmaf(p, f, 9.6181291e-3f);
    p = fmaf(p, f, 5.5504109e-2f);
    p = fmaf(p, f, 2.4022651e-1f);
    p = fmaf(p, f, 6.9314718e-1f);
    p = fmaf(p, f, 1.0f);
    return p * __int_as_float(((int)n + 127) << 23);
}

// ---------------------------------------------------------------------------
// Tensor-core flash attention. CTA = 128 q-rows of one (b,h); 8 warps x m16.
// Keys streamed in 64-chunks. 3-term bf16 splits on QK^T and PV.
// smem: Qh/Ql 128x72 + Kh/Kl 64x72 + Vh/Vl 64x72 (bf16) = 73728 B.
// ---------------------------------------------------------------------------
#define ATS 72
#define AQPL (128 * ATS * 2)    // 18432
#define AKPL (64 * ATS * 2)     // 9216
#define OFF_QH 0
#define OFF_QL (AQPL)
#define OFF_KH (2 * AQPL)
#define OFF_KL (2 * AQPL + AKPL)
#define OFF_VH (2 * AQPL + 2 * AKPL)
#define OFF_VL (2 * AQPL + 3 * AKPL)
#define ATTN_SMEM (2 * AQPL + 4 * AKPL)   // 73728

__global__ __launch_bounds__(256, 2)
void attn_mma_kernel(const float* __restrict__ ebias)
{
    extern __shared__ char smem[];
    const uint32_t sbase = smem_u32(smem);
    const int tid = threadIdx.x, wid = tid >> 5, lid = tid & 31;
    const int qt = blockIdx.x, h = blockIdx.y, b = blockIdx.z;
    const int q0 = qt * 128;

    // ---- load Q tile (hi/lo) ----
    {
        const __nv_bfloat16* qh = g_qh + (size_t)(b * NSEQ + q0) * HID + h * DHEAD;
        const __nv_bfloat16* ql = g_ql + (size_t)(b * NSEQ + q0) * HID + h * DHEAD;
#pragma unroll
        for (int l = 0; l < 4; l++) {
            int idx = tid + l * 256;
            int row = idx >> 3, c8 = (idx & 7) * 8;
            uint32_t so = (row * ATS + c8) * 2;
            *(uint4*)(smem + OFF_QH + so) = *(const uint4*)(qh + (size_t)row * HID + c8);
            *(uint4*)(smem + OFF_QL + so) = *(const uint4*)(ql + (size_t)row * HID + c8);
        }
    }

    const int gr = lid >> 2, tq = (lid & 3) * 2;
    const int rA = (lid & 7) + ((lid >> 3) & 1) * 8;
    const int kA = (lid >> 4) * 8;
    const int rB = (lid & 7) + (lid >> 4) * 8;
    const int kB = ((lid >> 3) & 1) * 8;
    const uint32_t aQh = sbase + OFF_QH + ((wid * 16 + rA) * ATS + kA) * 2;
    const uint32_t aQl = sbase + OFF_QL + ((wid * 16 + rA) * ATS + kA) * 2;
    const uint32_t aK  = sbase + OFF_KH + (rB * ATS + kB) * 2;
    const uint32_t aV  = sbase + OFF_VH + ((lid & 15) * ATS + (lid >> 4) * 8) * 2;

    float acc[8][4];
#pragma unroll
    for (int j = 0; j < 8; j++)
#pragma unroll
        for (int r = 0; r < 4; r++) acc[j][r] = 0.f;
    float mr0 = -1e30f, mr1 = -1e30f, rs0 = 0.f, rs1 = 0.f;
    int nz0 = 0, nz1 = 0;

    const float* bp0 = ebias + ((size_t)b * NSEQ + q0 + wid * 16 + gr) * NSEQ + tq;
    const float* bp1 = bp0 + 8 * NSEQ;

#pragma unroll 1
    for (int kc = 0; kc < 8; kc++) {
        __syncthreads();   // K/V buffers free
        {
            const size_t rb = (size_t)(b * NSEQ + kc * 64) * HID + h * DHEAD;
            const __nv_bfloat16* src[4] = {g_kh + rb, g_kl + rb, g_vh + rb, g_vl + rb};
#pragma unroll
            for (int pl = 0; pl < 4; pl++)
#pragma unroll
                for (int sub = 0; sub < 2; sub++) {
                    int idx = tid + sub * 256;
                    int row = idx >> 3, c8 = (idx & 7) * 8;
                    *(uint4*)(smem + OFF_KH + pl * AKPL + (row * ATS + c8) * 2) =
                        *(const uint4*)(src[pl] + (size_t)row * HID + c8);
                }
        }
        __syncthreads();

        // ---- S = Q K^T (3-term) ----
        float c[8][4];
#pragma unroll
        for (int j = 0; j < 8; j++)
#pragma unroll
            for (int r = 0; r < 4; r++) c[j][r] = 0.f;

#pragma unroll
        for (int ks = 0; ks < 4; ks++) {
            uint32_t Qh[4], Ql[4];
            ldm4(Qh, aQh + ks * 32);
            ldm4(Ql, aQl + ks * 32);
#pragma unroll
            for (int np = 0; np < 4; np++) {
                uint32_t Kh[4], Kl[4];
                ldm4(Kh, aK + ks * 32 + np * 16 * ATS * 2);
                ldm4(Kl, aK + AKPL + ks * 32 + np * 16 * ATS * 2);
                mma16816(c[np * 2],     Qh, Kh[0], Kh[1]);
                mma16816(c[np * 2 + 1], Qh, Kh[2], Kh[3]);
                mma16816(c[np * 2],     Ql, Kh[0], Kh[1]);
                mma16816(c[np * 2 + 1], Ql, Kh[2], Kh[3]);
                mma16816(c[np * 2],     Qh, Kl[0], Kl[1]);
                mma16816(c[np * 2 + 1], Qh, Kl[2], Kl[3]);
            }
        }

        // ---- add bias, online softmax ----
        float mc0 = -1e30f, mc1 = -1e30f;
        int n0 = 0, n1 = 0;
#pragma unroll
        for (int j = 0; j < 8; j++) {
            float2 b0 = *(const float2*)(bp0 + kc * 64 + j * 8);
            float2 b1 = *(const float2*)(bp1 + kc * 64 + j * 8);
            c[j][0] += b0.x; c[j][1] += b0.y;
            c[j][2] += b1.x; c[j][3] += b1.y;
            mc0 = fmaxf(mc0, fmaxf(c[j][0], c[j][1]));
            mc1 = fmaxf(mc1, fmaxf(c[j][2], c[j][3]));
            n0 |= (c[j][0] != 0.f) | (c[j][1] != 0.f);
            n1 |= (c[j][2] != 0.f) | (c[j][3] != 0.f);
        }
#pragma unroll
        for (int o = 1; o < 4; o <<= 1) {
            mc0 = fmaxf(mc0, __shfl_xor_sync(0xffffffffu, mc0, o));
            mc1 = fmaxf(mc1, __shfl_xor_sync(0xffffffffu, mc1, o));
            n0 |= __shfl_xor_sync(0xffffffffu, n0, o);
            n1 |= __shfl_xor_sync(0xffffffffu, n1, o);
        }
        nz0 |= n0; nz1 |= n1;
        float mn0 = fmaxf(mr0, mc0), mn1 = fmaxf(mr1, mc1);
        float cr0 = fast_exp2((mr0 - mn0) * LOG2E_F);
        float cr1 = fast_exp2((mr1 - mn1) * LOG2E_F);
        mr0 = mn0; mr1 = mn1;

        float s0 = 0.f, s1 = 0.f;
#pragma unroll
        for (int j = 0; j < 8; j++) {
            c[j][0] = fast_exp2((c[j][0] - mn0) * LOG2E_F);
            c[j][1] = fast_exp2((c[j][1] - mn0) * LOG2E_F);
            c[j][2] = fast_exp2((c[j][2] - mn1) * LOG2E_F);
            c[j][3] = fast_exp2((c[j][3] - mn1) * LOG2E_F);
            s0 += c[j][0] + c[j][1];
            s1 += c[j][2] + c[j][3];
        }
#pragma unroll
        for (int o = 1; o < 4; o <<= 1) {
            s0 += __shfl_xor_sync(0xffffffffu, s0, o);
            s1 += __shfl_xor_sync(0xffffffffu, s1, o);
        }
        rs0 = rs0 * cr0 + s0;
        rs1 = rs1 * cr1 + s1;
#pragma unroll
        for (int j = 0; j < 8; j++) {
            acc[j][0] *= cr0; acc[j][1] *= cr0;
            acc[j][2] *= cr1; acc[j][3] *= cr1;
        }

        // ---- acc += P V (3-term); P fragments from score regs ----
#pragma unroll
        for (int ks = 0; ks < 4; ks++) {
            uint32_t Ph[4], Pl[4];
            split2(c[2 * ks][0],     c[2 * ks][1],     Ph[0], Pl[0]);
            split2(c[2 * ks][2],     c[2 * ks][3],     Ph[1], Pl[1]);
            split2(c[2 * ks + 1][0], c[2 * ks + 1][1], Ph[2], Pl[2]);
            split2(c[2 * ks + 1][2], c[2 * ks + 1][3], Ph[3], Pl[3]);
#pragma unroll
            for (int np = 0; np < 4; np++) {
                uint32_t Vh[4], Vl[4];
                ldm4t(Vh, aV + ks * 16 * ATS * 2 + np * 32);
                ldm4t(Vl, aV + AKPL + ks * 16 * ATS * 2 + np * 32);
                mma16816(acc[np * 2],     Ph, Vh[0], Vh[1]);
                mma16816(acc[np * 2 + 1], Ph, Vh[2], Vh[3]);
                mma16816(acc[np * 2],     Pl, Vh[0], Vh[1]);
                mma16816(acc[np * 2 + 1], Pl, Vh[2], Vh[3]);
                mma16816(acc[np * 2],     Ph, Vl[0], Vl[1]);
                mma16816(acc[np * 2 + 1], Ph, Vl[2], Vl[3]);
            }
        }
    }

    // ---- epilogue: normalize (pad-mask) and store O hi/lo bf16 ----
    const float i0 = nz0 ? (1.f / rs0) : 0.f;
    const float i1 = nz1 ? (1.f / rs1) : 0.f;
    __nv_bfloat16* oh = g_oh + (size_t)(b * NSEQ + q0 + wid * 16) * HID + h * DHEAD;
    __nv_bfloat16* ol = g_ol + (size_t)(b * NSEQ + q0 + wid * 16) * HID + h * DHEAD;
#pragma unroll
    for (int j = 0; j < 8; j++) {
        const int col = j * 8 + tq;
        uint32_t h0, l0, h1, l1;
        split2(acc[j][0] * i0, acc[j][1] * i0, h0, l0);
        split2(acc[j][2] * i1, acc[j][3] * i1, h1, l1);
        *(uint32_t*)(oh + (size_t)gr * HID + col)       = h0;
        *(uint32_t*)(ol + (size_t)gr * HID + col)       = l0;
        *(uint32_t*)(oh + (size_t)(gr + 8) * HID + col) = h1;
        *(uint32_t*)(ol + (size_t)(gr + 8) * HID + col) = l1;
    }
}

// ---------------------------------------------------------------------------
// inputs: x, encoding_bias, Wq, Wk, Wv, bv, Wo, bo
// ---------------------------------------------------------------------------
extern "C" void kernel_launch(void* const* d_in, const int* in_sizes, int n_in,
                              void* d_out, int out_size)
{
    const float* x  = (const float*)d_in[0];
    const float* eb = (const float*)d_in[1];
    const float* Wq = (const float*)d_in[2];
    const float* Wk = (const float*)d_in[3];
    const float* Wv = (const float*)d_in[4];
    const float* bv = (const float*)d_in[5];
    const float* Wo = (const float*)d_in[6];
    const float* bo = (const float*)d_in[7];
    float* out = (float*)d_out;

    cudaFuncSetAttribute(attn_mma_kernel,
                         cudaFuncAttributeMaxDynamicSharedMemorySize, ATTN_SMEM);
    cudaFuncSetAttribute(gemm_mma_kernel,
                         cudaFuncAttributeMaxDynamicSharedMemorySize, GSMEM);

    const int nx4 = MTOT * HID / 4;
    const int nw4 = WSZ / 4;

    conv_split_kernel<<<(nx4 + 255) / 256, 256>>>(x,  0, nx4);
    conv_split_kernel<<<(nw4 + 255) / 256, 256>>>(Wq, 1, nw4);
    conv_split_kernel<<<(nw4 + 255) / 256, 256>>>(Wk, 2, nw4);
    conv_split_kernel<<<(nw4 + 255) / 256, 256>>>(Wv, 3, nw4);
    conv_split_kernel<<<(nw4 + 255) / 256, 256>>>(Wo, 4, nw4);

    gemm_mma_kernel<<<dim3(HID / GBN, MTOT / GBM, 3), 256, GSMEM>>>(
        nullptr, bv, nullptr, 0);                                   // Q,K,V -> bf16 hi/lo

    attn_mma_kernel<<<dim3(4, NHEAD, 16), 256, ATTN_SMEM>>>(eb);    // O -> bf16 hi/lo

    gemm_mma_kernel<<<dim3(HID / GBN, MTOT / GBM, 1), 256, GSMEM>>>(
        out, nullptr, bo, 1);                                       // O proj -> fp32
}

// round 12
// speedup vs baseline: 2.5686x; 1.0953x over previous
#include <cuda_runtime.h>
#include <cuda_bf16.h>
#include <cstdint>

// ---------------------------------------------------------------------------
// GraphormerMultiHeadAttention  (B=16, N=512, HIDDEN=768, 12 heads x 64)
//
//   1) split x, W* into bf16 hi/lo planes
//   2) mma.sync bf16 GEMM (3-term split) with cp.async pipeline: QKV fused
//      -> bf16 hi/lo outputs (scale folded into Q)
//   3) mma.sync bf16 flash attention, cp.async double-buffered K/V
//   4) mma.sync GEMM O projection -> fp32 out
// ---------------------------------------------------------------------------

#define HID    768
#define MTOT   8192
#define NSEQ   512
#define NHEAD  12
#define DHEAD  64
#define SCALE_F 0.03608439182435161f   // 768^-0.5
#define LOG2E_F 1.4426950408889634f
#define WSZ (HID * HID)

// ---------------- scratch (device globals; allocation-free) ----------------
__device__ __align__(16) __nv_bfloat16 g_ah[MTOT * HID];
__device__ __align__(16) __nv_bfloat16 g_al[MTOT * HID];
__device__ __align__(16) __nv_bfloat16 g_qh[MTOT * HID];
__device__ __align__(16) __nv_bfloat16 g_ql[MTOT * HID];
__device__ __align__(16) __nv_bfloat16 g_kh[MTOT * HID];
__device__ __align__(16) __nv_bfloat16 g_kl[MTOT * HID];
__device__ __align__(16) __nv_bfloat16 g_vh[MTOT * HID];
__device__ __align__(16) __nv_bfloat16 g_vl[MTOT * HID];
__device__ __align__(16) __nv_bfloat16 g_oh[MTOT * HID];
__device__ __align__(16) __nv_bfloat16 g_ol[MTOT * HID];
__device__ __align__(16) __nv_bfloat16 g_wh[4 * WSZ];
__device__ __align__(16) __nv_bfloat16 g_wl[4 * WSZ];

// ---------------------------------------------------------------------------
// fp32 -> (hi, lo) bf16 splits
// ---------------------------------------------------------------------------
__device__ __forceinline__ void split_store(const float4 v,
                                            __nv_bfloat162* ph, __nv_bfloat162* pl)
{
    __nv_bfloat16 h0 = __float2bfloat16_rn(v.x);
    __nv_bfloat16 h1 = __float2bfloat16_rn(v.y);
    __nv_bfloat16 h2 = __float2bfloat16_rn(v.z);
    __nv_bfloat16 h3 = __float2bfloat16_rn(v.w);
    __nv_bfloat162 H0, H1, L0, L1;
    H0.x = h0; H0.y = h1; H1.x = h2; H1.y = h3;
    L0.x = __float2bfloat16_rn(v.x - __bfloat162float(h0));
    L0.y = __float2bfloat16_rn(v.y - __bfloat162float(h1));
    L1.x = __float2bfloat16_rn(v.z - __bfloat162float(h2));
    L1.y = __float2bfloat16_rn(v.w - __bfloat162float(h3));
    ph[0] = H0; ph[1] = H1; pl[0] = L0; pl[1] = L1;
}

__global__ void conv_split_x(const float* __restrict__ src, int n4)
{
    int i = blockIdx.x * blockDim.x + threadIdx.x;
    if (i >= n4) return;
    split_store(((const float4*)src)[i],
                (__nv_bfloat162*)g_ah + 2 * i, (__nv_bfloat162*)g_al + 2 * i);
}

__global__ void conv_split_w4(const float* __restrict__ w0,
                              const float* __restrict__ w1,
                              const float* __restrict__ w2,
                              const float* __restrict__ w3, int n4)
{
    int i = blockIdx.x * blockDim.x + threadIdx.x;
    if (i >= n4) return;
    const int z = blockIdx.y;
    const float* src = (z == 0) ? w0 : (z == 1) ? w1 : (z == 2) ? w2 : w3;
    size_t base = (size_t)z * (WSZ / 2);   // in bf16x2 units
    split_store(((const float4*)src)[i],
                (__nv_bfloat162*)g_wh + base + 2 * i,
                (__nv_bfloat162*)g_wl + base + 2 * i);
}

// ---------------------------------------------------------------------------
// warp-mma / async-copy helpers
// ---------------------------------------------------------------------------
__device__ __forceinline__ uint32_t smem_u32(const void* p)
{
    uint32_t a;
    asm("{ .reg .u64 t; cvta.to.shared.u64 t, %1; cvt.u32.u64 %0, t; }"
        : "=r"(a) : "l"(p));
    return a;
}
__device__ __forceinline__ void cp16(uint32_t dst, const void* src)
{
    size_t gsrc = __cvta_generic_to_global(src);
    asm volatile("cp.async.cg.shared.global [%0], [%1], 16;"
                 :: "r"(dst), "l"(gsrc) : "memory");
}
__device__ __forceinline__ void cp_commit()
{
    asm volatile("cp.async.commit_group;" ::: "memory");
}
template <int N>
__device__ __forceinline__ void cp_wait()
{
    asm volatile("cp.async.wait_group %0;" :: "n"(N) : "memory");
}
__device__ __forceinline__ void ldm4(uint32_t* r, uint32_t addr)
{
    asm volatile("ldmatrix.sync.aligned.m8n8.x4.shared.b16 {%0,%1,%2,%3}, [%4];"
                 : "=r"(r[0]), "=r"(r[1]), "=r"(r[2]), "=r"(r[3]) : "r"(addr));
}
__device__ __forceinline__ void ldm4t(uint32_t* r, uint32_t addr)
{
    asm volatile("ldmatrix.sync.aligned.m8n8.x4.trans.shared.b16 {%0,%1,%2,%3}, [%4];"
                 : "=r"(r[0]), "=r"(r[1]), "=r"(r[2]), "=r"(r[3]) : "r"(addr));
}
__device__ __forceinline__ void mma16816(float* c, const uint32_t* a,
                                         uint32_t b0, uint32_t b1)
{
    asm volatile(
        "mma.sync.aligned.m16n8k16.row.col.f32.bf16.bf16.f32 "
        "{%0,%1,%2,%3}, {%4,%5,%6,%7}, {%8,%9}, {%0,%1,%2,%3};"
        : "+f"(c[0]), "+f"(c[1]), "+f"(c[2]), "+f"(c[3])
        : "r"(a[0]), "r"(a[1]), "r"(a[2]), "r"(a[3]), "r"(b0), "r"(b1));
}
__device__ __forceinline__ void split2(float x, float y, uint32_t& h, uint32_t& l)
{
    __nv_bfloat162 H, L;
    H.x = __float2bfloat16_rn(x); H.y = __float2bfloat16_rn(y);
    L.x = __float2bfloat16_rn(x - __bfloat162float(H.x));
    L.y = __float2bfloat16_rn(y - __bfloat162float(H.y));
    h = *(uint32_t*)&H; l = *(uint32_t*)&L;
}

// ---------------------------------------------------------------------------
// GEMM-NT: C[m][n] = sum_k A[m][k] * W[n][k] (+ bias[n]) via mma.sync bf16,
// 3-term split, cp.async double-buffered. CTA 128x128x(k32), 8 warps.
// z=0,1,2 -> bf16 hi/lo outputs (q scaled); z=3 -> fp32 out (+bo).
// ---------------------------------------------------------------------------
#define GBM 128
#define GBN 128
#define GBK 32
#define BKP 40
#define PLANE (128 * BKP * 2)
#define BUFB  (4 * PLANE)
#define GSMEM (2 * BUFB)
#define NKC (HID / GBK)

__global__ __launch_bounds__(256, 2)
void gemm_mma_kernel(float* __restrict__ outp,
                     const float* __restrict__ bias_v,
                     const float* __restrict__ bias_o,
                     int which)
{
    extern __shared__ char smem[];
    const uint32_t sbase = smem_u32(smem);
    const int tid = threadIdx.x, wid = tid >> 5, lid = tid & 31;

    const int z  = which ? 3 : blockIdx.z;
    const int n0 = blockIdx.x * GBN;
    const int m0 = blockIdx.y * GBM;

    const __nv_bfloat16* gAh = ((z == 3) ? g_oh : g_ah) + (size_t)m0 * HID;
    const __nv_bfloat16* gAl = ((z == 3) ? g_ol : g_al) + (size_t)m0 * HID;
    const __nv_bfloat16* gBh = g_wh + (size_t)z * WSZ + (size_t)n0 * HID;
    const __nv_bfloat16* gBl = g_wl + (size_t)z * WSZ + (size_t)n0 * HID;

    const int lr = tid >> 2;
    const int ls = (tid & 3) * 8;
    const size_t gofs0 = (size_t)lr * HID + ls;
    const size_t gofs1 = (size_t)(lr + 64) * HID + ls;
    const uint32_t eofs0 = (lr * BKP + ls) * 2;
    const uint32_t eofs1 = ((lr + 64) * BKP + ls) * 2;

    const int wm = wid & 3, wn = wid >> 2;
    const int gr = lid >> 2, tq = (lid & 3) * 2;
    const int rA = (lid & 7) + ((lid >> 3) & 1) * 8;
    const int kA = (lid >> 4) * 8;
    const int rB = (lid & 7) + (lid >> 4) * 8;
    const int kB = ((lid >> 3) & 1) * 8;
    const uint32_t aoff = sbase + ((wm * 32 + rA) * BKP + kA) * 2;
    const uint32_t boff = sbase + 2 * PLANE + ((wn * 64 + rB) * BKP + kB) * 2;

    auto load_chunk = [&](int t, int buf) {
        const int ko = t * GBK;
        const uint32_t sb = sbase + buf * BUFB;
        cp16(sb + 0 * PLANE + eofs0, gAh + gofs0 + ko);
        cp16(sb + 0 * PLANE + eofs1, gAh + gofs1 + ko);
        cp16(sb + 1 * PLANE + eofs0, gAl + gofs0 + ko);
        cp16(sb + 1 * PLANE + eofs1, gAl + gofs1 + ko);
        cp16(sb + 2 * PLANE + eofs0, gBh + gofs0 + ko);
        cp16(sb + 2 * PLANE + eofs1, gBh + gofs1 + ko);
        cp16(sb + 3 * PLANE + eofs0, gBl + gofs0 + ko);
        cp16(sb + 3 * PLANE + eofs1, gBl + gofs1 + ko);
        cp_commit();
    };

    float c[2][8][4];
#pragma unroll
    for (int mi = 0; mi < 2; mi++)
#pragma unroll
        for (int ni = 0; ni < 8; ni++)
#pragma unroll
            for (int r = 0; r < 4; r++) c[mi][ni][r] = 0.f;

    load_chunk(0, 0);

#pragma unroll 1
    for (int t = 0; t < NKC; t++) {
        if (t + 1 < NKC) { load_chunk(t + 1, (t + 1) & 1); cp_wait<1>(); }
        else             { cp_wait<0>(); }
        __syncthreads();

        const uint32_t bb = (t & 1) * BUFB;
#pragma unroll
        for (int ks = 0; ks < 2; ks++) {
            uint32_t Ah[2][4], Al[2][4];
            ldm4(Ah[0], aoff + bb + ks * 32);
            ldm4(Ah[1], aoff + bb + ks * 32 + 16 * BKP * 2);
            ldm4(Al[0], aoff + bb + PLANE + ks * 32);
            ldm4(Al[1], aoff + bb + PLANE + ks * 32 + 16 * BKP * 2);
#pragma unroll
            for (int np = 0; np < 4; np++) {
                uint32_t Bh[4], Bl[4];
                ldm4(Bh, boff + bb + ks * 32 + np * 16 * BKP * 2);
                ldm4(Bl, boff + bb + PLANE + ks * 32 + np * 16 * BKP * 2);
#pragma unroll
                for (int mi = 0; mi < 2; mi++) {
                    mma16816(c[mi][np * 2],     Ah[mi], Bh[0], Bh[1]);
                    mma16816(c[mi][np * 2 + 1], Ah[mi], Bh[2], Bh[3]);
                    mma16816(c[mi][np * 2],     Al[mi], Bh[0], Bh[1]);
                    mma16816(c[mi][np * 2 + 1], Al[mi], Bh[2], Bh[3]);
                    mma16816(c[mi][np * 2],     Ah[mi], Bl[0], Bl[1]);
                    mma16816(c[mi][np * 2 + 1], Ah[mi], Bl[2], Bl[3]);
                }
            }
        }
        __syncthreads();   // all reads of buffer (t&1) done before chunk t+2 lands
    }

    // ---- epilogue ----
    if (z < 3) {
        __nv_bfloat16* dh = (z == 0) ? g_qh : (z == 1) ? g_kh : g_vh;
        __nv_bfloat16* dl = (z == 0) ? g_ql : (z == 1) ? g_kl : g_vl;
        const float sc = (z == 0) ? SCALE_F : 1.0f;
#pragma unroll
        for (int mi = 0; mi < 2; mi++) {
            const int row = m0 + wm * 32 + mi * 16 + gr;
#pragma unroll
            for (int ni = 0; ni < 8; ni++) {
                const int col = n0 + wn * 64 + ni * 8 + tq;
                float b0 = 0.f, b1 = 0.f;
                if (z == 2) { b0 = bias_v[col]; b1 = bias_v[col + 1]; }
                uint32_t h0, l0, h1, l1;
                split2((c[mi][ni][0] + b0) * sc, (c[mi][ni][1] + b1) * sc, h0, l0);
                split2((c[mi][ni][2] + b0) * sc, (c[mi][ni][3] + b1) * sc, h1, l1);
                *(uint32_t*)(dh + (size_t)row * HID + col)       = h0;
                *(uint32_t*)(dl + (size_t)row * HID + col)       = l0;
                *(uint32_t*)(dh + (size_t)(row + 8) * HID + col) = h1;
                *(uint32_t*)(dl + (size_t)(row + 8) * HID + col) = l1;
            }
        }
    } else {
#pragma unroll
        for (int mi = 0; mi < 2; mi++) {
            const int row = m0 + wm * 32 + mi * 16 + gr;
#pragma unroll
            for (int ni = 0; ni < 8; ni++) {
                const int col = n0 + wn * 64 + ni * 8 + tq;
                float b0 = bias_o[col], b1 = bias_o[col + 1];
                *(float2*)(outp + (size_t)row * HID + col) =
                    make_float2(c[mi][ni][0] + b0, c[mi][ni][1] + b1);
                *(float2*)(outp + (size_t)(row + 8) * HID + col) =
                    make_float2(c[mi][ni][2] + b0, c[mi][ni][3] + b1);
            }
        }
    }
}

// ---------------------------------------------------------------------------
// exp2 on the FMA pipe (softmax args are <= 0; clamp at -80)
// ---------------------------------------------------------------------------
__device__ __forceinline__ float fast_exp2(float x)
{
    x = fmaxf(x, -80.0f);
    float n = rintf(x);
    float f = x - n;
    float p = 1.5403530e-4f;
    p = fmaf(p, f, 1.3333558e-3f);
    p = fmaf(p, f, 9.6181291e-3f);
    p = fmaf(p, f, 5.5504109e-2f);
    p = fmaf(p, f, 2.4022651e-1f);
    p = fmaf(p, f, 6.9314718e-1f);
    p = fmaf(p, f, 1.0f);
    return p * __int_as_float(((int)n + 127) << 23);
}

// ---------------------------------------------------------------------------
// Tensor-core flash attention, cp.async double-buffered K/V.
// CTA = 128 q-rows of one (b,h); 8 warps x m16. 3-term QK^T and PV.
// smem: Qh/Ql 128x72 + 2 x [Kh,Kl,Vh,Vl] 64x72 = 110592 B.
// ---------------------------------------------------------------------------
#define ATS 72
#define AQPL (128 * ATS * 2)    // 18432
#define AKPL (64 * ATS * 2)     // 9216
#define OFF_KV (2 * AQPL)
#define KVBUF (4 * AKPL)
#define ATTN_SMEM (2 * AQPL + 2 * KVBUF)   // 110592

__global__ __launch_bounds__(256, 2)
void attn_mma_kernel(const float* __restrict__ ebias)
{
    extern __shared__ char smem[];
    const uint32_t sbase = smem_u32(smem);
    const int tid = threadIdx.x, wid = tid >> 5, lid = tid & 31;
    const int qt = blockIdx.x, h = blockIdx.y, b = blockIdx.z;
    const int q0 = qt * 128;

    // loader coords (shared by Q and K/V loads)
    const int lrow = tid >> 3, lc8 = (tid & 7) * 8;

    auto load_kv = [&](int kc, int buf) {
        const size_t rb = (size_t)(b * NSEQ + kc * 64) * HID + h * DHEAD;
        const __nv_bfloat16* src[4] = {g_kh + rb, g_kl + rb, g_vh + rb, g_vl + rb};
        const uint32_t sb = sbase + OFF_KV + buf * KVBUF;
#pragma unroll
        for (int pl = 0; pl < 4; pl++)
#pragma unroll
            for (int sub = 0; sub < 2; sub++) {
                int row = lrow + sub * 32;
                cp16(sb + pl * AKPL + (row * ATS + lc8) * 2,
                     src[pl] + (size_t)row * HID + lc8);
            }
        cp_commit();
    };

    // ---- load Q tile (hi/lo) ----
    {
        const __nv_bfloat16* qh = g_qh + (size_t)(b * NSEQ + q0) * HID + h * DHEAD;
        const __nv_bfloat16* ql = g_ql + (size_t)(b * NSEQ + q0) * HID + h * DHEAD;
#pragma unroll
        for (int l = 0; l < 4; l++) {
            int row = lrow + l * 32;
            uint32_t so = (row * ATS + lc8) * 2;
            cp16(sbase + so,        qh + (size_t)row * HID + lc8);
            cp16(sbase + AQPL + so, ql + (size_t)row * HID + lc8);
        }
        cp_commit();
    }
    load_kv(0, 0);

    const int gr = lid >> 2, tq = (lid & 3) * 2;
    const int rA = (lid & 7) + ((lid >> 3) & 1) * 8;
    const int kA = (lid >> 4) * 8;
    const int rB = (lid & 7) + (lid >> 4) * 8;
    const int kB = ((lid >> 3) & 1) * 8;
    const uint32_t aQh = sbase + ((wid * 16 + rA) * ATS + kA) * 2;
    const uint32_t aQl = aQh + AQPL;
    const uint32_t oK  = (rB * ATS + kB) * 2;
    const uint32_t oV  = ((lid & 15) * ATS + (lid >> 4) * 8) * 2;

    float acc[8][4];
#pragma unroll
    for (int j = 0; j < 8; j++)
#pragma unroll
        for (int r = 0; r < 4; r++) acc[j][r] = 0.f;
    float mr0 = -1e30f, mr1 = -1e30f, rs0 = 0.f, rs1 = 0.f;
    int nz0 = 0, nz1 = 0;

    const float* bp0 = ebias + ((size_t)b * NSEQ + q0 + wid * 16 + gr) * NSEQ + tq;
    const float* bp1 = bp0 + 8 * NSEQ;

#pragma unroll 1
    for (int kc = 0; kc < 8; kc++) {
        if (kc + 1 < 8) { load_kv(kc + 1, (kc + 1) & 1); cp_wait<1>(); }
        else            { cp_wait<0>(); }
        __syncthreads();

        const uint32_t aK = sbase + OFF_KV + (kc & 1) * KVBUF + oK;
        const uint32_t aV = sbase + OFF_KV + (kc & 1) * KVBUF + 2 * AKPL + oV;

        // ---- S = Q K^T (3-term) ----
        float c[8][4];
#pragma unroll
        for (int j = 0; j < 8; j++)
#pragma unroll
            for (int r = 0; r < 4; r++) c[j][r] = 0.f;

#pragma unroll
        for (int ks = 0; ks < 4; ks++) {
            uint32_t Qh[4], Ql[4];
            ldm4(Qh, aQh + ks * 32);
            ldm4(Ql, aQl + ks * 32);
#pragma unroll
            for (int np = 0; np < 4; np++) {
                uint32_t Kh[4], Kl[4];
                ldm4(Kh, aK + ks * 32 + np * 16 * ATS * 2);
                ldm4(Kl, aK + AKPL + ks * 32 + np * 16 * ATS * 2);
                mma16816(c[np * 2],     Qh, Kh[0], Kh[1]);
                mma16816(c[np * 2 + 1], Qh, Kh[2], Kh[3]);
                mma16816(c[np * 2],     Ql, Kh[0], Kh[1]);
                mma16816(c[np * 2 + 1], Ql, Kh[2], Kh[3]);
                mma16816(c[np * 2],     Qh, Kl[0], Kl[1]);
                mma16816(c[np * 2 + 1], Qh, Kl[2], Kl[3]);
            }
        }

        // ---- add bias, online softmax ----
        float mc0 = -1e30f, mc1 = -1e30f;
        int n0 = 0, n1 = 0;
#pragma unroll
        for (int j = 0; j < 8; j++) {
            float2 b0 = *(const float2*)(bp0 + kc * 64 + j * 8);
            float2 b1 = *(const float2*)(bp1 + kc * 64 + j * 8);
            c[j][0] += b0.x; c[j][1] += b0.y;
            c[j][2] += b1.x; c[j][3] += b1.y;
            mc0 = fmaxf(mc0, fmaxf(c[j][0], c[j][1]));
            mc1 = fmaxf(mc1, fmaxf(c[j][2], c[j][3]));
            n0 |= (c[j][0] != 0.f) | (c[j][1] != 0.f);
            n1 |= (c[j][2] != 0.f) | (c[j][3] != 0.f);
        }
#pragma unroll
        for (int o = 1; o < 4; o <<= 1) {
            mc0 = fmaxf(mc0, __shfl_xor_sync(0xffffffffu, mc0, o));
            mc1 = fmaxf(mc1, __shfl_xor_sync(0xffffffffu, mc1, o));
            n0 |= __shfl_xor_sync(0xffffffffu, n0, o);
            n1 |= __shfl_xor_sync(0xffffffffu, n1, o);
        }
        nz0 |= n0; nz1 |= n1;
        float mn0 = fmaxf(mr0, mc0), mn1 = fmaxf(mr1, mc1);
        float cr0 = fast_exp2((mr0 - mn0) * LOG2E_F);
        float cr1 = fast_exp2((mr1 - mn1) * LOG2E_F);
        mr0 = mn0; mr1 = mn1;

        float s0 = 0.f, s1 = 0.f;
#pragma unroll
        for (int j = 0; j < 8; j++) {
            c[j][0] = fast_exp2((c[j][0] - mn0) * LOG2E_F);
            c[j][1] = fast_exp2((c[j][1] - mn0) * LOG2E_F);
            c[j][2] = fast_exp2((c[j][2] - mn1) * LOG2E_F);
            c[j][3] = fast_exp2((c[j][3] - mn1) * LOG2E_F);
            s0 += c[j][0] + c[j][1];
            s1 += c[j][2] + c[j][3];
        }
#pragma unroll
        for (int o = 1; o < 4; o <<= 1) {
            s0 += __shfl_xor_sync(0xffffffffu, s0, o);
            s1 += __shfl_xor_sync(0xffffffffu, s1, o);
        }
        rs0 = rs0 * cr0 + s0;
        rs1 = rs1 * cr1 + s1;
#pragma unroll
        for (int j = 0; j < 8; j++) {
            acc[j][0] *= cr0; acc[j][1] *= cr0;
            acc[j][2] *= cr1; acc[j][3] *= cr1;
        }

        // ---- acc += P V (3-term); P fragments from score regs ----
#pragma unroll
        for (int ks = 0; ks < 4; ks++) {
            uint32_t Ph[4], Pl[4];
            split2(c[2 * ks][0],     c[2 * ks][1],     Ph[0], Pl[0]);
            split2(c[2 * ks][2],     c[2 * ks][3],     Ph[1], Pl[1]);
            split2(c[2 * ks + 1][0], c[2 * ks + 1][1], Ph[2], Pl[2]);
            split2(c[2 * ks + 1][2], c[2 * ks + 1][3], Ph[3], Pl[3]);
#pragma unroll
            for (int np = 0; np < 4; np++) {
                uint32_t Vh[4], Vl[4];
                ldm4t(Vh, aV + ks * 16 * ATS * 2 + np * 32);
                ldm4t(Vl, aV + AKPL + ks * 16 * ATS * 2 + np * 32);
                mma16816(acc[np * 2],     Ph, Vh[0], Vh[1]);
                mma16816(acc[np * 2 + 1], Ph, Vh[2], Vh[3]);
                mma16816(acc[np * 2],     Pl, Vh[0], Vh[1]);
                mma16816(acc[np * 2 + 1], Pl, Vh[2], Vh[3]);
                mma16816(acc[np * 2],     Ph, Vl[0], Vl[1]);
                mma16816(acc[np * 2 + 1], Ph, Vl[2], Vl[3]);
            }
        }
        __syncthreads();   // reads of buffer (kc&1) done before chunk kc+2 lands
    }

    // ---- epilogue: normalize (pad-mask) and store O hi/lo bf16 ----
    const float i0 = nz0 ? (1.f / rs0) : 0.f;
    const float i1 = nz1 ? (1.f / rs1) : 0.f;
    __nv_bfloat16* oh = g_oh + (size_t)(b * NSEQ + q0 + wid * 16) * HID + h * DHEAD;
    __nv_bfloat16* ol = g_ol + (size_t)(b * NSEQ + q0 + wid * 16) * HID + h * DHEAD;
#pragma unroll
    for (int j = 0; j < 8; j++) {
        const int col = j * 8 + tq;
        uint32_t h0, l0, h1, l1;
        split2(acc[j][0] * i0, acc[j][1] * i0, h0, l0);
        split2(acc[j][2] * i1, acc[j][3] * i1, h1, l1);
        *(uint32_t*)(oh + (size_t)gr * HID + col)       = h0;
        *(uint32_t*)(ol + (size_t)gr * HID + col)       = l0;
        *(uint32_t*)(oh + (size_t)(gr + 8) * HID + col) = h1;
        *(uint32_t*)(ol + (size_t)(gr + 8) * HID + col) = l1;
    }
}

// ---------------------------------------------------------------------------
// inputs: x, encoding_bias, Wq, Wk, Wv, bv, Wo, bo
// ---------------------------------------------------------------------------
extern "C" void kernel_launch(void* const* d_in, const int* in_sizes, int n_in,
                              void* d_out, int out_size)
{
    const float* x  = (const float*)d_in[0];
    const float* eb = (const float*)d_in[1];
    const float* Wq = (const float*)d_in[2];
    const float* Wk = (const float*)d_in[3];
    const float* Wv = (const float*)d_in[4];
    const float* bv = (const float*)d_in[5];
    const float* Wo = (const float*)d_in[6];
    const float* bo = (const float*)d_in[7];
    float* out = (float*)d_out;

    cudaFuncSetAttribute(attn_mma_kernel,
                         cudaFuncAttributeMaxDynamicSharedMemorySize, ATTN_SMEM);
    cudaFuncSetAttribute(gemm_mma_kernel,
                         cudaFuncAttributeMaxDynamicSharedMemorySize, GSMEM);

    const int nx4 = MTOT * HID / 4;
    const int nw4 = WSZ / 4;

    conv_split_x<<<(nx4 + 255) / 256, 256>>>(x, nx4);
    conv_split_w4<<<dim3((nw4 + 255) / 256, 4), 256>>>(Wq, Wk, Wv, Wo, nw4);

    gemm_mma_kernel<<<dim3(HID / GBN, MTOT / GBM, 3), 256, GSMEM>>>(
        nullptr, bv, nullptr, 0);                                   // Q,K,V -> bf16 hi/lo

    attn_mma_kernel<<<dim3(4, NHEAD, 16), 256, ATTN_SMEM>>>(eb);    // O -> bf16 hi/lo

    gemm_mma_kernel<<<dim3(HID / GBN, MTOT / GBM, 1), 256, GSMEM>>>(
        out, nullptr, bo, 1);                                       // O proj -> fp32
}

// round 13
// speedup vs baseline: 3.5521x; 1.3829x over previous
#include <cuda_runtime.h>
#include <cuda_fp16.h>
#include <cstdint>

// ---------------------------------------------------------------------------
// GraphormerMultiHeadAttention  (B=16, N=512, HIDDEN=768, 12 heads x 64)
//
// fp16 2-term split everywhere:  C = (Ah + Al) x Bh,  Bh = fp16-rounded B.
// Dropped term ~2^-11 -> final rel_err ~3e-4 (< 1e-3 gate).
//   1) split x -> fp16 hi/lo; round W -> fp16
//   2) mma.sync fp16 GEMM, 3-stage cp.async pipeline: QKV fused
//   3) mma.sync fp16 flash attention, double-buffered K/V
//   4) mma.sync GEMM O projection -> fp32 out
// ---------------------------------------------------------------------------

#define HID    768
#define MTOT   8192
#define NSEQ   512
#define NHEAD  12
#define DHEAD  64
#define SCALE_F 0.03608439182435161f   // 768^-0.5
#define LOG2E_F 1.4426950408889634f
#define WSZ (HID * HID)

// ---------------- scratch (device globals; allocation-free) ----------------
__device__ __align__(16) __half g_ah[MTOT * HID];   // x hi
__device__ __align__(16) __half g_al[MTOT * HID];   // x lo
__device__ __align__(16) __half g_qh[MTOT * HID];   // Q hi (scaled)
__device__ __align__(16) __half g_ql[MTOT * HID];   // Q lo (scaled)
__device__ __align__(16) __half g_kh[MTOT * HID];   // K (single plane)
__device__ __align__(16) __half g_vh[MTOT * HID];   // V (single plane)
__device__ __align__(16) __half g_oh[MTOT * HID];   // attn out hi
__device__ __align__(16) __half g_ol[MTOT * HID];   // attn out lo
__device__ __align__(16) __half g_wh[4 * WSZ];      // Wq,Wk,Wv,Wo (single)

// ---------------------------------------------------------------------------
// conversions
// ---------------------------------------------------------------------------
__global__ void conv_split_x(const float* __restrict__ src, int n4)
{
    int i = blockIdx.x * blockDim.x + threadIdx.x;
    if (i >= n4) return;
    float4 v = ((const float4*)src)[i];
    __half h0 = __float2half_rn(v.x), h1 = __float2half_rn(v.y);
    __half h2 = __float2half_rn(v.z), h3 = __float2half_rn(v.w);
    __half2 H0, H1, L0, L1;
    H0.x = h0; H0.y = h1; H1.x = h2; H1.y = h3;
    L0.x = __float2half_rn(v.x - __half2float(h0));
    L0.y = __float2half_rn(v.y - __half2float(h1));
    L1.x = __float2half_rn(v.z - __half2float(h2));
    L1.y = __float2half_rn(v.w - __half2float(h3));
    ((__half2*)g_ah)[2 * i] = H0; ((__half2*)g_ah)[2 * i + 1] = H1;
    ((__half2*)g_al)[2 * i] = L0; ((__half2*)g_al)[2 * i + 1] = L1;
}

__global__ void conv_w4(const float* __restrict__ w0,
                        const float* __restrict__ w1,
                        const float* __restrict__ w2,
                        const float* __restrict__ w3, int n4)
{
    int i = blockIdx.x * blockDim.x + threadIdx.x;
    if (i >= n4) return;
    const int z = blockIdx.y;
    const float* src = (z == 0) ? w0 : (z == 1) ? w1 : (z == 2) ? w2 : w3;
    float4 v = ((const float4*)src)[i];
    __half2 H0, H1;
    H0.x = __float2half_rn(v.x); H0.y = __float2half_rn(v.y);
    H1.x = __float2half_rn(v.z); H1.y = __float2half_rn(v.w);
    size_t base = (size_t)z * (WSZ / 2);
    ((__half2*)g_wh)[base + 2 * i]     = H0;
    ((__half2*)g_wh)[base + 2 * i + 1] = H1;
}

// ---------------------------------------------------------------------------
// warp-mma / async-copy helpers
// ---------------------------------------------------------------------------
__device__ __forceinline__ uint32_t smem_u32(const void* p)
{
    uint32_t a;
    asm("{ .reg .u64 t; cvta.to.shared.u64 t, %1; cvt.u32.u64 %0, t; }"
        : "=r"(a) : "l"(p));
    return a;
}
__device__ __forceinline__ void cp16(uint32_t dst, const void* src)
{
    size_t gsrc = __cvta_generic_to_global(src);
    asm volatile("cp.async.cg.shared.global [%0], [%1], 16;"
                 :: "r"(dst), "l"(gsrc) : "memory");
}
__device__ __forceinline__ void cp_commit()
{
    asm volatile("cp.async.commit_group;" ::: "memory");
}
template <int N>
__device__ __forceinline__ void cp_wait()
{
    asm volatile("cp.async.wait_group %0;" :: "n"(N) : "memory");
}
__device__ __forceinline__ void ldm4(uint32_t* r, uint32_t addr)
{
    asm volatile("ldmatrix.sync.aligned.m8n8.x4.shared.b16 {%0,%1,%2,%3}, [%4];"
                 : "=r"(r[0]), "=r"(r[1]), "=r"(r[2]), "=r"(r[3]) : "r"(addr));
}
__device__ __forceinline__ void ldm4t(uint32_t* r, uint32_t addr)
{
    asm volatile("ldmatrix.sync.aligned.m8n8.x4.trans.shared.b16 {%0,%1,%2,%3}, [%4];"
                 : "=r"(r[0]), "=r"(r[1]), "=r"(r[2]), "=r"(r[3]) : "r"(addr));
}
__device__ __forceinline__ void mma16816(float* c, const uint32_t* a,
                                         uint32_t b0, uint32_t b1)
{
    asm volatile(
        "mma.sync.aligned.m16n8k16.row.col.f32.f16.f16.f32 "
        "{%0,%1,%2,%3}, {%4,%5,%6,%7}, {%8,%9}, {%0,%1,%2,%3};"
        : "+f"(c[0]), "+f"(c[1]), "+f"(c[2]), "+f"(c[3])
        : "r"(a[0]), "r"(a[1]), "r"(a[2]), "r"(a[3]), "r"(b0), "r"(b1));
}
// pack two fp32 into fp16x2 hi + fp16x2 lo
__device__ __forceinline__ void split2(float x, float y, uint32_t& h, uint32_t& l)
{
    __half2 H, L;
    H.x = __float2half_rn(x); H.y = __float2half_rn(y);
    L.x = __float2half_rn(x - __half2float(H.x));
    L.y = __float2half_rn(y - __half2float(H.y));
    h = *(uint32_t*)&H; l = *(uint32_t*)&L;
}

// ---------------------------------------------------------------------------
// GEMM-NT: C[m][n] = sum_k A[m][k] * W[n][k] (+ bias[n]), fp16 2-term,
// 3-stage cp.async pipeline. CTA 128x128x(k32), 8 warps (4m x 2n).
// z=0 -> Q hi/lo (scaled); z=1 -> K; z=2 -> V(+bv); z=3 -> fp32 out (+bo).
// ---------------------------------------------------------------------------
#define GBM 128
#define GBN 128
#define GBK 32
#define BKP 40
#define PLANE (128 * BKP * 2)     // 10240 B
#define BUFB  (3 * PLANE)         // Ah, Al, Bh = 30720 B per stage
#define NSTG  3
#define GSMEM (NSTG * BUFB)       // 92160 B
#define NKC (HID / GBK)           // 24

__global__ __launch_bounds__(256, 2)
void gemm_mma_kernel(float* __restrict__ outp,
                     const float* __restrict__ bias_v,
                     const float* __restrict__ bias_o,
                     int which)
{
    extern __shared__ char smem[];
    const uint32_t sbase = smem_u32(smem);
    const int tid = threadIdx.x, wid = tid >> 5, lid = tid & 31;

    const int z  = which ? 3 : blockIdx.z;
    const int n0 = blockIdx.x * GBN;
    const int m0 = blockIdx.y * GBM;

    const __half* gAh = ((z == 3) ? g_oh : g_ah) + (size_t)m0 * HID;
    const __half* gAl = ((z == 3) ? g_ol : g_al) + (size_t)m0 * HID;
    const __half* gBh = g_wh + (size_t)z * WSZ + (size_t)n0 * HID;

    const int lr = tid >> 2;
    const int ls = (tid & 3) * 8;
    const size_t gofs0 = (size_t)lr * HID + ls;
    const size_t gofs1 = (size_t)(lr + 64) * HID + ls;
    const uint32_t eofs0 = (lr * BKP + ls) * 2;
    const uint32_t eofs1 = ((lr + 64) * BKP + ls) * 2;

    const int wm = wid & 3, wn = wid >> 2;
    const int gr = lid >> 2, tq = (lid & 3) * 2;
    const int rA = (lid & 7) + ((lid >> 3) & 1) * 8;
    const int kA = (lid >> 4) * 8;
    const int rB = (lid & 7) + (lid >> 4) * 8;
    const int kB = ((lid >> 3) & 1) * 8;
    const uint32_t aoff = sbase + ((wm * 32 + rA) * BKP + kA) * 2;
    const uint32_t boff = sbase + 2 * PLANE + ((wn * 64 + rB) * BKP + kB) * 2;

    auto load_chunk = [&](int t, int stg) {
        const int ko = t * GBK;
        const uint32_t sb = sbase + stg * BUFB;
        cp16(sb + 0 * PLANE + eofs0, gAh + gofs0 + ko);
        cp16(sb + 0 * PLANE + eofs1, gAh + gofs1 + ko);
        cp16(sb + 1 * PLANE + eofs0, gAl + gofs0 + ko);
        cp16(sb + 1 * PLANE + eofs1, gAl + gofs1 + ko);
        cp16(sb + 2 * PLANE + eofs0, gBh + gofs0 + ko);
        cp16(sb + 2 * PLANE + eofs1, gBh + gofs1 + ko);
        cp_commit();
    };

    float c[2][8][4];
#pragma unroll
    for (int mi = 0; mi < 2; mi++)
#pragma unroll
        for (int ni = 0; ni < 8; ni++)
#pragma unroll
            for (int r = 0; r < 4; r++) c[mi][ni][r] = 0.f;

    load_chunk(0, 0);
    load_chunk(1, 1);

    int stg = 0, nstg = 2;
#pragma unroll 1
    for (int t = 0; t < NKC; t++) {
        if (t + 2 < NKC) { load_chunk(t + 2, nstg); }
        else             { cp_commit(); }             // keep group accounting
        cp_wait<2>();
        __syncthreads();

        const uint32_t bb = stg * BUFB;
#pragma unroll
        for (int ks = 0; ks < 2; ks++) {
            uint32_t Ah[2][4], Al[2][4];
            ldm4(Ah[0], aoff + bb + ks * 32);
            ldm4(Ah[1], aoff + bb + ks * 32 + 16 * BKP * 2);
            ldm4(Al[0], aoff + bb + PLANE + ks * 32);
            ldm4(Al[1], aoff + bb + PLANE + ks * 32 + 16 * BKP * 2);
#pragma unroll
            for (int np = 0; np < 4; np++) {
                uint32_t Bh[4];
                ldm4(Bh, boff + bb + ks * 32 + np * 16 * BKP * 2);
#pragma unroll
                for (int mi = 0; mi < 2; mi++) {
                    mma16816(c[mi][np * 2],     Ah[mi], Bh[0], Bh[1]);
                    mma16816(c[mi][np * 2 + 1], Ah[mi], Bh[2], Bh[3]);
                    mma16816(c[mi][np * 2],     Al[mi], Bh[0], Bh[1]);
                    mma16816(c[mi][np * 2 + 1], Al[mi], Bh[2], Bh[3]);
                }
            }
        }
        __syncthreads();   // all reads of this stage done before its reuse
        stg = (stg == 2) ? 0 : stg + 1;
        nstg = (nstg == 2) ? 0 : nstg + 1;
    }

    // ---- epilogue ----
    if (z == 0) {          // Q: hi/lo, scale folded in
#pragma unroll
        for (int mi = 0; mi < 2; mi++) {
            const int row = m0 + wm * 32 + mi * 16 + gr;
#pragma unroll
            for (int ni = 0; ni < 8; ni++) {
                const int col = n0 + wn * 64 + ni * 8 + tq;
                uint32_t h0, l0, h1, l1;
                split2(c[mi][ni][0] * SCALE_F, c[mi][ni][1] * SCALE_F, h0, l0);
                split2(c[mi][ni][2] * SCALE_F, c[mi][ni][3] * SCALE_F, h1, l1);
                *(uint32_t*)(g_qh + (size_t)row * HID + col)       = h0;
                *(uint32_t*)(g_ql + (size_t)row * HID + col)       = l0;
                *(uint32_t*)(g_qh + (size_t)(row + 8) * HID + col) = h1;
                *(uint32_t*)(g_ql + (size_t)(row + 8) * HID + col) = l1;
            }
        }
    } else if (z < 3) {    // K or V: single fp16 plane
        __half* dst = (z == 1) ? g_kh : g_vh;
#pragma unroll
        for (int mi = 0; mi < 2; mi++) {
            const int row = m0 + wm * 32 + mi * 16 + gr;
#pragma unroll
            for (int ni = 0; ni < 8; ni++) {
                const int col = n0 + wn * 64 + ni * 8 + tq;
                float b0 = 0.f, b1 = 0.f;
                if (z == 2) { b0 = bias_v[col]; b1 = bias_v[col + 1]; }
                __half2 v0, v1;
                v0.x = __float2half_rn(c[mi][ni][0] + b0);
                v0.y = __float2half_rn(c[mi][ni][1] + b1);
                v1.x = __float2half_rn(c[mi][ni][2] + b0);
                v1.y = __float2half_rn(c[mi][ni][3] + b1);
                *(__half2*)(dst + (size_t)row * HID + col)       = v0;
                *(__half2*)(dst + (size_t)(row + 8) * HID + col) = v1;
            }
        }
    } else {               // O projection: fp32 out + bo
#pragma unroll
        for (int mi = 0; mi < 2; mi++) {
            const int row = m0 + wm * 32 + mi * 16 + gr;
#pragma unroll
            for (int ni = 0; ni < 8; ni++) {
                const int col = n0 + wn * 64 + ni * 8 + tq;
                float b0 = bias_o[col], b1 = bias_o[col + 1];
                *(float2*)(outp + (size_t)row * HID + col) =
                    make_float2(c[mi][ni][0] + b0, c[mi][ni][1] + b1);
                *(float2*)(outp + (size_t)(row + 8) * HID + col) =
                    make_float2(c[mi][ni][2] + b0, c[mi][ni][3] + b1);
            }
        }
    }
}

// ---------------------------------------------------------------------------
// exp2 on the FMA pipe (softmax args are <= 0; clamp at -80)
// ---------------------------------------------------------------------------
__device__ __forceinline__ float fast_exp2(float x)
{
    x = fmaxf(x, -80.0f);
    float n = rintf(x);
    float f = x - n;
    float p = 1.5403530e-4f;
    p = fmaf(p, f, 1.3333558e-3f);
    p = fmaf(p, f, 9.6181291e-3f);
    p = fmaf(p, f, 5.5504109e-2f);
    p = fmaf(p, f, 2.4022651e-1f);
    p = fmaf(p, f, 6.9314718e-1f);
    p = fmaf(p, f, 1.0f);
    return p * __int_as_float(((int)n + 127) << 23);
}

// ---------------------------------------------------------------------------
// Tensor-core flash attention, fp16 2-term (Q split, K/V single planes),
// cp.async double-buffered K/V. CTA = 128 q-rows of one (b,h); 8 warps.
// smem: Qh/Ql 128x72 + 2 x [K,V] 64x72 = 73728 B.
// ---------------------------------------------------------------------------
#define ATS 72
#define AQPL (128 * ATS * 2)    // 18432
#define AKPL (64 * ATS * 2)     // 9216
#define OFF_KV (2 * AQPL)
#define KVBUF (2 * AKPL)        // K plane + V plane
#define ATTN_SMEM (2 * AQPL + 2 * KVBUF)   // 73728

__global__ __launch_bounds__(256, 2)
void attn_mma_kernel(const float* __restrict__ ebias)
{
    extern __shared__ char smem[];
    const uint32_t sbase = smem_u32(smem);
    const int tid = threadIdx.x, wid = tid >> 5, lid = tid & 31;
    const int qt = blockIdx.x, h = blockIdx.y, b = blockIdx.z;
    const int q0 = qt * 128;

    const int lrow = tid >> 3, lc8 = (tid & 7) * 8;

    auto load_kv = [&](int kc, int buf) {
        const size_t rb = (size_t)(b * NSEQ + kc * 64) * HID + h * DHEAD;
        const uint32_t sb = sbase + OFF_KV + buf * KVBUF;
#pragma unroll
        for (int sub = 0; sub < 2; sub++) {
            int row = lrow + sub * 32;
            cp16(sb + (row * ATS + lc8) * 2,        g_kh + rb + (size_t)row * HID + lc8);
            cp16(sb + AKPL + (row * ATS + lc8) * 2, g_vh + rb + (size_t)row * HID + lc8);
        }
        cp_commit();
    };

    // ---- load Q tile (hi/lo) ----
    {
        const __half* qh = g_qh + (size_t)(b * NSEQ + q0) * HID + h * DHEAD;
        const __half* ql = g_ql + (size_t)(b * NSEQ + q0) * HID + h * DHEAD;
#pragma unroll
        for (int l = 0; l < 4; l++) {
            int row = lrow + l * 32;
            uint32_t so = (row * ATS + lc8) * 2;
            cp16(sbase + so,        qh + (size_t)row * HID + lc8);
            cp16(sbase + AQPL + so, ql + (size_t)row * HID + lc8);
        }
        cp_commit();
    }
    load_kv(0, 0);

    const int gr = lid >> 2, tq = (lid & 3) * 2;
    const int rA = (lid & 7) + ((lid >> 3) & 1) * 8;
    const int kA = (lid >> 4) * 8;
    const int rB = (lid & 7) + (lid >> 4) * 8;
    const int kB = ((lid >> 3) & 1) * 8;
    const uint32_t aQh = sbase + ((wid * 16 + rA) * ATS + kA) * 2;
    const uint32_t aQl = aQh + AQPL;
    const uint32_t oK  = (rB * ATS + kB) * 2;
    const uint32_t oV  = ((lid & 15) * ATS + (lid >> 4) * 8) * 2;

    float acc[8][4];
#pragma unroll
    for (int j = 0; j < 8; j++)
#pragma unroll
        for (int r = 0; r < 4; r++) acc[j][r] = 0.f;
    float mr0 = -1e30f, mr1 = -1e30f, rs0 = 0.f, rs1 = 0.f;
    int nz0 = 0, nz1 = 0;

    const float* bp0 = ebias + ((size_t)b * NSEQ + q0 + wid * 16 + gr) * NSEQ + tq;
    const float* bp1 = bp0 + 8 * NSEQ;

#pragma unroll 1
    for (int kc = 0; kc < 8; kc++) {
        if (kc + 1 < 8) { load_kv(kc + 1, (kc + 1) & 1); cp_wait<1>(); }
        else            { cp_wait<0>(); }
        __syncthreads();

        const uint32_t aK = sbase + OFF_KV + (kc & 1) * KVBUF + oK;
        const uint32_t aV = sbase + OFF_KV + (kc & 1) * KVBUF + AKPL + oV;

        // ---- S = Q K^T (2-term) ----
        float c[8][4];
#pragma unroll
        for (int j = 0; j < 8; j++)
#pragma unroll
            for (int r = 0; r < 4; r++) c[j][r] = 0.f;

#pragma unroll
        for (int ks = 0; ks < 4; ks++) {
            uint32_t Qh[4], Ql[4];
            ldm4(Qh, aQh + ks * 32);
            ldm4(Ql, aQl + ks * 32);
#pragma unroll
            for (int np = 0; np < 4; np++) {
                uint32_t Kh[4];
                ldm4(Kh, aK + ks * 32 + np * 16 * ATS * 2);
                mma16816(c[np * 2],     Qh, Kh[0], Kh[1]);
                mma16816(c[np * 2 + 1], Qh, Kh[2], Kh[3]);
                mma16816(c[np * 2],     Ql, Kh[0], Kh[1]);
                mma16816(c[np * 2 + 1], Ql, Kh[2], Kh[3]);
            }
        }

        // ---- add bias, online softmax ----
        float mc0 = -1e30f, mc1 = -1e30f;
        int n0 = 0, n1 = 0;
#pragma unroll
        for (int j = 0; j < 8; j++) {
            float2 b0 = *(const float2*)(bp0 + kc * 64 + j * 8);
            float2 b1 = *(const float2*)(bp1 + kc * 64 + j * 8);
            c[j][0] += b0.x; c[j][1] += b0.y;
            c[j][2] += b1.x; c[j][3] += b1.y;
            mc0 = fmaxf(mc0, fmaxf(c[j][0], c[j][1]));
            mc1 = fmaxf(mc1, fmaxf(c[j][2], c[j][3]));
            n0 |= (c[j][0] != 0.f) | (c[j][1] != 0.f);
            n1 |= (c[j][2] != 0.f) | (c[j][3] != 0.f);
        }
#pragma unroll
        for (int o = 1; o < 4; o <<= 1) {
            mc0 = fmaxf(mc0, __shfl_xor_sync(0xffffffffu, mc0, o));
            mc1 = fmaxf(mc1, __shfl_xor_sync(0xffffffffu, mc1, o));
            n0 |= __shfl_xor_sync(0xffffffffu, n0, o);
            n1 |= __shfl_xor_sync(0xffffffffu, n1, o);
        }
        nz0 |= n0; nz1 |= n1;
        float mn0 = fmaxf(mr0, mc0), mn1 = fmaxf(mr1, mc1);
        float cr0 = fast_exp2((mr0 - mn0) * LOG2E_F);
        float cr1 = fast_exp2((mr1 - mn1) * LOG2E_F);
        mr0 = mn0; mr1 = mn1;

        float s0 = 0.f, s1 = 0.f;
#pragma unroll
        for (int j = 0; j < 8; j++) {
            c[j][0] = fast_exp2((c[j][0] - mn0) * LOG2E_F);
            c[j][1] = fast_exp2((c[j][1] - mn0) * LOG2E_F);
            c[j][2] = fast_exp2((c[j][2] - mn1) * LOG2E_F);
            c[j][3] = fast_exp2((c[j][3] - mn1) * LOG2E_F);
            s0 += c[j][0] + c[j][1];
            s1 += c[j][2] + c[j][3];
        }
#pragma unroll
        for (int o = 1; o < 4; o <<= 1) {
            s0 += __shfl_xor_sync(0xffffffffu, s0, o);
            s1 += __shfl_xor_sync(0xffffffffu, s1, o);
        }
        rs0 = rs0 * cr0 + s0;
        rs1 = rs1 * cr1 + s1;
#pragma unroll
        for (int j = 0; j < 8; j++) {
            acc[j][0] *= cr0; acc[j][1] *= cr0;
            acc[j][2] *= cr1; acc[j][3] *= cr1;
        }

        // ---- acc += P V (2-term: P split in-register, V single) ----
#pragma unroll
        for (int ks = 0; ks < 4; ks++) {
            uint32_t Ph[4], Pl[4];
            split2(c[2 * ks][0],     c[2 * ks][1],     Ph[0], Pl[0]);
            split2(c[2 * ks][2],     c[2 * ks][3],     Ph[1], Pl[1]);
            split2(c[2 * ks + 1][0], c[2 * ks + 1][1], Ph[2], Pl[2]);
            split2(c[2 * ks + 1][2], c[2 * ks + 1][3], Ph[3], Pl[3]);
#pragma unroll
            for (int np = 0; np < 4; np++) {
                uint32_t Vh[4];
                ldm4t(Vh, aV + ks * 16 * ATS * 2 + np * 32);
                mma16816(acc[np * 2],     Ph, Vh[0], Vh[1]);
                mma16816(acc[np * 2 + 1], Ph, Vh[2], Vh[3]);
                mma16816(acc[np * 2],     Pl, Vh[0], Vh[1]);
                mma16816(acc[np * 2 + 1], Pl, Vh[2], Vh[3]);
            }
        }
        __syncthreads();   // reads of buffer (kc&1) done before chunk kc+2 lands
    }

    // ---- epilogue: normalize (pad-mask) and store O hi/lo fp16 ----
    const float i0 = nz0 ? (1.f / rs0) : 0.f;
    const float i1 = nz1 ? (1.f / rs1) : 0.f;
    __half* oh = g_oh + (size_t)(b * NSEQ + q0 + wid * 16) * HID + h * DHEAD;
    __half* ol = g_ol + (size_t)(b * NSEQ + q0 + wid * 16) * HID + h * DHEAD;
#pragma unroll
    for (int j = 0; j < 8; j++) {
        const int col = j * 8 + tq;
        uint32_t h0, l0, h1, l1;
        split2(acc[j][0] * i0, acc[j][1] * i0, h0, l0);
        split2(acc[j][2] * i1, acc[j][3] * i1, h1, l1);
        *(uint32_t*)(oh + (size_t)gr * HID + col)       = h0;
        *(uint32_t*)(ol + (size_t)gr * HID + col)       = l0;
        *(uint32_t*)(oh + (size_t)(gr + 8) * HID + col) = h1;
        *(uint32_t*)(ol + (size_t)(gr + 8) * HID + col) = l1;
    }
}

// ---------------------------------------------------------------------------
// inputs: x, encoding_bias, Wq, Wk, Wv, bv, Wo, bo
// ---------------------------------------------------------------------------
extern "C" void kernel_launch(void* const* d_in, const int* in_sizes, int n_in,
                              void* d_out, int out_size)
{
    const float* x  = (const float*)d_in[0];
    const float* eb = (const float*)d_in[1];
    const float* Wq = (const float*)d_in[2];
    const float* Wk = (const float*)d_in[3];
    const float* Wv = (const float*)d_in[4];
    const float* bv = (const float*)d_in[5];
    const float* Wo = (const float*)d_in[6];
    const float* bo = (const float*)d_in[7];
    float* out = (float*)d_out;

    cudaFuncSetAttribute(attn_mma_kernel,
                         cudaFuncAttributeMaxDynamicSharedMemorySize, ATTN_SMEM);
    cudaFuncSetAttribute(gemm_mma_kernel,
                         cudaFuncAttributeMaxDynamicSharedMemorySize, GSMEM);

    const int nx4 = MTOT * HID / 4;
    const int nw4 = WSZ / 4;

    conv_split_x<<<(nx4 + 255) / 256, 256>>>(x, nx4);
    conv_w4<<<dim3((nw4 + 255) / 256, 4), 256>>>(Wq, Wk, Wv, Wo, nw4);

    gemm_mma_kernel<<<dim3(HID / GBN, MTOT / GBM, 3), 256, GSMEM>>>(
        nullptr, bv, nullptr, 0);                                   // Q,K,V

    attn_mma_kernel<<<dim3(4, NHEAD, 16), 256, ATTN_SMEM>>>(eb);    // O hi/lo

    gemm_mma_kernel<<<dim3(HID / GBN, MTOT / GBM, 1), 256, GSMEM>>>(
        out, nullptr, bo, 1);                                       // O proj
}

// round 14
// speedup vs baseline: 3.7665x; 1.0604x over previous
#include <cuda_runtime.h>
#include <cuda_fp16.h>
#include <cstdint>

// ---------------------------------------------------------------------------
// GraphormerMultiHeadAttention  (B=16, N=512, HIDDEN=768, 12 heads x 64)
//
// fp16 2-term split everywhere:  C = (Ah + Al) x Bh,  Bh = fp16-rounded B.
//   1) split x -> fp16 hi/lo; round W -> fp16
//   2) mma.sync fp16 GEMM, 3-stage cp.async pipeline (1 barrier/iter): QKV
//   3) mma.sync fp16 flash attention, log2-domain softmax w/ MUFU ex2
//   4) mma.sync GEMM O projection -> fp32 out
// ---------------------------------------------------------------------------

#define HID    768
#define MTOT   8192
#define NSEQ   512
#define NHEAD  12
#define DHEAD  64
#define SCALE_F 0.03608439182435161f   // 768^-0.5
#define LOG2E_F 1.4426950408889634f
#define QSCALE  (SCALE_F * LOG2E_F)    // log2-domain scores
#define WSZ (HID * HID)

// ---------------- scratch (device globals; allocation-free) ----------------
__device__ __align__(16) __half g_ah[MTOT * HID];   // x hi
__device__ __align__(16) __half g_al[MTOT * HID];   // x lo
__device__ __align__(16) __half g_qh[MTOT * HID];   // Q hi (scaled by QSCALE)
__device__ __align__(16) __half g_ql[MTOT * HID];   // Q lo
__device__ __align__(16) __half g_kh[MTOT * HID];   // K (single plane)
__device__ __align__(16) __half g_vh[MTOT * HID];   // V (single plane)
__device__ __align__(16) __half g_oh[MTOT * HID];   // attn out hi
__device__ __align__(16) __half g_ol[MTOT * HID];   // attn out lo
__device__ __align__(16) __half g_wh[4 * WSZ];      // Wq,Wk,Wv,Wo (single)

// ---------------------------------------------------------------------------
// conversions
// ---------------------------------------------------------------------------
__global__ void conv_split_x(const float* __restrict__ src, int n4)
{
    int i = blockIdx.x * blockDim.x + threadIdx.x;
    if (i >= n4) return;
    float4 v = ((const float4*)src)[i];
    __half2 H0 = __floats2half2_rn(v.x, v.y);
    __half2 H1 = __floats2half2_rn(v.z, v.w);
    float2 f0 = __half22float2(H0), f1 = __half22float2(H1);
    __half2 L0 = __floats2half2_rn(v.x - f0.x, v.y - f0.y);
    __half2 L1 = __floats2half2_rn(v.z - f1.x, v.w - f1.y);
    ((__half2*)g_ah)[2 * i] = H0; ((__half2*)g_ah)[2 * i + 1] = H1;
    ((__half2*)g_al)[2 * i] = L0; ((__half2*)g_al)[2 * i + 1] = L1;
}

__global__ void conv_w4(const float* __restrict__ w0,
                        const float* __restrict__ w1,
                        const float* __restrict__ w2,
                        const float* __restrict__ w3, int n4)
{
    int i = blockIdx.x * blockDim.x + threadIdx.x;
    if (i >= n4) return;
    const int z = blockIdx.y;
    const float* src = (z == 0) ? w0 : (z == 1) ? w1 : (z == 2) ? w2 : w3;
    float4 v = ((const float4*)src)[i];
    size_t base = (size_t)z * (WSZ / 2);
    ((__half2*)g_wh)[base + 2 * i]     = __floats2half2_rn(v.x, v.y);
    ((__half2*)g_wh)[base + 2 * i + 1] = __floats2half2_rn(v.z, v.w);
}

// ---------------------------------------------------------------------------
// warp-mma / async-copy helpers
// ---------------------------------------------------------------------------
__device__ __forceinline__ uint32_t smem_u32(const void* p)
{
    uint32_t a;
    asm("{ .reg .u64 t; cvta.to.shared.u64 t, %1; cvt.u32.u64 %0, t; }"
        : "=r"(a) : "l"(p));
    return a;
}
__device__ __forceinline__ void cp16(uint32_t dst, const void* src)
{
    size_t gsrc = __cvta_generic_to_global(src);
    asm volatile("cp.async.cg.shared.global [%0], [%1], 16;"
                 :: "r"(dst), "l"(gsrc) : "memory");
}
__device__ __forceinline__ void cp_commit()
{
    asm volatile("cp.async.commit_group;" ::: "memory");
}
template <int N>
__device__ __forceinline__ void cp_wait()
{
    asm volatile("cp.async.wait_group %0;" :: "n"(N) : "memory");
}
__device__ __forceinline__ void ldm4(uint32_t* r, uint32_t addr)
{
    asm volatile("ldmatrix.sync.aligned.m8n8.x4.shared.b16 {%0,%1,%2,%3}, [%4];"
                 : "=r"(r[0]), "=r"(r[1]), "=r"(r[2]), "=r"(r[3]) : "r"(addr));
}
__device__ __forceinline__ void ldm4t(uint32_t* r, uint32_t addr)
{
    asm volatile("ldmatrix.sync.aligned.m8n8.x4.trans.shared.b16 {%0,%1,%2,%3}, [%4];"
                 : "=r"(r[0]), "=r"(r[1]), "=r"(r[2]), "=r"(r[3]) : "r"(addr));
}
__device__ __forceinline__ void mma16816(float* c, const uint32_t* a,
                                         uint32_t b0, uint32_t b1)
{
    asm volatile(
        "mma.sync.aligned.m16n8k16.row.col.f32.f16.f16.f32 "
        "{%0,%1,%2,%3}, {%4,%5,%6,%7}, {%8,%9}, {%0,%1,%2,%3};"
        : "+f"(c[0]), "+f"(c[1]), "+f"(c[2]), "+f"(c[3])
        : "r"(a[0]), "r"(a[1]), "r"(a[2]), "r"(a[3]), "r"(b0), "r"(b1));
}
// MUFU exp2 (args <= 0 in softmax; large negatives -> 0)
__device__ __forceinline__ float ex2f(float x)
{
    float r;
    asm("ex2.approx.f32 %0, %1;" : "=f"(r) : "f"(x));
    return r;
}
// pack two fp32 into fp16x2 hi + fp16x2 lo
__device__ __forceinline__ void split2(float x, float y, uint32_t& h, uint32_t& l)
{
    __half2 H = __floats2half2_rn(x, y);
    float2 hf = __half22float2(H);
    __half2 L = __floats2half2_rn(x - hf.x, y - hf.y);
    h = *(uint32_t*)&H; l = *(uint32_t*)&L;
}

// ---------------------------------------------------------------------------
// GEMM-NT: C[m][n] = sum_k A[m][k] * W[n][k] (+ bias[n]), fp16 2-term,
// 3-stage cp.async pipeline, ONE barrier per k-iteration.
// z=0 -> Q hi/lo (QSCALE); z=1 -> K; z=2 -> V(+bv); z=3 -> fp32 out (+bo).
// ---------------------------------------------------------------------------
#define GBM 128
#define GBN 128
#define GBK 32
#define BKP 40
#define PLANE (128 * BKP * 2)     // 10240 B
#define BUFB  (3 * PLANE)         // Ah, Al, Bh = 30720 B per stage
#define NSTG  3
#define GSMEM (NSTG * BUFB)       // 92160 B
#define NKC (HID / GBK)           // 24

__global__ __launch_bounds__(256, 2)
void gemm_mma_kernel(float* __restrict__ outp,
                     const float* __restrict__ bias_v,
                     const float* __restrict__ bias_o,
                     int which)
{
    extern __shared__ char smem[];
    const uint32_t sbase = smem_u32(smem);
    const int tid = threadIdx.x, wid = tid >> 5, lid = tid & 31;

    const int z  = which ? 3 : blockIdx.z;
    const int n0 = blockIdx.x * GBN;
    const int m0 = blockIdx.y * GBM;

    const __half* gAh = ((z == 3) ? g_oh : g_ah) + (size_t)m0 * HID;
    const __half* gAl = ((z == 3) ? g_ol : g_al) + (size_t)m0 * HID;
    const __half* gBh = g_wh + (size_t)z * WSZ + (size_t)n0 * HID;

    const int lr = tid >> 2;
    const int ls = (tid & 3) * 8;
    const size_t gofs0 = (size_t)lr * HID + ls;
    const size_t gofs1 = (size_t)(lr + 64) * HID + ls;
    const uint32_t eofs0 = (lr * BKP + ls) * 2;
    const uint32_t eofs1 = ((lr + 64) * BKP + ls) * 2;

    const int wm = wid & 3, wn = wid >> 2;
    const int gr = lid >> 2, tq = (lid & 3) * 2;
    const int rA = (lid & 7) + ((lid >> 3) & 1) * 8;
    const int kA = (lid >> 4) * 8;
    const int rB = (lid & 7) + (lid >> 4) * 8;
    const int kB = ((lid >> 3) & 1) * 8;
    const uint32_t aoff = sbase + ((wm * 32 + rA) * BKP + kA) * 2;
    const uint32_t boff = sbase + 2 * PLANE + ((wn * 64 + rB) * BKP + kB) * 2;

    auto load_chunk = [&](int t, int stg) {
        const int ko = t * GBK;
        const uint32_t sb = sbase + stg * BUFB;
        cp16(sb + 0 * PLANE + eofs0, gAh + gofs0 + ko);
        cp16(sb + 0 * PLANE + eofs1, gAh + gofs1 + ko);
        cp16(sb + 1 * PLANE + eofs0, gAl + gofs0 + ko);
        cp16(sb + 1 * PLANE + eofs1, gAl + gofs1 + ko);
        cp16(sb + 2 * PLANE + eofs0, gBh + gofs0 + ko);
        cp16(sb + 2 * PLANE + eofs1, gBh + gofs1 + ko);
        cp_commit();
    };

    float c[2][8][4];
#pragma unroll
    for (int mi = 0; mi < 2; mi++)
#pragma unroll
        for (int ni = 0; ni < 8; ni++)
#pragma unroll
            for (int r = 0; r < 4; r++) c[mi][ni][r] = 0.f;

    load_chunk(0, 0);
    load_chunk(1, 1);

    int stg = 0, nstg = 2;
#pragma unroll 1
    for (int t = 0; t < NKC; t++) {
        cp_wait<1>();          // chunk t resident (empty commits keep indices)
        __syncthreads();       // also separates last iter's reads from new writes
        if (t + 2 < NKC) load_chunk(t + 2, nstg);
        else             cp_commit();               // empty group: keep accounting

        const uint32_t bb = stg * BUFB;
#pragma unroll
        for (int ks = 0; ks < 2; ks++) {
            uint32_t Ah[2][4], Al[2][4];
            ldm4(Ah[0], aoff + bb + ks * 32);
            ldm4(Ah[1], aoff + bb + ks * 32 + 16 * BKP * 2);
            ldm4(Al[0], aoff + bb + PLANE + ks * 32);
            ldm4(Al[1], aoff + bb + PLANE + ks * 32 + 16 * BKP * 2);
#pragma unroll
            for (int np = 0; np < 4; np++) {
                uint32_t Bh[4];
                ldm4(Bh, boff + bb + ks * 32 + np * 16 * BKP * 2);
#pragma unroll
                for (int mi = 0; mi < 2; mi++) {
                    mma16816(c[mi][np * 2],     Ah[mi], Bh[0], Bh[1]);
                    mma16816(c[mi][np * 2 + 1], Ah[mi], Bh[2], Bh[3]);
                    mma16816(c[mi][np * 2],     Al[mi], Bh[0], Bh[1]);
                    mma16816(c[mi][np * 2 + 1], Al[mi], Bh[2], Bh[3]);
                }
            }
        }
        stg = (stg == 2) ? 0 : stg + 1;
        nstg = (nstg == 2) ? 0 : nstg + 1;
    }

    // ---- epilogue ----
    if (z == 0) {          // Q: hi/lo, QSCALE (log2-domain) folded in
#pragma unroll
        for (int mi = 0; mi < 2; mi++) {
            const int row = m0 + wm * 32 + mi * 16 + gr;
#pragma unroll
            for (int ni = 0; ni < 8; ni++) {
                const int col = n0 + wn * 64 + ni * 8 + tq;
                uint32_t h0, l0, h1, l1;
                split2(c[mi][ni][0] * QSCALE, c[mi][ni][1] * QSCALE, h0, l0);
                split2(c[mi][ni][2] * QSCALE, c[mi][ni][3] * QSCALE, h1, l1);
                *(uint32_t*)(g_qh + (size_t)row * HID + col)       = h0;
                *(uint32_t*)(g_ql + (size_t)row * HID + col)       = l0;
                *(uint32_t*)(g_qh + (size_t)(row + 8) * HID + col) = h1;
                *(uint32_t*)(g_ql + (size_t)(row + 8) * HID + col) = l1;
            }
        }
    } else if (z < 3) {    // K or V: single fp16 plane
        __half* dst = (z == 1) ? g_kh : g_vh;
#pragma unroll
        for (int mi = 0; mi < 2; mi++) {
            const int row = m0 + wm * 32 + mi * 16 + gr;
#pragma unroll
            for (int ni = 0; ni < 8; ni++) {
                const int col = n0 + wn * 64 + ni * 8 + tq;
                float b0 = 0.f, b1 = 0.f;
                if (z == 2) { b0 = bias_v[col]; b1 = bias_v[col + 1]; }
                *(__half2*)(dst + (size_t)row * HID + col) =
                    __floats2half2_rn(c[mi][ni][0] + b0, c[mi][ni][1] + b1);
                *(__half2*)(dst + (size_t)(row + 8) * HID + col) =
                    __floats2half2_rn(c[mi][ni][2] + b0, c[mi][ni][3] + b1);
            }
        }
    } else {               // O projection: fp32 out + bo
#pragma unroll
        for (int mi = 0; mi < 2; mi++) {
            const int row = m0 + wm * 32 + mi * 16 + gr;
#pragma unroll
            for (int ni = 0; ni < 8; ni++) {
                const int col = n0 + wn * 64 + ni * 8 + tq;
                float b0 = bias_o[col], b1 = bias_o[col + 1];
                *(float2*)(outp + (size_t)row * HID + col) =
                    make_float2(c[mi][ni][0] + b0, c[mi][ni][1] + b1);
                *(float2*)(outp + (size_t)(row + 8) * HID + col) =
                    make_float2(c[mi][ni][2] + b0, c[mi][ni][3] + b1);
            }
        }
    }
}

// ---------------------------------------------------------------------------
// Tensor-core flash attention, fp16 2-term, log2-domain softmax (MUFU ex2),
// cp.async double-buffered K/V, ONE barrier per chunk.
// CTA = 128 q-rows of one (b,h); 8 warps.
// smem: Qh/Ql 128x72 + 2 x [K,V] 64x72 = 73728 B.
// ---------------------------------------------------------------------------
#define ATS 72
#define AQPL (128 * ATS * 2)    // 18432
#define AKPL (64 * ATS * 2)     // 9216
#define OFF_KV (2 * AQPL)
#define KVBUF (2 * AKPL)
#define ATTN_SMEM (2 * AQPL + 2 * KVBUF)   // 73728

__global__ __launch_bounds__(256, 2)
void attn_mma_kernel(const float* __restrict__ ebias)
{
    extern __shared__ char smem[];
    const uint32_t sbase = smem_u32(smem);
    const int tid = threadIdx.x, wid = tid >> 5, lid = tid & 31;
    const int qt = blockIdx.x, h = blockIdx.y, b = blockIdx.z;
    const int q0 = qt * 128;

    const int lrow = tid >> 3, lc8 = (tid & 7) * 8;

    auto load_kv = [&](int kc, int buf) {
        const size_t rb = (size_t)(b * NSEQ + kc * 64) * HID + h * DHEAD;
        const uint32_t sb = sbase + OFF_KV + buf * KVBUF;
#pragma unroll
        for (int sub = 0; sub < 2; sub++) {
            int row = lrow + sub * 32;
            cp16(sb + (row * ATS + lc8) * 2,        g_kh + rb + (size_t)row * HID + lc8);
            cp16(sb + AKPL + (row * ATS + lc8) * 2, g_vh + rb + (size_t)row * HID + lc8);
        }
        cp_commit();
    };

    // ---- load Q tile (hi/lo) ----
    {
        const __half* qh = g_qh + (size_t)(b * NSEQ + q0) * HID + h * DHEAD;
        const __half* ql = g_ql + (size_t)(b * NSEQ + q0) * HID + h * DHEAD;
#pragma unroll
        for (int l = 0; l < 4; l++) {
            int row = lrow + l * 32;
            uint32_t so = (row * ATS + lc8) * 2;
            cp16(sbase + so,        qh + (size_t)row * HID + lc8);
            cp16(sbase + AQPL + so, ql + (size_t)row * HID + lc8);
        }
        cp_commit();
    }
    load_kv(0, 0);

    const int gr = lid >> 2, tq = (lid & 3) * 2;
    const int rA = (lid & 7) + ((lid >> 3) & 1) * 8;
    const int kA = (lid >> 4) * 8;
    const int rB = (lid & 7) + (lid >> 4) * 8;
    const int kB = ((lid >> 3) & 1) * 8;
    const uint32_t aQh = sbase + ((wid * 16 + rA) * ATS + kA) * 2;
    const uint32_t aQl = aQh + AQPL;
    const uint32_t oK  = (rB * ATS + kB) * 2;
    const uint32_t oV  = ((lid & 15) * ATS + (lid >> 4) * 8) * 2;

    float acc[8][4];
#pragma unroll
    for (int j = 0; j < 8; j++)
#pragma unroll
        for (int r = 0; r < 4; r++) acc[j][r] = 0.f;
    float mr0 = -1e30f, mr1 = -1e30f, rs0 = 0.f, rs1 = 0.f;
    int nz0 = 0, nz1 = 0;

    const float* bp0 = ebias + ((size_t)b * NSEQ + q0 + wid * 16 + gr) * NSEQ + tq;
    const float* bp1 = bp0 + 8 * NSEQ;

#pragma unroll 1
    for (int kc = 0; kc < 8; kc++) {
        cp_wait<0>();      // Q (first iter) + K/V chunk kc resident
        __syncthreads();   // also separates last iter's reads from new writes
        if (kc + 1 < 8) load_kv(kc + 1, (kc + 1) & 1);

        const uint32_t aK = sbase + OFF_KV + (kc & 1) * KVBUF + oK;
        const uint32_t aV = sbase + OFF_KV + (kc & 1) * KVBUF + AKPL + oV;

        // ---- S = Q K^T (2-term, log2 domain) ----
        float c[8][4];
#pragma unroll
        for (int j = 0; j < 8; j++)
#pragma unroll
            for (int r = 0; r < 4; r++) c[j][r] = 0.f;

#pragma unroll
        for (int ks = 0; ks < 4; ks++) {
            uint32_t Qh[4], Ql[4];
            ldm4(Qh, aQh + ks * 32);
            ldm4(Ql, aQl + ks * 32);
#pragma unroll
            for (int np = 0; np < 4; np++) {
                uint32_t Kh[4];
                ldm4(Kh, aK + ks * 32 + np * 16 * ATS * 2);
                mma16816(c[np * 2],     Qh, Kh[0], Kh[1]);
                mma16816(c[np * 2 + 1], Qh, Kh[2], Kh[3]);
                mma16816(c[np * 2],     Ql, Kh[0], Kh[1]);
                mma16816(c[np * 2 + 1], Ql, Kh[2], Kh[3]);
            }
        }

        // ---- add bias (x LOG2E via FMA), online softmax in log2 domain ----
        float mc0 = -1e30f, mc1 = -1e30f;
        int n0 = 0, n1 = 0;
#pragma unroll
        for (int j = 0; j < 8; j++) {
            float2 b0 = *(const float2*)(bp0 + kc * 64 + j * 8);
            float2 b1 = *(const float2*)(bp1 + kc * 64 + j * 8);
            c[j][0] = fmaf(b0.x, LOG2E_F, c[j][0]);
            c[j][1] = fmaf(b0.y, LOG2E_F, c[j][1]);
            c[j][2] = fmaf(b1.x, LOG2E_F, c[j][2]);
            c[j][3] = fmaf(b1.y, LOG2E_F, c[j][3]);
            mc0 = fmaxf(mc0, fmaxf(c[j][0], c[j][1]));
            mc1 = fmaxf(mc1, fmaxf(c[j][2], c[j][3]));
            n0 |= (c[j][0] != 0.f) | (c[j][1] != 0.f);
            n1 |= (c[j][2] != 0.f) | (c[j][3] != 0.f);
        }
#pragma unroll
        for (int o = 1; o < 4; o <<= 1) {
            mc0 = fmaxf(mc0, __shfl_xor_sync(0xffffffffu, mc0, o));
            mc1 = fmaxf(mc1, __shfl_xor_sync(0xffffffffu, mc1, o));
            n0 |= __shfl_xor_sync(0xffffffffu, n0, o);
            n1 |= __shfl_xor_sync(0xffffffffu, n1, o);
        }
        nz0 |= n0; nz1 |= n1;
        float mn0 = fmaxf(mr0, mc0), mn1 = fmaxf(mr1, mc1);
        float cr0 = ex2f(mr0 - mn0);
        float cr1 = ex2f(mr1 - mn1);
        mr0 = mn0; mr1 = mn1;

        float s0 = 0.f, s1 = 0.f;
#pragma unroll
        for (int j = 0; j < 8; j++) {
            c[j][0] = ex2f(c[j][0] - mn0);
            c[j][1] = ex2f(c[j][1] - mn0);
            c[j][2] = ex2f(c[j][2] - mn1);
            c[j][3] = ex2f(c[j][3] - mn1);
            s0 += c[j][0] + c[j][1];
            s1 += c[j][2] + c[j][3];
        }
#pragma unroll
        for (int o = 1; o < 4; o <<= 1) {
            s0 += __shfl_xor_sync(0xffffffffu, s0, o);
            s1 += __shfl_xor_sync(0xffffffffu, s1, o);
        }
        rs0 = rs0 * cr0 + s0;
        rs1 = rs1 * cr1 + s1;
#pragma unroll
        for (int j = 0; j < 8; j++) {
            acc[j][0] *= cr0; acc[j][1] *= cr0;
            acc[j][2] *= cr1; acc[j][3] *= cr1;
        }

        // ---- acc += P V (2-term: P split in-register, V single) ----
#pragma unroll
        for (int ks = 0; ks < 4; ks++) {
            uint32_t Ph[4], Pl[4];
            split2(c[2 * ks][0],     c[2 * ks][1],     Ph[0], Pl[0]);
            split2(c[2 * ks][2],     c[2 * ks][3],     Ph[1], Pl[1]);
            split2(c[2 * ks + 1][0], c[2 * ks + 1][1], Ph[2], Pl[2]);
            split2(c[2 * ks + 1][2], c[2 * ks + 1][3], Ph[3], Pl[3]);
#pragma unroll
            for (int np = 0; np < 4; np++) {
                uint32_t Vh[4];
                ldm4t(Vh, aV + ks * 16 * ATS * 2 + np * 32);
                mma16816(acc[np * 2],     Ph, Vh[0], Vh[1]);
                mma16816(acc[np * 2 + 1], Ph, Vh[2], Vh[3]);
                mma16816(acc[np * 2],     Pl, Vh[0], Vh[1]);
                mma16816(acc[np * 2 + 1], Pl, Vh[2], Vh[3]);
            }
        }
    }

    // ---- epilogue: normalize (pad-mask) and store O hi/lo fp16 ----
    const float i0 = nz0 ? (1.f / rs0) : 0.f;
    const float i1 = nz1 ? (1.f / rs1) : 0.f;
    __half* oh = g_oh + (size_t)(b * NSEQ + q0 + wid * 16) * HID + h * DHEAD;
    __half* ol = g_ol + (size_t)(b * NSEQ + q0 + wid * 16) * HID + h * DHEAD;
#pragma unroll
    for (int j = 0; j < 8; j++) {
        const int col = j * 8 + tq;
        uint32_t h0, l0, h1, l1;
        split2(acc[j][0] * i0, acc[j][1] * i0, h0, l0);
        split2(acc[j][2] * i1, acc[j][3] * i1, h1, l1);
        *(uint32_t*)(oh + (size_t)gr * HID + col)       = h0;
        *(uint32_t*)(ol + (size_t)gr * HID + col)       = l0;
        *(uint32_t*)(oh + (size_t)(gr + 8) * HID + col) = h1;
        *(uint32_t*)(ol + (size_t)(gr + 8) * HID + col) = l1;
    }
}

// ---------------------------------------------------------------------------
// inputs: x, encoding_bias, Wq, Wk, Wv, bv, Wo, bo
// ---------------------------------------------------------------------------
extern "C" void kernel_launch(void* const* d_in, const int* in_sizes, int n_in,
                              void* d_out, int out_size)
{
    const float* x  = (const float*)d_in[0];
    const float* eb = (const float*)d_in[1];
    const float* Wq = (const float*)d_in[2];
    const float* Wk = (const float*)d_in[3];
    const float* Wv = (const float*)d_in[4];
    const float* bv = (const float*)d_in[5];
    const float* Wo = (const float*)d_in[6];
    const float* bo = (const float*)d_in[7];
    float* out = (float*)d_out;

    cudaFuncSetAttribute(attn_mma_kernel,
                         cudaFuncAttributeMaxDynamicSharedMemorySize, ATTN_SMEM);
    cudaFuncSetAttribute(gemm_mma_kernel,
                         cudaFuncAttributeMaxDynamicSharedMemorySize, GSMEM);

    const int nx4 = MTOT * HID / 4;
    const int nw4 = WSZ / 4;

    conv_split_x<<<(nx4 + 255) / 256, 256>>>(x, nx4);
    conv_w4<<<dim3((nw4 + 255) / 256, 4), 256>>>(Wq, Wk, Wv, Wo, nw4);

    gemm_mma_kernel<<<dim3(HID / GBN, MTOT / GBM, 3), 256, GSMEM>>>(
        nullptr, bv, nullptr, 0);                                   // Q,K,V

    attn_mma_kernel<<<dim3(4, NHEAD, 16), 256, ATTN_SMEM>>>(eb);    // O hi/lo

    gemm_mma_kernel<<<dim3(HID / GBN, MTOT / GBM, 1), 256, GSMEM>>>(
        out, nullptr, bo, 1);                                       // O proj
}

// round 15
// speedup vs baseline: 5.0372x; 1.3374x over previous
#include <cuda_runtime.h>
#include <cuda_fp16.h>
#include <cstdint>

// ---------------------------------------------------------------------------
// GraphormerMultiHeadAttention  (B=16, N=512, HIDDEN=768, 12 heads x 64)
//
// Precision allocated by error-path analysis:
//   score path (Q,K):  1-term fp16 (exp sensitivity is absolute-score ~2^-12)
//   value path (V,P):  1-term fp16 (each adds ~2^-12 to O)
//   output path (O):   2-term fp16 hi/lo into the final projection
// Predicted rel_err ~5.5e-4 (< 1e-3 gate).
//   1) round x, W -> fp16
//   2) mma.sync fp16 GEMM<1-term>, 3-stage cp.async pipeline: QKV fused
//   3) mma.sync fp16 flash attention, log2-domain softmax (MUFU ex2)
//   4) mma.sync GEMM<2-term> O projection -> fp32 out
// ---------------------------------------------------------------------------

#define HID    768
#define MTOT   8192
#define NSEQ   512
#define NHEAD  12
#define DHEAD  64
#define SCALE_F 0.03608439182435161f   // 768^-0.5
#define LOG2E_F 1.4426950408889634f
#define QSCALE  (SCALE_F * LOG2E_F)    // log2-domain scores
#define WSZ (HID * HID)

// ---------------- scratch (device globals; allocation-free) ----------------
__device__ __align__(16) __half g_ah[MTOT * HID];   // x (fp16)
__device__ __align__(16) __half g_qh[MTOT * HID];   // Q (QSCALE folded)
__device__ __align__(16) __half g_kh[MTOT * HID];   // K
__device__ __align__(16) __half g_vh[MTOT * HID];   // V
__device__ __align__(16) __half g_oh[MTOT * HID];   // attn out hi
__device__ __align__(16) __half g_ol[MTOT * HID];   // attn out lo
__device__ __align__(16) __half g_wh[4 * WSZ];      // Wq,Wk,Wv,Wo (fp16)

// ---------------------------------------------------------------------------
// conversions
// ---------------------------------------------------------------------------
__global__ void conv_round_x(const float* __restrict__ src, int n4)
{
    int i = blockIdx.x * blockDim.x + threadIdx.x;
    if (i >= n4) return;
    float4 v = ((const float4*)src)[i];
    ((__half2*)g_ah)[2 * i]     = __floats2half2_rn(v.x, v.y);
    ((__half2*)g_ah)[2 * i + 1] = __floats2half2_rn(v.z, v.w);
}

__global__ void conv_w4(const float* __restrict__ w0,
                        const float* __restrict__ w1,
                        const float* __restrict__ w2,
                        const float* __restrict__ w3, int n4)
{
    int i = blockIdx.x * blockDim.x + threadIdx.x;
    if (i >= n4) return;
    const int z = blockIdx.y;
    const float* src = (z == 0) ? w0 : (z == 1) ? w1 : (z == 2) ? w2 : w3;
    float4 v = ((const float4*)src)[i];
    size_t base = (size_t)z * (WSZ / 2);
    ((__half2*)g_wh)[base + 2 * i]     = __floats2half2_rn(v.x, v.y);
    ((__half2*)g_wh)[base + 2 * i + 1] = __floats2half2_rn(v.z, v.w);
}

// ---------------------------------------------------------------------------
// warp-mma / async-copy helpers
// ---------------------------------------------------------------------------
__device__ __forceinline__ uint32_t smem_u32(const void* p)
{
    uint32_t a;
    asm("{ .reg .u64 t; cvta.to.shared.u64 t, %1; cvt.u32.u64 %0, t; }"
        : "=r"(a) : "l"(p));
    return a;
}
__device__ __forceinline__ void cp16(uint32_t dst, const void* src)
{
    size_t gsrc = __cvta_generic_to_global(src);
    asm volatile("cp.async.cg.shared.global [%0], [%1], 16;"
                 :: "r"(dst), "l"(gsrc) : "memory");
}
__device__ __forceinline__ void cp_commit()
{
    asm volatile("cp.async.commit_group;" ::: "memory");
}
template <int N>
__device__ __forceinline__ void cp_wait()
{
    asm volatile("cp.async.wait_group %0;" :: "n"(N) : "memory");
}
__device__ __forceinline__ void ldm4(uint32_t* r, uint32_t addr)
{
    asm volatile("ldmatrix.sync.aligned.m8n8.x4.shared.b16 {%0,%1,%2,%3}, [%4];"
                 : "=r"(r[0]), "=r"(r[1]), "=r"(r[2]), "=r"(r[3]) : "r"(addr));
}
__device__ __forceinline__ void ldm4t(uint32_t* r, uint32_t addr)
{
    asm volatile("ldmatrix.sync.aligned.m8n8.x4.trans.shared.b16 {%0,%1,%2,%3}, [%4];"
                 : "=r"(r[0]), "=r"(r[1]), "=r"(r[2]), "=r"(r[3]) : "r"(addr));
}
__device__ __forceinline__ void mma16816(float* c, const uint32_t* a,
                                         uint32_t b0, uint32_t b1)
{
    asm volatile(
        "mma.sync.aligned.m16n8k16.row.col.f32.f16.f16.f32 "
        "{%0,%1,%2,%3}, {%4,%5,%6,%7}, {%8,%9}, {%0,%1,%2,%3};"
        : "+f"(c[0]), "+f"(c[1]), "+f"(c[2]), "+f"(c[3])
        : "r"(a[0]), "r"(a[1]), "r"(a[2]), "r"(a[3]), "r"(b0), "r"(b1));
}
__device__ __forceinline__ float ex2f(float x)
{
    float r;
    asm("ex2.approx.f32 %0, %1;" : "=f"(r) : "f"(x));
    return r;
}
__device__ __forceinline__ uint32_t packh2(float x, float y)
{
    __half2 H = __floats2half2_rn(x, y);
    return *(uint32_t*)&H;
}
__device__ __forceinline__ void split2(float x, float y, uint32_t& h, uint32_t& l)
{
    __half2 H = __floats2half2_rn(x, y);
    float2 hf = __half22float2(H);
    __half2 L = __floats2half2_rn(x - hf.x, y - hf.y);
    h = *(uint32_t*)&H; l = *(uint32_t*)&L;
}

// ---------------------------------------------------------------------------
// GEMM-NT: C[m][n] = sum_k A[m][k] * W[n][k] (+ bias), fp16, TERMS-term A,
// 3-stage cp.async pipeline, one barrier per k-iter. CTA 128x128x(k32).
// z=0 -> Q (QSCALE); z=1 -> K; z=2 -> V(+bv); z=3 -> fp32 out (+bo, 2-term A).
// ---------------------------------------------------------------------------
#define GBM 128
#define GBN 128
#define GBK 32
#define BKP 40
#define PLANE (128 * BKP * 2)     // 10240 B per 128-row plane
#define NKC (HID / GBK)           // 24

template <int TERMS>
__global__ __launch_bounds__(256, 2)
void gemm_mma_kernel(float* __restrict__ outp,
                     const float* __restrict__ bias_v,
                     const float* __restrict__ bias_o,
                     int z_base)
{
    constexpr int NPL = TERMS + 1;             // A-hi [,A-lo], B
    constexpr uint32_t BUFB = NPL * PLANE;
    extern __shared__ char smem[];
    const uint32_t sbase = smem_u32(smem);
    const int tid = threadIdx.x, wid = tid >> 5, lid = tid & 31;

    const int z  = z_base + blockIdx.z;
    const int n0 = blockIdx.x * GBN;
    const int m0 = blockIdx.y * GBM;

    const __half* gAh = ((z == 3) ? g_oh : g_ah) + (size_t)m0 * HID;
    const __half* gAl = g_ol + (size_t)m0 * HID;           // used iff TERMS==2
    const __half* gBh = g_wh + (size_t)z * WSZ + (size_t)n0 * HID;

    const int lr = tid >> 2;
    const int ls = (tid & 3) * 8;
    const size_t gofs0 = (size_t)lr * HID + ls;
    const size_t gofs1 = (size_t)(lr + 64) * HID + ls;
    const uint32_t eofs0 = (lr * BKP + ls) * 2;
    const uint32_t eofs1 = ((lr + 64) * BKP + ls) * 2;

    const int wm = wid & 3, wn = wid >> 2;
    const int gr = lid >> 2, tq = (lid & 3) * 2;
    const int rA = (lid & 7) + ((lid >> 3) & 1) * 8;
    const int kA = (lid >> 4) * 8;
    const int rB = (lid & 7) + (lid >> 4) * 8;
    const int kB = ((lid >> 3) & 1) * 8;
    const uint32_t aoff = sbase + ((wm * 32 + rA) * BKP + kA) * 2;
    const uint32_t boff = sbase + TERMS * PLANE + ((wn * 64 + rB) * BKP + kB) * 2;

    auto load_chunk = [&](int t, int stg) {
        const int ko = t * GBK;
        const uint32_t sb = sbase + stg * BUFB;
        cp16(sb + eofs0, gAh + gofs0 + ko);
        cp16(sb + eofs1, gAh + gofs1 + ko);
        if (TERMS == 2) {
            cp16(sb + PLANE + eofs0, gAl + gofs0 + ko);
            cp16(sb + PLANE + eofs1, gAl + gofs1 + ko);
        }
        cp16(sb + TERMS * PLANE + eofs0, gBh + gofs0 + ko);
        cp16(sb + TERMS * PLANE + eofs1, gBh + gofs1 + ko);
        cp_commit();
    };

    float c[2][8][4];
#pragma unroll
    for (int mi = 0; mi < 2; mi++)
#pragma unroll
        for (int ni = 0; ni < 8; ni++)
#pragma unroll
            for (int r = 0; r < 4; r++) c[mi][ni][r] = 0.f;

    load_chunk(0, 0);
    load_chunk(1, 1);

    int stg = 0, nstg = 2;
#pragma unroll 1
    for (int t = 0; t < NKC; t++) {
        cp_wait<1>();
        __syncthreads();
        if (t + 2 < NKC) load_chunk(t + 2, nstg);
        else             cp_commit();

        const uint32_t bb = stg * BUFB;
#pragma unroll
        for (int ks = 0; ks < 2; ks++) {
            uint32_t Ah[2][4], Al[2][4];
            ldm4(Ah[0], aoff + bb + ks * 32);
            ldm4(Ah[1], aoff + bb + ks * 32 + 16 * BKP * 2);
            if (TERMS == 2) {
                ldm4(Al[0], aoff + bb + PLANE + ks * 32);
                ldm4(Al[1], aoff + bb + PLANE + ks * 32 + 16 * BKP * 2);
            }
#pragma unroll
            for (int np = 0; np < 4; np++) {
                uint32_t Bh[4];
                ldm4(Bh, boff + bb + ks * 32 + np * 16 * BKP * 2);
#pragma unroll
                for (int mi = 0; mi < 2; mi++) {
                    mma16816(c[mi][np * 2],     Ah[mi], Bh[0], Bh[1]);
                    mma16816(c[mi][np * 2 + 1], Ah[mi], Bh[2], Bh[3]);
                    if (TERMS == 2) {
                        mma16816(c[mi][np * 2],     Al[mi], Bh[0], Bh[1]);
                        mma16816(c[mi][np * 2 + 1], Al[mi], Bh[2], Bh[3]);
                    }
                }
            }
        }
        stg = (stg == 2) ? 0 : stg + 1;
        nstg = (nstg == 2) ? 0 : nstg + 1;
    }

    // ---- epilogue ----
    if (z == 0) {          // Q: single plane, QSCALE (log2-domain) folded in
#pragma unroll
        for (int mi = 0; mi < 2; mi++) {
            const int row = m0 + wm * 32 + mi * 16 + gr;
#pragma unroll
            for (int ni = 0; ni < 8; ni++) {
                const int col = n0 + wn * 64 + ni * 8 + tq;
                *(uint32_t*)(g_qh + (size_t)row * HID + col) =
                    packh2(c[mi][ni][0] * QSCALE, c[mi][ni][1] * QSCALE);
                *(uint32_t*)(g_qh + (size_t)(row + 8) * HID + col) =
                    packh2(c[mi][ni][2] * QSCALE, c[mi][ni][3] * QSCALE);
            }
        }
    } else if (z < 3) {    // K or V
        __half* dst = (z == 1) ? g_kh : g_vh;
#pragma unroll
        for (int mi = 0; mi < 2; mi++) {
            const int row = m0 + wm * 32 + mi * 16 + gr;
#pragma unroll
            for (int ni = 0; ni < 8; ni++) {
                const int col = n0 + wn * 64 + ni * 8 + tq;
                float b0 = 0.f, b1 = 0.f;
                if (z == 2) { b0 = bias_v[col]; b1 = bias_v[col + 1]; }
                *(uint32_t*)(dst + (size_t)row * HID + col) =
                    packh2(c[mi][ni][0] + b0, c[mi][ni][1] + b1);
                *(uint32_t*)(dst + (size_t)(row + 8) * HID + col) =
                    packh2(c[mi][ni][2] + b0, c[mi][ni][3] + b1);
            }
        }
    } else {               // O projection: fp32 out + bo
#pragma unroll
        for (int mi = 0; mi < 2; mi++) {
            const int row = m0 + wm * 32 + mi * 16 + gr;
#pragma unroll
            for (int ni = 0; ni < 8; ni++) {
                const int col = n0 + wn * 64 + ni * 8 + tq;
                float b0 = bias_o[col], b1 = bias_o[col + 1];
                *(float2*)(outp + (size_t)row * HID + col) =
                    make_float2(c[mi][ni][0] + b0, c[mi][ni][1] + b1);
                *(float2*)(outp + (size_t)(row + 8) * HID + col) =
                    make_float2(c[mi][ni][2] + b0, c[mi][ni][3] + b1);
            }
        }
    }
}

// ---------------------------------------------------------------------------
// Tensor-core flash attention: Q,K,V,P single fp16; log2-domain softmax via
// MUFU ex2; cp.async double-buffered K/V; one barrier per chunk.
// CTA = 128 q-rows of one (b,h); 8 warps. O written as fp16 hi/lo (2-term).
// smem: Q 128x72 + 2 x [K,V] 64x72 = 55296 B.
// ---------------------------------------------------------------------------
#define ATS 72
#define AQPL (128 * ATS * 2)    // 18432
#define AKPL (64 * ATS * 2)     // 9216
#define OFF_KV AQPL
#define KVBUF (2 * AKPL)
#define ATTN_SMEM (AQPL + 2 * KVBUF)   // 55296

__global__ __launch_bounds__(256, 2)
void attn_mma_kernel(const float* __restrict__ ebias)
{
    extern __shared__ char smem[];
    const uint32_t sbase = smem_u32(smem);
    const int tid = threadIdx.x, wid = tid >> 5, lid = tid & 31;
    const int qt = blockIdx.x, h = blockIdx.y, b = blockIdx.z;
    const int q0 = qt * 128;

    const int lrow = tid >> 3, lc8 = (tid & 7) * 8;

    auto load_kv = [&](int kc, int buf) {
        const size_t rb = (size_t)(b * NSEQ + kc * 64) * HID + h * DHEAD;
        const uint32_t sb = sbase + OFF_KV + buf * KVBUF;
#pragma unroll
        for (int sub = 0; sub < 2; sub++) {
            int row = lrow + sub * 32;
            cp16(sb + (row * ATS + lc8) * 2,        g_kh + rb + (size_t)row * HID + lc8);
            cp16(sb + AKPL + (row * ATS + lc8) * 2, g_vh + rb + (size_t)row * HID + lc8);
        }
        cp_commit();
    };

    // ---- load Q tile ----
    {
        const __half* qh = g_qh + (size_t)(b * NSEQ + q0) * HID + h * DHEAD;
#pragma unroll
        for (int l = 0; l < 4; l++) {
            int row = lrow + l * 32;
            cp16(sbase + (row * ATS + lc8) * 2, qh + (size_t)row * HID + lc8);
        }
        cp_commit();
    }
    load_kv(0, 0);

    const int gr = lid >> 2, tq = (lid & 3) * 2;
    const int rA = (lid & 7) + ((lid >> 3) & 1) * 8;
    const int kA = (lid >> 4) * 8;
    const int rB = (lid & 7) + (lid >> 4) * 8;
    const int kB = ((lid >> 3) & 1) * 8;
    const uint32_t aQh = sbase + ((wid * 16 + rA) * ATS + kA) * 2;
    const uint32_t oK  = (rB * ATS + kB) * 2;
    const uint32_t oV  = ((lid & 15) * ATS + (lid >> 4) * 8) * 2;

    float acc[8][4];
#pragma unroll
    for (int j = 0; j < 8; j++)
#pragma unroll
        for (int r = 0; r < 4; r++) acc[j][r] = 0.f;
    float mr0 = -1e30f, mr1 = -1e30f, rs0 = 0.f, rs1 = 0.f;
    int nz0 = 0, nz1 = 0;

    const float* bp0 = ebias + ((size_t)b * NSEQ + q0 + wid * 16 + gr) * NSEQ + tq;
    const float* bp1 = bp0 + 8 * NSEQ;

#pragma unroll 1
    for (int kc = 0; kc < 8; kc++) {
        cp_wait<0>();
        __syncthreads();
        if (kc + 1 < 8) load_kv(kc + 1, (kc + 1) & 1);

        const uint32_t aK = sbase + OFF_KV + (kc & 1) * KVBUF + oK;
        const uint32_t aV = sbase + OFF_KV + (kc & 1) * KVBUF + AKPL + oV;

        // ---- S = Q K^T (log2 domain) ----
        float c[8][4];
#pragma unroll
        for (int j = 0; j < 8; j++)
#pragma unroll
            for (int r = 0; r < 4; r++) c[j][r] = 0.f;

#pragma unroll
        for (int ks = 0; ks < 4; ks++) {
            uint32_t Qh[4];
            ldm4(Qh, aQh + ks * 32);
#pragma unroll
            for (int np = 0; np < 4; np++) {
                uint32_t Kh[4];
                ldm4(Kh, aK + ks * 32 + np * 16 * ATS * 2);
                mma16816(c[np * 2],     Qh, Kh[0], Kh[1]);
                mma16816(c[np * 2 + 1], Qh, Kh[2], Kh[3]);
            }
        }

        // ---- add bias (x LOG2E via FMA), online softmax in log2 domain ----
        float mc0 = -1e30f, mc1 = -1e30f;
        int n0 = 0, n1 = 0;
#pragma unroll
        for (int j = 0; j < 8; j++) {
            float2 b0 = *(const float2*)(bp0 + kc * 64 + j * 8);
            float2 b1 = *(const float2*)(bp1 + kc * 64 + j * 8);
            c[j][0] = fmaf(b0.x, LOG2E_F, c[j][0]);
            c[j][1] = fmaf(b0.y, LOG2E_F, c[j][1]);
            c[j][2] = fmaf(b1.x, LOG2E_F, c[j][2]);
            c[j][3] = fmaf(b1.y, LOG2E_F, c[j][3]);
            mc0 = fmaxf(mc0, fmaxf(c[j][0], c[j][1]));
            mc1 = fmaxf(mc1, fmaxf(c[j][2], c[j][3]));
            n0 |= (c[j][0] != 0.f) | (c[j][1] != 0.f);
            n1 |= (c[j][2] != 0.f) | (c[j][3] != 0.f);
        }
#pragma unroll
        for (int o = 1; o < 4; o <<= 1) {
            mc0 = fmaxf(mc0, __shfl_xor_sync(0xffffffffu, mc0, o));
            mc1 = fmaxf(mc1, __shfl_xor_sync(0xffffffffu, mc1, o));
            n0 |= __shfl_xor_sync(0xffffffffu, n0, o);
            n1 |= __shfl_xor_sync(0xffffffffu, n1, o);
        }
        nz0 |= n0; nz1 |= n1;
        float mn0 = fmaxf(mr0, mc0), mn1 = fmaxf(mr1, mc1);
        float cr0 = ex2f(mr0 - mn0);
        float cr1 = ex2f(mr1 - mn1);
        mr0 = mn0; mr1 = mn1;

        float s0 = 0.f, s1 = 0.f;
#pragma unroll
        for (int j = 0; j < 8; j++) {
            c[j][0] = ex2f(c[j][0] - mn0);
            c[j][1] = ex2f(c[j][1] - mn0);
            c[j][2] = ex2f(c[j][2] - mn1);
            c[j][3] = ex2f(c[j][3] - mn1);
            s0 += c[j][0] + c[j][1];
            s1 += c[j][2] + c[j][3];
        }
#pragma unroll
        for (int o = 1; o < 4; o <<= 1) {
            s0 += __shfl_xor_sync(0xffffffffu, s0, o);
            s1 += __shfl_xor_sync(0xffffffffu, s1, o);
        }
        rs0 = rs0 * cr0 + s0;
        rs1 = rs1 * cr1 + s1;
#pragma unroll
        for (int j = 0; j < 8; j++) {
            acc[j][0] *= cr0; acc[j][1] *= cr0;
            acc[j][2] *= cr1; acc[j][3] *= cr1;
        }

        // ---- acc += P V (P single fp16) ----
#pragma unroll
        for (int ks = 0; ks < 4; ks++) {
            uint32_t Ph[4];
            Ph[0] = packh2(c[2 * ks][0],     c[2 * ks][1]);
            Ph[1] = packh2(c[2 * ks][2],     c[2 * ks][3]);
            Ph[2] = packh2(c[2 * ks + 1][0], c[2 * ks + 1][1]);
            Ph[3] = packh2(c[2 * ks + 1][2], c[2 * ks + 1][3]);
#pragma unroll
            for (int np = 0; np < 4; np++) {
                uint32_t Vh[4];
                ldm4t(Vh, aV + ks * 16 * ATS * 2 + np * 32);
                mma16816(acc[np * 2],     Ph, Vh[0], Vh[1]);
                mma16816(acc[np * 2 + 1], Ph, Vh[2], Vh[3]);
            }
        }
    }

    // ---- epilogue: normalize (pad-mask) and store O hi/lo fp16 ----
    const float i0 = nz0 ? (1.f / rs0) : 0.f;
    const float i1 = nz1 ? (1.f / rs1) : 0.f;
    __half* oh = g_oh + (size_t)(b * NSEQ + q0 + wid * 16) * HID + h * DHEAD;
    __half* ol = g_ol + (size_t)(b * NSEQ + q0 + wid * 16) * HID + h * DHEAD;
#pragma unroll
    for (int j = 0; j < 8; j++) {
        const int col = j * 8 + tq;
        uint32_t h0, l0, h1, l1;
        split2(acc[j][0] * i0, acc[j][1] * i0, h0, l0);
        split2(acc[j][2] * i1, acc[j][3] * i1, h1, l1);
        *(uint32_t*)(oh + (size_t)gr * HID + col)       = h0;
        *(uint32_t*)(ol + (size_t)gr * HID + col)       = l0;
        *(uint32_t*)(oh + (size_t)(gr + 8) * HID + col) = h1;
        *(uint32_t*)(ol + (size_t)(gr + 8) * HID + col) = l1;
    }
}

// ---------------------------------------------------------------------------
// inputs: x, encoding_bias, Wq, Wk, Wv, bv, Wo, bo
// ---------------------------------------------------------------------------
extern "C" void kernel_launch(void* const* d_in, const int* in_sizes, int n_in,
                              void* d_out, int out_size)
{
    const float* x  = (const float*)d_in[0];
    const float* eb = (const float*)d_in[1];
    const float* Wq = (const float*)d_in[2];
    const float* Wk = (const float*)d_in[3];
    const float* Wv = (const float*)d_in[4];
    const float* bv = (const float*)d_in[5];
    const float* Wo = (const float*)d_in[6];
    const float* bo = (const float*)d_in[7];
    float* out = (float*)d_out;

    const int GS1 = 3 * 2 * PLANE;   // 61440  (1-term: A,B planes x 3 stages)
    const int GS2 = 3 * 3 * PLANE;   // 92160  (2-term: A-hi,A-lo,B x 3 stages)

    cudaFuncSetAttribute(attn_mma_kernel,
                         cudaFuncAttributeMaxDynamicSharedMemorySize, ATTN_SMEM);
    cudaFuncSetAttribute(gemm_mma_kernel<1>,
                         cudaFuncAttributeMaxDynamicSharedMemorySize, GS1);
    cudaFuncSetAttribute(gemm_mma_kernel<2>,
                         cudaFuncAttributeMaxDynamicSharedMemorySize, GS2);

    const int nx4 = MTOT * HID / 4;
    const int nw4 = WSZ / 4;

    conv_round_x<<<(nx4 + 255) / 256, 256>>>(x, nx4);
    conv_w4<<<dim3((nw4 + 255) / 256, 4), 256>>>(Wq, Wk, Wv, Wo, nw4);

    gemm_mma_kernel<1><<<dim3(HID / GBN, MTOT / GBM, 3), 256, GS1>>>(
        nullptr, bv, nullptr, 0);                                   // Q,K,V

    attn_mma_kernel<<<dim3(4, NHEAD, 16), 256, ATTN_SMEM>>>(eb);    // O hi/lo

    gemm_mma_kernel<2><<<dim3(HID / GBN, MTOT / GBM, 1), 256, GS2>>>(
        out, nullptr, bo, 3);                                       // O proj
}

// round 16
// speedup vs baseline: 6.1709x; 1.2251x over previous
#include <cuda_runtime.h>
#include <cuda_fp16.h>
#include <cstdint>

// ---------------------------------------------------------------------------
// GraphormerMultiHeadAttention  (B=16, N=512, HIDDEN=768, 12 heads x 64)
//
// All-fp16 1-term MMA data flow (error budget ~5.3e-4 < 1e-3):
//   x,W -> fp16; QKV GEMM -> fp16 Q(scaled)/K/V; flash attention (log2-domain
//   softmax, MUFU ex2, bias prefetched to smem) -> fp16 O; O GEMM -> fp32 out.
// ---------------------------------------------------------------------------

#define HID    768
#define MTOT   8192
#define NSEQ   512
#define NHEAD  12
#define DHEAD  64
#define SCALE_F 0.03608439182435161f   // 768^-0.5
#define LOG2E_F 1.4426950408889634f
#define QSCALE  (SCALE_F * LOG2E_F)    // log2-domain scores
#define WSZ (HID * HID)

// ---------------- scratch (device globals; allocation-free) ----------------
__device__ __align__(16) __half g_ah[MTOT * HID];   // x (fp16)
__device__ __align__(16) __half g_qh[MTOT * HID];   // Q (QSCALE folded)
__device__ __align__(16) __half g_kh[MTOT * HID];   // K
__device__ __align__(16) __half g_vh[MTOT * HID];   // V
__device__ __align__(16) __half g_oh[MTOT * HID];   // attn out
__device__ __align__(16) __half g_wh[4 * WSZ];      // Wq,Wk,Wv,Wo (fp16)

// ---------------------------------------------------------------------------
// conversions
// ---------------------------------------------------------------------------
__global__ void conv_round_x(const float* __restrict__ src, int n4)
{
    int i = blockIdx.x * blockDim.x + threadIdx.x;
    if (i >= n4) return;
    float4 v = ((const float4*)src)[i];
    ((__half2*)g_ah)[2 * i]     = __floats2half2_rn(v.x, v.y);
    ((__half2*)g_ah)[2 * i + 1] = __floats2half2_rn(v.z, v.w);
}

__global__ void conv_w4(const float* __restrict__ w0,
                        const float* __restrict__ w1,
                        const float* __restrict__ w2,
                        const float* __restrict__ w3, int n4)
{
    int i = blockIdx.x * blockDim.x + threadIdx.x;
    if (i >= n4) return;
    const int z = blockIdx.y;
    const float* src = (z == 0) ? w0 : (z == 1) ? w1 : (z == 2) ? w2 : w3;
    float4 v = ((const float4*)src)[i];
    size_t base = (size_t)z * (WSZ / 2);
    ((__half2*)g_wh)[base + 2 * i]     = __floats2half2_rn(v.x, v.y);
    ((__half2*)g_wh)[base + 2 * i + 1] = __floats2half2_rn(v.z, v.w);
}

// ---------------------------------------------------------------------------
// warp-mma / async-copy helpers
// ---------------------------------------------------------------------------
__device__ __forceinline__ uint32_t smem_u32(const void* p)
{
    uint32_t a;
    asm("{ .reg .u64 t; cvta.to.shared.u64 t, %1; cvt.u32.u64 %0, t; }"
        : "=r"(a) : "l"(p));
    return a;
}
__device__ __forceinline__ void cp16(uint32_t dst, const void* src)
{
    size_t gsrc = __cvta_generic_to_global(src);
    asm volatile("cp.async.cg.shared.global [%0], [%1], 16;"
                 :: "r"(dst), "l"(gsrc) : "memory");
}
__device__ __forceinline__ void cp_commit()
{
    asm volatile("cp.async.commit_group;" ::: "memory");
}
template <int N>
__device__ __forceinline__ void cp_wait()
{
    asm volatile("cp.async.wait_group %0;" :: "n"(N) : "memory");
}
__device__ __forceinline__ void ldm4(uint32_t* r, uint32_t addr)
{
    asm volatile("ldmatrix.sync.aligned.m8n8.x4.shared.b16 {%0,%1,%2,%3}, [%4];"
                 : "=r"(r[0]), "=r"(r[1]), "=r"(r[2]), "=r"(r[3]) : "r"(addr));
}
__device__ __forceinline__ void ldm4t(uint32_t* r, uint32_t addr)
{
    asm volatile("ldmatrix.sync.aligned.m8n8.x4.trans.shared.b16 {%0,%1,%2,%3}, [%4];"
                 : "=r"(r[0]), "=r"(r[1]), "=r"(r[2]), "=r"(r[3]) : "r"(addr));
}
__device__ __forceinline__ void mma16816(float* c, const uint32_t* a,
                                         uint32_t b0, uint32_t b1)
{
    asm volatile(
        "mma.sync.aligned.m16n8k16.row.col.f32.f16.f16.f32 "
        "{%0,%1,%2,%3}, {%4,%5,%6,%7}, {%8,%9}, {%0,%1,%2,%3};"
        : "+f"(c[0]), "+f"(c[1]), "+f"(c[2]), "+f"(c[3])
        : "r"(a[0]), "r"(a[1]), "r"(a[2]), "r"(a[3]), "r"(b0), "r"(b1));
}
__device__ __forceinline__ float ex2f(float x)
{
    float r;
    asm("ex2.approx.f32 %0, %1;" : "=f"(r) : "f"(x));
    return r;
}
__device__ __forceinline__ uint32_t packh2(float x, float y)
{
    __half2 H = __floats2half2_rn(x, y);
    return *(uint32_t*)&H;
}

// ---------------------------------------------------------------------------
// GEMM-NT: C[m][n] = sum_k A[m][k] * W[n][k] (+ bias), fp16 1-term.
// CTA 128x128, GBK=64, 3-stage cp.async pipeline, one barrier per k-iter.
// z=0 -> Q (QSCALE); z=1 -> K; z=2 -> V(+bv); z=3 -> fp32 out (+bo).
// ---------------------------------------------------------------------------
#define GBM 128
#define GBN 128
#define GBK 64
#define KSTR 72                         // padded k-stride (elements)
#define GPL (128 * KSTR * 2)            // 18432 B per 128-row plane
#define GBUF (2 * GPL)                  // A + B = 36864 B per stage
#define GSMEM (3 * GBUF)                // 110592 B
#define NKC (HID / GBK)                 // 12

__global__ __launch_bounds__(256, 2)
void gemm_mma_kernel(float* __restrict__ outp,
                     const float* __restrict__ bias_v,
                     const float* __restrict__ bias_o,
                     int z_base)
{
    extern __shared__ char smem[];
    const uint32_t sbase = smem_u32(smem);
    const int tid = threadIdx.x, wid = tid >> 5, lid = tid & 31;

    const int z  = z_base + blockIdx.z;
    const int n0 = blockIdx.x * GBN;
    const int m0 = blockIdx.y * GBM;

    const __half* gA = ((z == 3) ? g_oh : g_ah) + (size_t)m0 * HID;
    const __half* gB = g_wh + (size_t)z * WSZ + (size_t)n0 * HID;

    const int lrow = tid >> 3, lc8 = (tid & 7) * 8;   // 32 rows, 8 segs/row

    const int wm = wid & 3, wn = wid >> 2;
    const int gr = lid >> 2, tq = (lid & 3) * 2;
    const int rA = (lid & 7) + ((lid >> 3) & 1) * 8;
    const int kA = (lid >> 4) * 8;
    const int rB = (lid & 7) + (lid >> 4) * 8;
    const int kB = ((lid >> 3) & 1) * 8;
    const uint32_t aoff = sbase + ((wm * 32 + rA) * KSTR + kA) * 2;
    const uint32_t boff = sbase + GPL + ((wn * 64 + rB) * KSTR + kB) * 2;

    auto load_chunk = [&](int t, int stg) {
        const int ko = t * GBK;
        const uint32_t sb = sbase + stg * GBUF;
#pragma unroll
        for (int sub = 0; sub < 4; sub++) {
            int row = lrow + sub * 32;
            uint32_t so = (row * KSTR + lc8) * 2;
            cp16(sb + so,       gA + (size_t)row * HID + ko + lc8);
            cp16(sb + GPL + so, gB + (size_t)row * HID + ko + lc8);
        }
        cp_commit();
    };

    float c[2][8][4];
#pragma unroll
    for (int mi = 0; mi < 2; mi++)
#pragma unroll
        for (int ni = 0; ni < 8; ni++)
#pragma unroll
            for (int r = 0; r < 4; r++) c[mi][ni][r] = 0.f;

    load_chunk(0, 0);
    load_chunk(1, 1);

    int stg = 0, nstg = 2;
#pragma unroll 1
    for (int t = 0; t < NKC; t++) {
        cp_wait<1>();
        __syncthreads();
        if (t + 2 < NKC) load_chunk(t + 2, nstg);
        else             cp_commit();

        const uint32_t bb = stg * GBUF;
#pragma unroll
        for (int ks = 0; ks < 4; ks++) {
            uint32_t Ah[2][4];
            ldm4(Ah[0], aoff + bb + ks * 32);
            ldm4(Ah[1], aoff + bb + ks * 32 + 16 * KSTR * 2);
#pragma unroll
            for (int np = 0; np < 4; np++) {
                uint32_t Bh[4];
                ldm4(Bh, boff + bb + ks * 32 + np * 16 * KSTR * 2);
#pragma unroll
                for (int mi = 0; mi < 2; mi++) {
                    mma16816(c[mi][np * 2],     Ah[mi], Bh[0], Bh[1]);
                    mma16816(c[mi][np * 2 + 1], Ah[mi], Bh[2], Bh[3]);
                }
            }
        }
        stg = (stg == 2) ? 0 : stg + 1;
        nstg = (nstg == 2) ? 0 : nstg + 1;
    }

    // ---- epilogue ----
    if (z == 0) {          // Q: QSCALE (log2-domain) folded in
#pragma unroll
        for (int mi = 0; mi < 2; mi++) {
            const int row = m0 + wm * 32 + mi * 16 + gr;
#pragma unroll
            for (int ni = 0; ni < 8; ni++) {
                const int col = n0 + wn * 64 + ni * 8 + tq;
                *(uint32_t*)(g_qh + (size_t)row * HID + col) =
                    packh2(c[mi][ni][0] * QSCALE, c[mi][ni][1] * QSCALE);
                *(uint32_t*)(g_qh + (size_t)(row + 8) * HID + col) =
                    packh2(c[mi][ni][2] * QSCALE, c[mi][ni][3] * QSCALE);
            }
        }
    } else if (z < 3) {    // K or V
        __half* dst = (z == 1) ? g_kh : g_vh;
#pragma unroll
        for (int mi = 0; mi < 2; mi++) {
            const int row = m0 + wm * 32 + mi * 16 + gr;
#pragma unroll
            for (int ni = 0; ni < 8; ni++) {
                const int col = n0 + wn * 64 + ni * 8 + tq;
                float b0 = 0.f, b1 = 0.f;
                if (z == 2) { b0 = bias_v[col]; b1 = bias_v[col + 1]; }
                *(uint32_t*)(dst + (size_t)row * HID + col) =
                    packh2(c[mi][ni][0] + b0, c[mi][ni][1] + b1);
                *(uint32_t*)(dst + (size_t)(row + 8) * HID + col) =
                    packh2(c[mi][ni][2] + b0, c[mi][ni][3] + b1);
            }
        }
    } else {               // O projection: fp32 out + bo
#pragma unroll
        for (int mi = 0; mi < 2; mi++) {
            const int row = m0 + wm * 32 + mi * 16 + gr;
#pragma unroll
            for (int ni = 0; ni < 8; ni++) {
                const int col = n0 + wn * 64 + ni * 8 + tq;
                float b0 = bias_o[col], b1 = bias_o[col + 1];
                *(float2*)(outp + (size_t)row * HID + col) =
                    make_float2(c[mi][ni][0] + b0, c[mi][ni][1] + b1);
                *(float2*)(outp + (size_t)(row + 8) * HID + col) =
                    make_float2(c[mi][ni][2] + b0, c[mi][ni][3] + b1);
            }
        }
    }
}

// ---------------------------------------------------------------------------
// Tensor-core flash attention: Q,K,V,P single fp16; log2-domain softmax via
// MUFU ex2; cp.async double-buffered K/V; bias prefetched to smem (1 buffer).
// CTA = 128 q-rows of one (b,h); 8 warps. O written as single fp16 plane.
// smem: Q 128x72 + 2 x [K,V] 64x72 + bias 128x68 f32 = 88064 B.
// ---------------------------------------------------------------------------
#define ATS 72
#define AQPL (128 * ATS * 2)    // 18432
#define AKPL (64 * ATS * 2)     // 9216
#define OFF_KV AQPL
#define KVBUF (2 * AKPL)        // 18432
#define BSTR 68
#define OFF_B (AQPL + 2 * KVBUF)          // 55296
#define ATTN_SMEM (OFF_B + 128 * BSTR * 4) // 90112

__global__ __launch_bounds__(256, 2)
void attn_mma_kernel(const float* __restrict__ ebias)
{
    extern __shared__ char smem[];
    const uint32_t sbase = smem_u32(smem);
    const int tid = threadIdx.x, wid = tid >> 5, lid = tid & 31;
    const int qt = blockIdx.x, h = blockIdx.y, b = blockIdx.z;
    const int q0 = qt * 128;

    const int lrow = tid >> 3, lc8 = (tid & 7) * 8;
    const int brow = tid >> 4, bc4 = (tid & 15) * 4;   // bias loader coords

    auto load_kv = [&](int kc, int buf) {
        const size_t rb = (size_t)(b * NSEQ + kc * 64) * HID + h * DHEAD;
        const uint32_t sb = sbase + OFF_KV + buf * KVBUF;
#pragma unroll
        for (int sub = 0; sub < 2; sub++) {
            int row = lrow + sub * 32;
            cp16(sb + (row * ATS + lc8) * 2,        g_kh + rb + (size_t)row * HID + lc8);
            cp16(sb + AKPL + (row * ATS + lc8) * 2, g_vh + rb + (size_t)row * HID + lc8);
        }
        cp_commit();
    };
    auto load_bias = [&](int kc) {
        const float* src = ebias + ((size_t)(b * NSEQ + q0)) * NSEQ + kc * 64;
#pragma unroll
        for (int sub = 0; sub < 8; sub++) {
            int row = brow + sub * 16;
            cp16(sbase + OFF_B + (row * BSTR + bc4) * 4,
                 src + (size_t)row * NSEQ + bc4);
        }
        cp_commit();
    };

    // ---- load Q tile ----
    {
        const __half* qh = g_qh + (size_t)(b * NSEQ + q0) * HID + h * DHEAD;
#pragma unroll
        for (int l = 0; l < 4; l++) {
            int row = lrow + l * 32;
            cp16(sbase + (row * ATS + lc8) * 2, qh + (size_t)row * HID + lc8);
        }
        cp_commit();
    }
    load_kv(0, 0);
    load_bias(0);

    const int gr = lid >> 2, tq = (lid & 3) * 2;
    const int rA = (lid & 7) + ((lid >> 3) & 1) * 8;
    const int kA = (lid >> 4) * 8;
    const int rB = (lid & 7) + (lid >> 4) * 8;
    const int kB = ((lid >> 3) & 1) * 8;
    const uint32_t aQh = sbase + ((wid * 16 + rA) * ATS + kA) * 2;
    const uint32_t oK  = (rB * ATS + kB) * 2;
    const uint32_t oV  = ((lid & 15) * ATS + (lid >> 4) * 8) * 2;
    const uint32_t bof0 = sbase + OFF_B + ((wid * 16 + gr) * BSTR + tq) * 4;
    const uint32_t bof1 = bof0 + 8 * BSTR * 4;

    float acc[8][4];
#pragma unroll
    for (int j = 0; j < 8; j++)
#pragma unroll
        for (int r = 0; r < 4; r++) acc[j][r] = 0.f;
    float mr0 = -1e30f, mr1 = -1e30f, rs0 = 0.f, rs1 = 0.f;
    int nz0 = 0, nz1 = 0;

#pragma unroll 1
    for (int kc = 0; kc < 8; kc++) {
        cp_wait<0>();      // K/V chunk kc + bias kc (+ Q first iter) resident
        __syncthreads();   // separates last iter's reads from this iter's loads
        if (kc + 1 < 8) load_kv(kc + 1, (kc + 1) & 1);

        const uint32_t aK = sbase + OFF_KV + (kc & 1) * KVBUF + oK;
        const uint32_t aV = sbase + OFF_KV + (kc & 1) * KVBUF + AKPL + oV;

        // ---- S = Q K^T (log2 domain) ----
        float c[8][4];
#pragma unroll
        for (int j = 0; j < 8; j++)
#pragma unroll
            for (int r = 0; r < 4; r++) c[j][r] = 0.f;

#pragma unroll
        for (int ks = 0; ks < 4; ks++) {
            uint32_t Qh[4];
            ldm4(Qh, aQh + ks * 32);
#pragma unroll
            for (int np = 0; np < 4; np++) {
                uint32_t Kh[4];
                ldm4(Kh, aK + ks * 32 + np * 16 * ATS * 2);
                mma16816(c[np * 2],     Qh, Kh[0], Kh[1]);
                mma16816(c[np * 2 + 1], Qh, Kh[2], Kh[3]);
            }
        }

        // ---- add bias (from smem, x LOG2E), online softmax in log2 domain --
        float mc0 = -1e30f, mc1 = -1e30f;
        int n0 = 0, n1 = 0;
#pragma unroll
        for (int j = 0; j < 8; j++) {
            float2 b0 = *(const float2*)(smem + (bof0 - sbase) + j * 32);
            float2 b1 = *(const float2*)(smem + (bof1 - sbase) + j * 32);
            c[j][0] = fmaf(b0.x, LOG2E_F, c[j][0]);
            c[j][1] = fmaf(b0.y, LOG2E_F, c[j][1]);
            c[j][2] = fmaf(b1.x, LOG2E_F, c[j][2]);
            c[j][3] = fmaf(b1.y, LOG2E_F, c[j][3]);
            mc0 = fmaxf(mc0, fmaxf(c[j][0], c[j][1]));
            mc1 = fmaxf(mc1, fmaxf(c[j][2], c[j][3]));
            n0 |= (c[j][0] != 0.f) | (c[j][1] != 0.f);
            n1 |= (c[j][2] != 0.f) | (c[j][3] != 0.f);
        }
#pragma unroll
        for (int o = 1; o < 4; o <<= 1) {
            mc0 = fmaxf(mc0, __shfl_xor_sync(0xffffffffu, mc0, o));
            mc1 = fmaxf(mc1, __shfl_xor_sync(0xffffffffu, mc1, o));
            n0 |= __shfl_xor_sync(0xffffffffu, n0, o);
            n1 |= __shfl_xor_sync(0xffffffffu, n1, o);
        }
        nz0 |= n0; nz1 |= n1;
        float mn0 = fmaxf(mr0, mc0), mn1 = fmaxf(mr1, mc1);
        float cr0 = ex2f(mr0 - mn0);
        float cr1 = ex2f(mr1 - mn1);
        mr0 = mn0; mr1 = mn1;

        float s0 = 0.f, s1 = 0.f;
#pragma unroll
        for (int j = 0; j < 8; j++) {
            c[j][0] = ex2f(c[j][0] - mn0);
            c[j][1] = ex2f(c[j][1] - mn0);
            c[j][2] = ex2f(c[j][2] - mn1);
            c[j][3] = ex2f(c[j][3] - mn1);
            s0 += c[j][0] + c[j][1];
            s1 += c[j][2] + c[j][3];
        }
#pragma unroll
        for (int o = 1; o < 4; o <<= 1) {
            s0 += __shfl_xor_sync(0xffffffffu, s0, o);
            s1 += __shfl_xor_sync(0xffffffffu, s1, o);
        }
        rs0 = rs0 * cr0 + s0;
        rs1 = rs1 * cr1 + s1;
#pragma unroll
        for (int j = 0; j < 8; j++) {
            acc[j][0] *= cr0; acc[j][1] *= cr0;
            acc[j][2] *= cr1; acc[j][3] *= cr1;
        }

        // bias buffer fully consumed -> prefetch next chunk's bias
        __syncthreads();
        if (kc + 1 < 8) load_bias(kc + 1);
        else            cp_commit();

        // ---- acc += P V (P single fp16) ----
#pragma unroll
        for (int ks = 0; ks < 4; ks++) {
            uint32_t Ph[4];
            Ph[0] = packh2(c[2 * ks][0],     c[2 * ks][1]);
            Ph[1] = packh2(c[2 * ks][2],     c[2 * ks][3]);
            Ph[2] = packh2(c[2 * ks + 1][0], c[2 * ks + 1][1]);
            Ph[3] = packh2(c[2 * ks + 1][2], c[2 * ks + 1][3]);
#pragma unroll
            for (int np = 0; np < 4; np++) {
                uint32_t Vh[4];
                ldm4t(Vh, aV + ks * 16 * ATS * 2 + np * 32);
                mma16816(acc[np * 2],     Ph, Vh[0], Vh[1]);
                mma16816(acc[np * 2 + 1], Ph, Vh[2], Vh[3]);
            }
        }
    }

    // ---- epilogue: normalize (pad-mask) and store O (single fp16 plane) ----
    const float i0 = nz0 ? (1.f / rs0) : 0.f;
    const float i1 = nz1 ? (1.f / rs1) : 0.f;
    __half* oh = g_oh + (size_t)(b * NSEQ + q0 + wid * 16) * HID + h * DHEAD;
#pragma unroll
    for (int j = 0; j < 8; j++) {
        const int col = j * 8 + tq;
        *(uint32_t*)(oh + (size_t)gr * HID + col) =
            packh2(acc[j][0] * i0, acc[j][1] * i0);
        *(uint32_t*)(oh + (size_t)(gr + 8) * HID + col) =
            packh2(acc[j][2] * i1, acc[j][3] * i1);
    }
}

// ---------------------------------------------------------------------------
// inputs: x, encoding_bias, Wq, Wk, Wv, bv, Wo, bo
// ---------------------------------------------------------------------------
extern "C" void kernel_launch(void* const* d_in, const int* in_sizes, int n_in,
                              void* d_out, int out_size)
{
    const float* x  = (const float*)d_in[0];
    const float* eb = (const float*)d_in[1];
    const float* Wq = (const float*)d_in[2];
    const float* Wk = (const float*)d_in[3];
    const float* Wv = (const float*)d_in[4];
    const float* bv = (const float*)d_in[5];
    const float* Wo = (const float*)d_in[6];
    const float* bo = (const float*)d_in[7];
    float* out = (float*)d_out;

    cudaFuncSetAttribute(attn_mma_kernel,
                         cudaFuncAttributeMaxDynamicSharedMemorySize, ATTN_SMEM);
    cudaFuncSetAttribute(gemm_mma_kernel,
                         cudaFuncAttributeMaxDynamicSharedMemorySize, GSMEM);

    const int nx4 = MTOT * HID / 4;
    const int nw4 = WSZ / 4;

    conv_round_x<<<(nx4 + 255) / 256, 256>>>(x, nx4);
    conv_w4<<<dim3((nw4 + 255) / 256, 4), 256>>>(Wq, Wk, Wv, Wo, nw4);

    gemm_mma_kernel<<<dim3(HID / GBN, MTOT / GBM, 3), 256, GSMEM>>>(
        nullptr, bv, nullptr, 0);                                   // Q,K,V

    attn_mma_kernel<<<dim3(4, NHEAD, 16), 256, ATTN_SMEM>>>(eb);    // O

    gemm_mma_kernel<<<dim3(HID / GBN, MTOT / GBM, 1), 256, GSMEM>>>(
        out, nullptr, bo, 3);                                       // O proj
}